// round 3
// baseline (speedup 1.0000x reference)
#include <cuda_runtime.h>

typedef unsigned long long ull;
#define DEV static __device__ __forceinline__

DEV ull fdup(float x){ ull r; asm("mov.b64 %0, {%1, %1};" : "=l"(r) : "f"(x)); return r; }
DEV float2 u2f(ull v){ float2 r; asm("mov.b64 {%0, %1}, %2;" : "=f"(r.x), "=f"(r.y) : "l"(v)); return r; }
DEV void fma2(ull& d, ull a, ull b){ asm("fma.rn.f32x2 %0, %1, %2, %0;" : "+l"(d) : "l"(a), "l"(b)); }

// ---- scratch offsets (floats) ----
#define O_LL0 0ull
#define O_HI0 2359296ull
#define O_LL1 11796480ull
#define O_HI1 12386304ull
#define O_LM0 14745600ull
#define O_LM1 17104896ull
#define O_RC  17694720ull
#define O_XZ  20054016ull
#define O_XS  29491200ull
#define O_DT  34209792ull
#define O_BC  38928384ull
#define O_YS  40108032ull
#define O_AT  44826624ull
#define O_HL  45416448ull
#define O_HIN 46006272ull
#define O_WTP 46596096ull
#define O_IWP 46698496ull
#define O_AB  46800896ull
#define O_WE  46802944ull
#define S_TOT 46827520ull

__device__ __align__(16) float g_scratch[S_TOT];

// ---- prep: pack filters, A=-exp(A_log), Weff2 = [Wcomb ; W_x rows 4..35 ; zeros] ----
__global__ void prep_k(const float* __restrict__ wt, const float* __restrict__ iwt,
                       const float* __restrict__ A_log, const float* __restrict__ W_x,
                       const float* __restrict__ W_dt, float* __restrict__ base)
{
    int i = blockIdx.x * 256 + threadIdx.x;
    if (i < 51200) {
        int ic = i / 800, r = i % 800, t = r / 32, op = r % 32;
        float2* wp = (float2*)(base + O_WTP);
        float2* ip = (float2*)(base + O_IWP);
        wp[i] = make_float2(wt[((2*op)*64 + ic)*25 + t], wt[((2*op+1)*64 + ic)*25 + t]);
        ip[i] = make_float2(iwt[((2*op)*64 + ic)*25 + t], iwt[((2*op+1)*64 + ic)*25 + t]);
    }
    if (i < 2048) base[O_AB + i] = -__expf(A_log[i]);
    if (i < 16384) {
        int d = i >> 7, k = i & 127;
        float s = 0.f;
        #pragma unroll
        for (int r = 0; r < 4; r++) s += W_dt[d*4 + r] * W_x[r*128 + k];
        base[O_WE + i] = s;
    }
    if (i < 8192) {
        int j = i >> 7, k = i & 127;
        base[O_WE + (size_t)(128 + j)*128 + k] = (j < 32) ? W_x[(4 + j)*128 + k] : 0.f;
    }
}

// ---- 5x5 conv 64->64, SAME. INMODE: 0 plain, 1 transposed-seq, 2 depth-to-space(ll+high)
//      OUTMODE: 0 plain, 1 space-to-depth split (s0->outLL seq, s1..3->outP bands) ----
template<int INMODE, int OUTMODE>
__global__ void __launch_bounds__(256) conv5_k(const float* __restrict__ in, const float* __restrict__ llB,
    const float* __restrict__ high, const float2* __restrict__ wp,
    float* __restrict__ outP, float* __restrict__ outLL, int H, int W)
{
    __shared__ float ism[32 * 240];
    int t = threadIdx.x, ocp = t & 31, row = t >> 5;
    int b = blockIdx.z, x0 = blockIdx.x * 16, y0 = blockIdx.y * 8;
    int h2 = H >> 1, w2 = W >> 1, L2 = h2 * w2;
    ull acc[16];
    #pragma unroll
    for (int px = 0; px < 16; px++) acc[px] = 0ull;

    for (int icc = 0; icc < 2; icc++) {
        __syncthreads();
        for (int i = t; i < 7680; i += 256) {
            int icl = i / 240, rem = i % 240, r, c;
            if (INMODE == 1) { c = rem / 12; r = rem % 12; }
            else             { r = rem / 20; c = rem % 20; }
            int gy = y0 + r - 2, gx = x0 + c - 2, ic = icc * 32 + icl;
            float v = 0.f;
            if ((unsigned)gy < (unsigned)H && (unsigned)gx < (unsigned)W) {
                if (INMODE == 0)      v = in[(((size_t)b*64 + ic)*H + gy)*W + gx];
                else if (INMODE == 1) v = in[(((size_t)b*64 + ic)*W + gx)*H + gy];
                else {
                    int s = (gy & 1)*2 + (gx & 1), hy = gy >> 1, hx = gx >> 1;
                    if (s == 0) {
                        v = in[((size_t)b*64 + ic)*L2 + hx*h2 + hy];
                        if (llB) v += llB[(((size_t)b*64 + ic)*h2 + hy)*w2 + hx];
                    } else {
                        v = high[((((size_t)b*64 + ic)*4 + s)*h2 + hy)*w2 + hx];
                    }
                }
            }
            ism[icl*240 + r*20 + c] = v;
        }
        __syncthreads();
        for (int icl = 0; icl < 32; icl++) {
            const float* ib = ism + icl*240 + row*20;
            const float2* wb = wp + ((size_t)(icc*32 + icl)*25)*32 + ocp;
            #pragma unroll
            for (int ky = 0; ky < 5; ky++) {
                const float* rp = ib + ky*20;
                float f[20];
                #pragma unroll
                for (int j = 0; j < 5; j++) *(float4*)&f[j*4] = *(const float4*)(rp + j*4);
                ull ff[20];
                #pragma unroll
                for (int j = 0; j < 20; j++) ff[j] = fdup(f[j]);
                #pragma unroll
                for (int kx = 0; kx < 5; kx++) {
                    ull wu = *(const ull*)(wb + (size_t)(ky*5 + kx)*32);
                    #pragma unroll
                    for (int px = 0; px < 16; px++) fma2(acc[px], ff[px + kx], wu);
                }
            }
        }
    }

    int gy = y0 + row, oc0 = ocp * 2;
    if (OUTMODE == 0) {
        float* o0 = outP + (((size_t)b*64 + oc0)*H + gy)*W + x0;
        float* o1 = o0 + (size_t)H * W;
        #pragma unroll
        for (int px = 0; px < 16; px++) { float2 v = u2f(acc[px]); o0[px] = v.x; o1[px] = v.y; }
    } else {
        int p = gy & 1, hy = gy >> 1;
        #pragma unroll
        for (int px = 0; px < 16; px++) {
            int gx = x0 + px, s = p*2 + (gx & 1), hx = gx >> 1;
            float2 v = u2f(acc[px]);
            if (s == 0) {
                outLL[((size_t)b*64 + oc0)*L2 + hx*h2 + hy]     = v.x;
                outLL[((size_t)b*64 + oc0 + 1)*L2 + hx*h2 + hy] = v.y;
            } else {
                size_t o = (((size_t)b*64 + oc0)*4 + s)*h2;
                outP[(o + hy)*w2 + hx]          = v.x;
                outP[(o + 4*h2 + hy)*w2 + hx]   = v.y;
            }
        }
    }
}

DEV float softplus_f(float x){ return fmaxf(x, 0.f) + log1pf(__expf(-fabsf(x))); }

// ---- GEMM C[M,N] = A[M,K] @ W[N,K]^T. AMODE: 0 plain(lda), 1 seq-gather.
//      EPI: 1 xz plain(ldc=256), 2 dt(softplus)+BC split, 3 scatter to seq layout ----
template<int AMODE, int EPI>
__global__ void __launch_bounds__(256) gemm_k(const float* __restrict__ A, const float* __restrict__ W,
    float* __restrict__ out, const float* __restrict__ bias, int K, int lda, int L, float* __restrict__ base)
{
    __shared__ ull  At2[32 * 65];
    __shared__ float Wt[32 * 66];
    int t = threadIdx.x, tx = t & 15, ty = t >> 4;
    int m0 = blockIdx.x * 64, n0 = blockIdx.y * 64;
    int b = m0 / L, l0 = m0 % L;
    ull acc[4][2];
    #pragma unroll
    for (int i = 0; i < 4; i++) { acc[i][0] = 0ull; acc[i][1] = 0ull; }

    for (int kc = 0; kc < K; kc += 32) {
        __syncthreads();
        if (AMODE == 0) {
            for (int i = t; i < 512; i += 256) {
                int kq = i >> 6, ml = i & 63;
                float4 v = *(const float4*)(A + (size_t)(m0 + ml)*lda + kc + kq*4);
                At2[(kq*4+0)*65 + ml] = fdup(v.x);
                At2[(kq*4+1)*65 + ml] = fdup(v.y);
                At2[(kq*4+2)*65 + ml] = fdup(v.z);
                At2[(kq*4+3)*65 + ml] = fdup(v.w);
            }
        } else {
            for (int i = t; i < 2048; i += 256) {
                int k = i >> 6, ml = i & 63;
                At2[k*65 + ml] = fdup(A[((size_t)b*64 + kc + k)*L + l0 + ml]);
            }
        }
        for (int i = t; i < 512; i += 256) {
            int kq = i >> 6, nl = i & 63;
            float4 v = *(const float4*)(W + (size_t)(n0 + nl)*K + kc + kq*4);
            Wt[(kq*4+0)*66 + nl] = v.x;
            Wt[(kq*4+1)*66 + nl] = v.y;
            Wt[(kq*4+2)*66 + nl] = v.z;
            Wt[(kq*4+3)*66 + nl] = v.w;
        }
        __syncthreads();
        #pragma unroll 4
        for (int k = 0; k < 32; k++) {
            ull a0 = At2[k*65 + ty*4 + 0];
            ull a1 = At2[k*65 + ty*4 + 1];
            ull a2 = At2[k*65 + ty*4 + 2];
            ull a3 = At2[k*65 + ty*4 + 3];
            ull w0 = *(const ull*)&Wt[k*66 + tx*4];
            ull w1 = *(const ull*)&Wt[k*66 + tx*4 + 2];
            fma2(acc[0][0], a0, w0); fma2(acc[0][1], a0, w1);
            fma2(acc[1][0], a1, w0); fma2(acc[1][1], a1, w1);
            fma2(acc[2][0], a2, w0); fma2(acc[2][1], a2, w1);
            fma2(acc[3][0], a3, w0); fma2(acc[3][1], a3, w1);
        }
    }

    #pragma unroll
    for (int i = 0; i < 4; i++) {
        int m = m0 + ty*4 + i;
        #pragma unroll
        for (int j = 0; j < 2; j++) {
            float2 c = u2f(acc[i][j]);
            int n = n0 + tx*4 + j*2;
            if (EPI == 1) {
                out[(size_t)m*256 + n]     = c.x;
                out[(size_t)m*256 + n + 1] = c.y;
            } else if (EPI == 2) {
                float cv[2] = {c.x, c.y};
                #pragma unroll
                for (int q = 0; q < 2; q++) {
                    int nn = n + q;
                    if (nn < 128)      base[O_DT + (size_t)m*128 + nn] = softplus_f(cv[q] + bias[nn]);
                    else if (nn < 160) base[O_BC + (size_t)m*32 + nn - 128] = cv[q];
                }
            } else { // EPI 3
                int l = l0 + ty*4 + i;
                out[((size_t)b*64 + n)*L + l]     = c.x;
                out[((size_t)b*64 + n + 1)*L + l] = c.y;
            }
        }
    }
}

// ---- depthwise causal conv (k=4) + silu ----
__global__ void dwconv_k(const float* __restrict__ cw, const float* __restrict__ cb, int L, float* __restrict__ base)
{
    size_t g = (size_t)blockIdx.x * 256 + threadIdx.x;
    int d = (int)(g & 127);
    size_t m = g >> 7;
    int l = (int)(m % (size_t)L);
    const float* xz = base + O_XZ;
    float acc = cb[d];
    #pragma unroll
    for (int j = 0; j < 4; j++) {
        int lj = l - 3 + j;
        if (lj >= 0) acc = fmaf(cw[d*4 + j], xz[(m - 3 + j)*256 + d], acc);
    }
    base[O_XS + g] = acc * __fdividef(1.f, 1.f + __expf(-acc));
}

// ---- scan phase 1: per-chunk local scan -> (A_prod, h_local) ----
__global__ void scan1_k(int L, int NCH, float* __restrict__ base)
{
    int t = threadIdx.x, s = t & 15;
    int ch = blockIdx.y, b = blockIdx.z, d = blockIdx.x * 16 + (t >> 4);
    const float* dt = base + O_DT; const float* xs = base + O_XS; const float* bc = base + O_BC;
    float a = base[O_AB + d*16 + s];
    float h = 0.f, P = 1.f;
    size_t ml = (size_t)b*L + (size_t)ch*128;
    for (int i = 0; i < 128; i++) {
        size_t m = ml + i;
        float dtv = __ldg(dt + m*128 + d);
        float e  = __expf(dtv * a);
        float bm = __ldg(bc + m*32 + s);
        float xv = __ldg(xs + m*128 + d);
        h = h*e + dtv*xv*bm;
        P *= e;
    }
    size_t ix = (((size_t)(b*NCH + ch)*128) + d)*16 + s;
    base[O_AT + ix] = P;
    base[O_HL + ix] = h;
}

// ---- scan phase 2: sequential over chunks -> carry-in per chunk ----
__global__ void scan2_k(int NCH, float* __restrict__ base)
{
    int g = blockIdx.x * 256 + threadIdx.x;
    int b = g >> 11, ds = g & 2047;
    float carry = 0.f;
    for (int ch = 0; ch < NCH; ch++) {
        size_t ix = ((size_t)(b*NCH + ch))*2048 + ds;
        base[O_HIN + ix] = carry;
        carry = carry * base[O_AT + ix] + base[O_HL + ix];
    }
}

// ---- scan phase 3: full scan with carry-in, emit y ----
__global__ void scan3_k(int L, int NCH, float* __restrict__ base)
{
    int t = threadIdx.x, s = t & 15;
    int ch = blockIdx.y, b = blockIdx.z, d = blockIdx.x * 16 + (t >> 4);
    const float* dt = base + O_DT; const float* xs = base + O_XS; const float* bc = base + O_BC;
    float a = base[O_AB + d*16 + s];
    size_t ix = (((size_t)(b*NCH + ch)*128) + d)*16 + s;
    float h = base[O_HIN + ix];
    size_t ml = (size_t)b*L + (size_t)ch*128;
    for (int i = 0; i < 128; i++) {
        size_t m = ml + i;
        float dtv = __ldg(dt + m*128 + d);
        float e  = __expf(dtv * a);
        float bm = __ldg(bc + m*32 + s);
        float xv = __ldg(xs + m*128 + d);
        h = h*e + dtv*xv*bm;
        float part = h * __ldg(bc + m*32 + 16 + s);
        part += __shfl_xor_sync(0xffffffffu, part, 8);
        part += __shfl_xor_sync(0xffffffffu, part, 4);
        part += __shfl_xor_sync(0xffffffffu, part, 2);
        part += __shfl_xor_sync(0xffffffffu, part, 1);
        if (s == 0) base[O_YS + m*128 + d] = part;
    }
}

// ---- y = (y_scan + xs*D) * silu(z) ----
__global__ void ymul_k(const float* __restrict__ Dp, float* __restrict__ base)
{
    size_t g = (size_t)blockIdx.x * 256 + threadIdx.x;
    int d = (int)(g & 127);
    size_t m = g >> 7;
    float z = base[O_XZ + m*256 + 128 + d];
    float sz = z * __fdividef(1.f, 1.f + __expf(-z));
    base[O_YS + g] = (base[O_YS + g] + base[O_XS + g] * Dp[d]) * sz;
}

extern "C" void kernel_launch(void* const* d_in, const int* in_sizes, int n_in,
                              void* d_out, int out_size)
{
    const float* x      = (const float*)d_in[0];
    const float* wt     = (const float*)d_in[1];
    const float* iwt    = (const float*)d_in[2];
    const float* W_in   = (const float*)d_in[3];
    const float* conv_w = (const float*)d_in[4];
    const float* conv_b = (const float*)d_in[5];
    const float* W_x    = (const float*)d_in[6];
    const float* W_dt   = (const float*)d_in[7];
    const float* b_dt   = (const float*)d_in[8];
    const float* A_log  = (const float*)d_in[9];
    const float* Dp     = (const float*)d_in[10];
    const float* W_out  = (const float*)d_in[11];
    (void)in_sizes; (void)n_in; (void)out_size;

    float* S = nullptr;
    cudaGetSymbolAddress((void**)&S, g_scratch);

    prep_k<<<200, 256>>>(wt, iwt, A_log, W_x, W_dt, S);

    auto mamba = [&](int L, int NCH, const float* llseq, float* llm) {
        int M = 4 * L;
        gemm_k<1,1><<<dim3(M/64, 4), 256>>>(llseq, W_in, S + O_XZ, nullptr, 64, 0, L, S);
        dwconv_k<<<(M*128)/256, 256>>>(conv_w, conv_b, L, S);
        gemm_k<0,2><<<dim3(M/64, 3), 256>>>(S + O_XS, S + O_WE, nullptr, b_dt, 128, 128, L, S);
        scan1_k<<<dim3(8, NCH, 4), 256>>>(L, NCH, S);
        scan2_k<<<32, 256>>>(NCH, S);
        scan3_k<<<dim3(8, NCH, 4), 256>>>(L, NCH, S);
        ymul_k<<<(M*128)/256, 256>>>(Dp, S);
        gemm_k<0,3><<<dim3(M/64, 1), 256>>>(S + O_YS, W_out, llm, nullptr, 128, 128, L, S);
    };

    // level 0 decomposition (192x192 -> 96x96)
    conv5_k<0,1><<<dim3(12,24,4), 256>>>(x, nullptr, nullptr, (const float2*)(S + O_WTP),
                                         S + O_HI0, S + O_LL0, 192, 192);
    mamba(9216, 72, S + O_LL0, S + O_LM0);
    // level 1 decomposition (96x96 -> 48x48) on raw LL0
    conv5_k<1,1><<<dim3(6,12,4), 256>>>(S + O_LL0, nullptr, nullptr, (const float2*)(S + O_WTP),
                                        S + O_HI1, S + O_LL1, 96, 96);
    mamba(2304, 18, S + O_LL1, S + O_LM1);
    // reconstruction level 1 -> 96x96
    conv5_k<2,0><<<dim3(6,12,4), 256>>>(S + O_LM1, nullptr, S + O_HI1, (const float2*)(S + O_IWP),
                                        S + O_RC, nullptr, 96, 96);
    // reconstruction level 0 -> 192x192 (final output)
    conv5_k<2,0><<<dim3(12,24,4), 256>>>(S + O_LM0, S + O_RC, S + O_HI0, (const float2*)(S + O_IWP),
                                         (float*)d_out, nullptr, 192, 192);
}

// round 4
// speedup vs baseline: 1.0022x; 1.0022x over previous
#include <cuda_runtime.h>

typedef unsigned long long ull;
#define DEV static __device__ __forceinline__

DEV ull fdup(float x){ ull r; asm("mov.b64 %0, {%1, %1};" : "=l"(r) : "f"(x)); return r; }
DEV float2 u2f(ull v){ float2 r; asm("mov.b64 {%0, %1}, %2;" : "=f"(r.x), "=f"(r.y) : "l"(v)); return r; }
DEV void fma2(ull& d, ull a, ull b){ asm("fma.rn.f32x2 %0, %1, %2, %0;" : "+l"(d) : "l"(a), "l"(b)); }

// ---- scratch offsets (floats) ----
#define O_LL0 0ull
#define O_HI0 2359296ull
#define O_LL1 11796480ull
#define O_HI1 12386304ull
#define O_LM0 14745600ull
#define O_LM1 17104896ull
#define O_RC  17694720ull
#define O_XZ  20054016ull
#define O_XS  29491200ull
#define O_DT  34209792ull
#define O_BC  38928384ull
#define O_YS  40108032ull
#define O_AT  44826624ull
#define O_HL  45416448ull
#define O_HIN 46006272ull
#define O_WTP 46596096ull
#define O_IWP 46698496ull
#define O_AB  46800896ull
#define O_WE  46802944ull
#define S_TOT 46827520ull

__device__ __align__(16) float g_scratch[S_TOT];

// ---- prep: pack filters, A=-exp(A_log), Weff2 = [Wcomb ; W_x rows 4..35 ; zeros] ----
__global__ void prep_k(const float* __restrict__ wt, const float* __restrict__ iwt,
                       const float* __restrict__ A_log, const float* __restrict__ W_x,
                       const float* __restrict__ W_dt, float* __restrict__ base)
{
    int i = blockIdx.x * 256 + threadIdx.x;
    if (i < 51200) {
        int ic = i / 800, r = i % 800, t = r / 32, op = r % 32;
        float2* wp = (float2*)(base + O_WTP);
        float2* ip = (float2*)(base + O_IWP);
        wp[i] = make_float2(wt[((2*op)*64 + ic)*25 + t], wt[((2*op+1)*64 + ic)*25 + t]);
        ip[i] = make_float2(iwt[((2*op)*64 + ic)*25 + t], iwt[((2*op+1)*64 + ic)*25 + t]);
    }
    if (i < 2048) base[O_AB + i] = -__expf(A_log[i]);
    if (i < 16384) {
        int d = i >> 7, k = i & 127;
        float s = 0.f;
        #pragma unroll
        for (int r = 0; r < 4; r++) s += W_dt[d*4 + r] * W_x[r*128 + k];
        base[O_WE + i] = s;
    }
    if (i < 8192) {
        int j = i >> 7, k = i & 127;
        base[O_WE + (size_t)(128 + j)*128 + k] = (j < 32) ? W_x[(4 + j)*128 + k] : 0.f;
    }
}

// ---- 5x5 conv 64->64, SAME. INMODE: 0 plain, 1 transposed-seq, 2 depth-to-space(ll+high)
//      OUTMODE: 0 plain, 1 space-to-depth split (s0->outLL seq, s1..3->outP bands) ----
template<int INMODE, int OUTMODE>
__global__ void __launch_bounds__(256) conv5_k(const float* __restrict__ in, const float* __restrict__ llB,
    const float* __restrict__ high, const float2* __restrict__ wp,
    float* __restrict__ outP, float* __restrict__ outLL, int H, int W)
{
    __shared__ float ism[32 * 240];
    int t = threadIdx.x, ocp = t & 31, row = t >> 5;
    int b = blockIdx.z, x0 = blockIdx.x * 16, y0 = blockIdx.y * 8;
    int h2 = H >> 1, w2 = W >> 1, L2 = h2 * w2;
    ull acc[16];
    #pragma unroll
    for (int px = 0; px < 16; px++) acc[px] = 0ull;

    for (int icc = 0; icc < 2; icc++) {
        __syncthreads();
        for (int i = t; i < 7680; i += 256) {
            int icl = i / 240, rem = i % 240, r, c;
            if (INMODE == 1) { c = rem / 12; r = rem % 12; }
            else             { r = rem / 20; c = rem % 20; }
            int gy = y0 + r - 2, gx = x0 + c - 2, ic = icc * 32 + icl;
            float v = 0.f;
            if ((unsigned)gy < (unsigned)H && (unsigned)gx < (unsigned)W) {
                if (INMODE == 0)      v = in[(((size_t)b*64 + ic)*H + gy)*W + gx];
                else if (INMODE == 1) v = in[(((size_t)b*64 + ic)*W + gx)*H + gy];
                else {
                    int s = (gy & 1)*2 + (gx & 1), hy = gy >> 1, hx = gx >> 1;
                    if (s == 0) {
                        v = in[((size_t)b*64 + ic)*L2 + hx*h2 + hy];
                        if (llB) v += llB[(((size_t)b*64 + ic)*h2 + hy)*w2 + hx];
                    } else {
                        v = high[((((size_t)b*64 + ic)*4 + s)*h2 + hy)*w2 + hx];
                    }
                }
            }
            ism[icl*240 + r*20 + c] = v;
        }
        __syncthreads();
        for (int icl = 0; icl < 32; icl++) {
            const float* ib = ism + icl*240 + row*20;
            const float2* wb = wp + ((size_t)(icc*32 + icl)*25)*32 + ocp;
            #pragma unroll
            for (int ky = 0; ky < 5; ky++) {
                const float* rp = ib + ky*20;
                float f[20];
                #pragma unroll
                for (int j = 0; j < 5; j++) *(float4*)&f[j*4] = *(const float4*)(rp + j*4);
                ull ff[20];
                #pragma unroll
                for (int j = 0; j < 20; j++) ff[j] = fdup(f[j]);
                #pragma unroll
                for (int kx = 0; kx < 5; kx++) {
                    ull wu = *(const ull*)(wb + (size_t)(ky*5 + kx)*32);
                    #pragma unroll
                    for (int px = 0; px < 16; px++) fma2(acc[px], ff[px + kx], wu);
                }
            }
        }
    }

    int gy = y0 + row, oc0 = ocp * 2;
    if (OUTMODE == 0) {
        float* o0 = outP + (((size_t)b*64 + oc0)*H + gy)*W + x0;
        float* o1 = o0 + (size_t)H * W;
        #pragma unroll
        for (int px = 0; px < 16; px++) { float2 v = u2f(acc[px]); o0[px] = v.x; o1[px] = v.y; }
    } else {
        int p = gy & 1, hy = gy >> 1;
        #pragma unroll
        for (int px = 0; px < 16; px++) {
            int gx = x0 + px, s = p*2 + (gx & 1), hx = gx >> 1;
            float2 v = u2f(acc[px]);
            if (s == 0) {
                outLL[((size_t)b*64 + oc0)*L2 + hx*h2 + hy]     = v.x;
                outLL[((size_t)b*64 + oc0 + 1)*L2 + hx*h2 + hy] = v.y;
            } else {
                size_t o = (((size_t)b*64 + oc0)*4 + s)*h2;
                outP[(o + hy)*w2 + hx]          = v.x;
                outP[(o + 4*h2 + hy)*w2 + hx]   = v.y;
            }
        }
    }
}

DEV float softplus_f(float x){ return fmaxf(x, 0.f) + log1pf(__expf(-fabsf(x))); }

// ---- GEMM C[M,N] = A[M,K] @ W[N,K]^T. AMODE: 0 plain(lda), 1 seq-gather.
//      EPI: 1 xz plain(ldc=256), 2 dt(softplus)+BC split, 3 scatter to seq layout ----
template<int AMODE, int EPI>
__global__ void __launch_bounds__(256) gemm_k(const float* __restrict__ A, const float* __restrict__ W,
    float* __restrict__ out, const float* __restrict__ bias, int K, int lda, int L, float* __restrict__ base)
{
    __shared__ ull  At2[32 * 65];
    __shared__ float Wt[32 * 66];
    int t = threadIdx.x, tx = t & 15, ty = t >> 4;
    int m0 = blockIdx.x * 64, n0 = blockIdx.y * 64;
    int b = m0 / L, l0 = m0 % L;
    ull acc[4][2];
    #pragma unroll
    for (int i = 0; i < 4; i++) { acc[i][0] = 0ull; acc[i][1] = 0ull; }

    for (int kc = 0; kc < K; kc += 32) {
        __syncthreads();
        if (AMODE == 0) {
            for (int i = t; i < 512; i += 256) {
                int kq = i >> 6, ml = i & 63;
                float4 v = *(const float4*)(A + (size_t)(m0 + ml)*lda + kc + kq*4);
                At2[(kq*4+0)*65 + ml] = fdup(v.x);
                At2[(kq*4+1)*65 + ml] = fdup(v.y);
                At2[(kq*4+2)*65 + ml] = fdup(v.z);
                At2[(kq*4+3)*65 + ml] = fdup(v.w);
            }
        } else {
            for (int i = t; i < 2048; i += 256) {
                int k = i >> 6, ml = i & 63;
                At2[k*65 + ml] = fdup(A[((size_t)b*64 + kc + k)*L + l0 + ml]);
            }
        }
        for (int i = t; i < 512; i += 256) {
            int kq = i >> 6, nl = i & 63;
            float4 v = *(const float4*)(W + (size_t)(n0 + nl)*K + kc + kq*4);
            Wt[(kq*4+0)*66 + nl] = v.x;
            Wt[(kq*4+1)*66 + nl] = v.y;
            Wt[(kq*4+2)*66 + nl] = v.z;
            Wt[(kq*4+3)*66 + nl] = v.w;
        }
        __syncthreads();
        #pragma unroll 4
        for (int k = 0; k < 32; k++) {
            ull a0 = At2[k*65 + ty*4 + 0];
            ull a1 = At2[k*65 + ty*4 + 1];
            ull a2 = At2[k*65 + ty*4 + 2];
            ull a3 = At2[k*65 + ty*4 + 3];
            ull w0 = *(const ull*)&Wt[k*66 + tx*4];
            ull w1 = *(const ull*)&Wt[k*66 + tx*4 + 2];
            fma2(acc[0][0], a0, w0); fma2(acc[0][1], a0, w1);
            fma2(acc[1][0], a1, w0); fma2(acc[1][1], a1, w1);
            fma2(acc[2][0], a2, w0); fma2(acc[2][1], a2, w1);
            fma2(acc[3][0], a3, w0); fma2(acc[3][1], a3, w1);
        }
    }

    #pragma unroll
    for (int i = 0; i < 4; i++) {
        int m = m0 + ty*4 + i;
        #pragma unroll
        for (int j = 0; j < 2; j++) {
            float2 c = u2f(acc[i][j]);
            int n = n0 + tx*4 + j*2;
            if (EPI == 1) {
                out[(size_t)m*256 + n]     = c.x;
                out[(size_t)m*256 + n + 1] = c.y;
            } else if (EPI == 2) {
                float cv[2] = {c.x, c.y};
                #pragma unroll
                for (int q = 0; q < 2; q++) {
                    int nn = n + q;
                    if (nn < 128)      base[O_DT + (size_t)m*128 + nn] = softplus_f(cv[q] + bias[nn]);
                    else if (nn < 160) base[O_BC + (size_t)m*32 + nn - 128] = cv[q];
                }
            } else { // EPI 3
                int l = l0 + ty*4 + i;
                out[((size_t)b*64 + n)*L + l]     = c.x;
                out[((size_t)b*64 + n + 1)*L + l] = c.y;
            }
        }
    }
}

// ---- depthwise causal conv (k=4) + silu ----
__global__ void dwconv_k(const float* __restrict__ cw, const float* __restrict__ cb, int L, float* __restrict__ base)
{
    size_t g = (size_t)blockIdx.x * 256 + threadIdx.x;
    int d = (int)(g & 127);
    size_t m = g >> 7;
    int l = (int)(m % (size_t)L);
    const float* xz = base + O_XZ;
    float acc = cb[d];
    #pragma unroll
    for (int j = 0; j < 4; j++) {
        int lj = l - 3 + j;
        if (lj >= 0) acc = fmaf(cw[d*4 + j], xz[(m - 3 + j)*256 + d], acc);
    }
    base[O_XS + g] = acc * __fdividef(1.f, 1.f + __expf(-acc));
}

// ---- scan phase 1: per-chunk local scan -> (A_prod, h_local) ----
__global__ void scan1_k(int L, int NCH, float* __restrict__ base)
{
    int t = threadIdx.x, s = t & 15;
    int ch = blockIdx.y, b = blockIdx.z, d = blockIdx.x * 16 + (t >> 4);
    const float* dt = base + O_DT; const float* xs = base + O_XS; const float* bc = base + O_BC;
    float a = base[O_AB + d*16 + s];
    float h = 0.f, P = 1.f;
    size_t ml = (size_t)b*L + (size_t)ch*128;
    for (int i = 0; i < 128; i++) {
        size_t m = ml + i;
        float dtv = __ldg(dt + m*128 + d);
        float e  = __expf(dtv * a);
        float bm = __ldg(bc + m*32 + s);
        float xv = __ldg(xs + m*128 + d);
        h = h*e + dtv*xv*bm;
        P *= e;
    }
    size_t ix = (((size_t)(b*NCH + ch)*128) + d)*16 + s;
    base[O_AT + ix] = P;
    base[O_HL + ix] = h;
}

// ---- scan phase 2: sequential over chunks -> carry-in per chunk ----
__global__ void scan2_k(int NCH, float* __restrict__ base)
{
    int g = blockIdx.x * 256 + threadIdx.x;
    int b = g >> 11, ds = g & 2047;
    float carry = 0.f;
    for (int ch = 0; ch < NCH; ch++) {
        size_t ix = ((size_t)(b*NCH + ch))*2048 + ds;
        base[O_HIN + ix] = carry;
        carry = carry * base[O_AT + ix] + base[O_HL + ix];
    }
}

// ---- scan phase 3: full scan with carry-in, emit y ----
__global__ void scan3_k(int L, int NCH, float* __restrict__ base)
{
    int t = threadIdx.x, s = t & 15;
    int ch = blockIdx.y, b = blockIdx.z, d = blockIdx.x * 16 + (t >> 4);
    const float* dt = base + O_DT; const float* xs = base + O_XS; const float* bc = base + O_BC;
    float a = base[O_AB + d*16 + s];
    size_t ix = (((size_t)(b*NCH + ch)*128) + d)*16 + s;
    float h = base[O_HIN + ix];
    size_t ml = (size_t)b*L + (size_t)ch*128;
    for (int i = 0; i < 128; i++) {
        size_t m = ml + i;
        float dtv = __ldg(dt + m*128 + d);
        float e  = __expf(dtv * a);
        float bm = __ldg(bc + m*32 + s);
        float xv = __ldg(xs + m*128 + d);
        h = h*e + dtv*xv*bm;
        float part = h * __ldg(bc + m*32 + 16 + s);
        part += __shfl_xor_sync(0xffffffffu, part, 8);
        part += __shfl_xor_sync(0xffffffffu, part, 4);
        part += __shfl_xor_sync(0xffffffffu, part, 2);
        part += __shfl_xor_sync(0xffffffffu, part, 1);
        if (s == 0) base[O_YS + m*128 + d] = part;
    }
}

// ---- y = (y_scan + xs*D) * silu(z) ----
__global__ void ymul_k(const float* __restrict__ Dp, float* __restrict__ base)
{
    size_t g = (size_t)blockIdx.x * 256 + threadIdx.x;
    int d = (int)(g & 127);
    size_t m = g >> 7;
    float z = base[O_XZ + m*256 + 128 + d];
    float sz = z * __fdividef(1.f, 1.f + __expf(-z));
    base[O_YS + g] = (base[O_YS + g] + base[O_XS + g] * Dp[d]) * sz;
}

extern "C" void kernel_launch(void* const* d_in, const int* in_sizes, int n_in,
                              void* d_out, int out_size)
{
    const float* x      = (const float*)d_in[0];
    const float* wt     = (const float*)d_in[1];
    const float* iwt    = (const float*)d_in[2];
    const float* W_in   = (const float*)d_in[3];
    const float* conv_w = (const float*)d_in[4];
    const float* conv_b = (const float*)d_in[5];
    const float* W_x    = (const float*)d_in[6];
    const float* W_dt   = (const float*)d_in[7];
    const float* b_dt   = (const float*)d_in[8];
    const float* A_log  = (const float*)d_in[9];
    const float* Dp     = (const float*)d_in[10];
    const float* W_out  = (const float*)d_in[11];
    (void)in_sizes; (void)n_in; (void)out_size;

    float* S = nullptr;
    cudaGetSymbolAddress((void**)&S, g_scratch);

    prep_k<<<200, 256>>>(wt, iwt, A_log, W_x, W_dt, S);

    auto mamba = [&](int L, int NCH, const float* llseq, float* llm) {
        int M = 4 * L;
        gemm_k<1,1><<<dim3(M/64, 4), 256>>>(llseq, W_in, S + O_XZ, nullptr, 64, 0, L, S);
        dwconv_k<<<(M*128)/256, 256>>>(conv_w, conv_b, L, S);
        gemm_k<0,2><<<dim3(M/64, 3), 256>>>(S + O_XS, S + O_WE, nullptr, b_dt, 128, 128, L, S);
        scan1_k<<<dim3(8, NCH, 4), 256>>>(L, NCH, S);
        scan2_k<<<32, 256>>>(NCH, S);
        scan3_k<<<dim3(8, NCH, 4), 256>>>(L, NCH, S);
        ymul_k<<<(M*128)/256, 256>>>(Dp, S);
        gemm_k<0,3><<<dim3(M/64, 1), 256>>>(S + O_YS, W_out, llm, nullptr, 128, 128, L, S);
    };

    // level 0 decomposition (192x192 -> 96x96)
    conv5_k<0,1><<<dim3(12,24,4), 256>>>(x, nullptr, nullptr, (const float2*)(S + O_WTP),
                                         S + O_HI0, S + O_LL0, 192, 192);
    mamba(9216, 72, S + O_LL0, S + O_LM0);
    // level 1 decomposition (96x96 -> 48x48) on raw LL0
    conv5_k<1,1><<<dim3(6,12,4), 256>>>(S + O_LL0, nullptr, nullptr, (const float2*)(S + O_WTP),
                                        S + O_HI1, S + O_LL1, 96, 96);
    mamba(2304, 18, S + O_LL1, S + O_LM1);
    // reconstruction level 1 -> 96x96
    conv5_k<2,0><<<dim3(6,12,4), 256>>>(S + O_LM1, nullptr, S + O_HI1, (const float2*)(S + O_IWP),
                                        S + O_RC, nullptr, 96, 96);
    // reconstruction level 0 -> 192x192 (final output)
    conv5_k<2,0><<<dim3(12,24,4), 256>>>(S + O_LM0, S + O_RC, S + O_HI0, (const float2*)(S + O_IWP),
                                         (float*)d_out, nullptr, 192, 192);
}

// round 6
// speedup vs baseline: 1.4565x; 1.4533x over previous
#include <cuda_runtime.h>
#include <cuda_bf16.h>
#include <cstdint>

typedef unsigned long long ull;
typedef unsigned int u32;
#define DEV static __device__ __forceinline__

DEV ull fdup(float x){ ull r; asm("mov.b64 %0, {%1, %1};" : "=l"(r) : "f"(x)); return r; }
DEV float2 u2f(ull v){ float2 r; asm("mov.b64 {%0, %1}, %2;" : "=f"(r.x), "=f"(r.y) : "l"(v)); return r; }
DEV void fma2(ull& d, ull a, ull b){ asm("fma.rn.f32x2 %0, %1, %2, %0;" : "+l"(d) : "l"(a), "l"(b)); }
DEV u32 bpack(float lo, float hi){ u32 r; asm("cvt.rn.bf16x2.f32 %0, %2, %1;" : "=r"(r) : "f"(lo), "f"(hi)); return r; }
DEV float bres(float a){ u32 t = bpack(a, a); return a - __uint_as_float(t & 0xFFFF0000u); }
DEV u32 s2u(const void* p){ u32 a; asm("{ .reg .u64 t; cvta.to.shared.u64 t, %1; cvt.u32.u64 %0, t; }" : "=r"(a) : "l"(p)); return a; }

DEV void ldsm4(u32* r, u32 a){ asm volatile("ldmatrix.sync.aligned.m8n8.x4.shared.b16 {%0,%1,%2,%3}, [%4];"
  : "=r"(r[0]),"=r"(r[1]),"=r"(r[2]),"=r"(r[3]) : "r"(a)); }
DEV void ldsm2(u32* r, u32 a){ asm volatile("ldmatrix.sync.aligned.m8n8.x2.shared.b16 {%0,%1}, [%2];"
  : "=r"(r[0]),"=r"(r[1]) : "r"(a)); }
DEV void mma16816(float* c, const u32* a, const u32* b){
  asm volatile("mma.sync.aligned.m16n8k16.row.col.f32.bf16.bf16.f32 {%0,%1,%2,%3},{%4,%5,%6,%7},{%8,%9},{%0,%1,%2,%3};"
    : "+f"(c[0]),"+f"(c[1]),"+f"(c[2]),"+f"(c[3])
    : "r"(a[0]),"r"(a[1]),"r"(a[2]),"r"(a[3]),"r"(b[0]),"r"(b[1]));
}
DEV void cpasync16(u32 dst, const void* src){
  asm volatile("cp.async.cg.shared.global [%0], [%1], 16;" :: "r"(dst), "l"(src) : "memory");
}
#define CP_COMMIT() asm volatile("cp.async.commit_group;" ::: "memory")
#define CP_WAIT1()  asm volatile("cp.async.wait_group 1;" ::: "memory")
#define CP_WAIT0()  asm volatile("cp.async.wait_group 0;" ::: "memory")

// ---- scratch offsets (floats) ----
#define O_LL0 0ull
#define O_HI0 2359296ull
#define O_LL1 11796480ull
#define O_HI1 12386304ull
#define O_LM0 14745600ull
#define O_LM1 17104896ull
#define O_RC  17694720ull
#define O_XZ  20054016ull
#define O_XS  29491200ull
#define O_DT  34209792ull
#define O_BC  38928384ull
#define O_YS  40108032ull
#define O_AT  44826624ull
#define O_HL  45416448ull
#define O_HIN 46006272ull
#define O_WB  46596096ull
#define O_AB  46800896ull
#define O_WE  46802944ull
#define O_PAD 46827520ull
#define S_TOT 56662016ull

__device__ __align__(16) float g_scratch[S_TOT];

// ---- prep: bf16 hi/lo weight slabs, A=-exp(A_log), Weff ----
__global__ void prep_k(const float* __restrict__ wt, const float* __restrict__ iwt,
                       const float* __restrict__ A_log, const float* __restrict__ W_x,
                       const float* __restrict__ W_dt, float* __restrict__ base)
{
    int i = blockIdx.x * 256 + threadIdx.x;
    if (i < 204800) {
        int f = i / 102400, r = i % 102400, term = r / 51200;
        int tap = (r / 2048) % 25, r3 = r % 2048, oc = r3 >> 5, k2 = r3 & 31;
        const float* filt = f ? iwt : wt;
        float w0 = filt[(oc*64 + 2*k2)*25 + tap];
        float w1 = filt[(oc*64 + 2*k2 + 1)*25 + tap];
        u32 v = term ? bpack(bres(w0), bres(w1)) : bpack(w0, w1);
        ((u32*)base)[O_WB + i] = v;
    }
    if (i < 2048) base[O_AB + i] = -__expf(A_log[i]);
    if (i < 16384) {
        int d = i >> 7, k = i & 127;
        float s = 0.f;
        #pragma unroll
        for (int r = 0; r < 4; r++) s += W_dt[d*4 + r] * W_x[r*128 + k];
        base[O_WE + i] = s;
    }
    if (i < 8192) {
        int j = i >> 7, k = i & 127;
        base[O_WE + (size_t)(128 + j)*128 + k] = (j < 32) ? W_x[(4 + j)*128 + k] : 0.f;
    }
}

// ---- pad into NHWC. MODE: 0 plain NCHW, 1 transposed-seq, 2 depth-to-space ----
template<int MODE>
__global__ void pad_k(const float* __restrict__ in, const float* __restrict__ llB,
                      const float* __restrict__ high, float* __restrict__ PAD, int H, int W)
{
    int ic = threadIdx.x, xp = blockIdx.x, yp = blockIdx.y, b = blockIdx.z;
    int X = W + 4, xi = xp - 2, yi = yp - 2;
    float v = 0.f;
    if ((unsigned)xi < (unsigned)W && (unsigned)yi < (unsigned)H) {
        if (MODE == 0)      v = in[(((size_t)b*64 + ic)*H + yi)*W + xi];
        else if (MODE == 1) v = in[(((size_t)b*64 + ic)*W + xi)*H + yi];
        else {
            int h2 = H>>1, w2 = W>>1, L2 = h2*w2, s = (yi&1)*2 + (xi&1), hy = yi>>1, hx = xi>>1;
            if (s == 0) {
                v = in[((size_t)b*64 + ic)*L2 + hx*h2 + hy];
                if (llB) v += llB[(((size_t)b*64 + ic)*h2 + hy)*w2 + hx];
            } else v = high[((((size_t)b*64 + ic)*4 + s)*h2 + hy)*w2 + hx];
        }
    }
    PAD[(((size_t)b*(H+4) + yp)*X + xp)*64 + ic] = v;
}

// ---- warp-MMA bf16 3-term conv: M=128(2rows x 64px), N=64 oc, 25 taps x K=64 ic ----
// smem: A hi [6][68][72]bf16 @0 (58752B), A lo @58752, B [2buf][2term][64][72]bf16 @117504 (36864B)
#define CSM 154368
__global__ void __launch_bounds__(256, 1) convt_k(
    const float* __restrict__ PAD, const u32* __restrict__ WBu,
    float* __restrict__ outP, float* __restrict__ outLL, int H, int W, int OUTMODE)
{
    extern __shared__ char sm[];
    u32 su = s2u(sm);
    int tid = threadIdx.x, wid = tid >> 5, lane = tid & 31;
    int wm = wid & 3, wn = wid >> 2;
    int b = blockIdx.z, Y0 = blockIdx.y * 2, x0 = blockIdx.x * 64;
    int X = W + 4;

    // --- load + convert 6x68x64 window to bf16 hi/lo ---
    for (int i = tid; i < 6528; i += 256) {
        int r = i / 1088, rem = i % 1088, xx = rem >> 4, kg = rem & 15;
        float4 v = make_float4(0.f,0.f,0.f,0.f);
        if (x0 + xx < X)
            v = *(const float4*)(PAD + (((size_t)b*(H+4) + Y0 + r)*X + x0 + xx)*64 + kg*4);
        u32 off = (u32)((r*68 + xx)*144 + kg*8);
        *(uint2*)(sm + off)         = make_uint2(bpack(v.x, v.y), bpack(v.z, v.w));
        *(uint2*)(sm + 58752 + off) = make_uint2(bpack(bres(v.x), bres(v.y)), bpack(bres(v.z), bres(v.w)));
    }

    // --- B prefetch: taps 0,1 ---
    const u32* WT = WBu;               // term-major: [term][tap][oc][32]
    auto issueB = [&](int tap, int buf) {
        for (int it = 0; it < 4; it++) {
            int u = it*256 + tid, term = u >> 9, oc = (u >> 3) & 63, ch = u & 7;
            u32 dst = su + 117504u + (u32)(buf*2 + term)*9216u + (u32)(oc*144 + ch*16);
            cpasync16(dst, WT + ((size_t)(term*25 + tap)*64 + oc)*32 + ch*4);
        }
        CP_COMMIT();
    };
    issueB(0, 0);
    issueB(1, 1);
    __syncthreads();   // A window visible

    // --- per-lane constant frag address bases ---
    u32 abase[2], bbase[4];
    #pragma unroll
    for (int mt = 0; mt < 2; mt++) {
        int pix = wm*32 + mt*16 + (lane & 15);
        abase[mt] = (u32)(((pix >> 6)*68 + (pix & 63))*144 + ((lane >> 4)*16));
    }
    #pragma unroll
    for (int nt = 0; nt < 4; nt++) {
        int bn = wn*32 + nt*8 + (lane & 7);
        bbase[nt] = su + 117504u + (u32)(bn*144 + ((lane >> 3) & 1)*16);
    }

    float acc[2][4][4];
    #pragma unroll
    for (int mt = 0; mt < 2; mt++)
        #pragma unroll
        for (int nt = 0; nt < 4; nt++)
            #pragma unroll
            for (int q = 0; q < 4; q++) acc[mt][nt][q] = 0.f;

    for (int tap = 0; tap < 25; tap++) {
        if (tap < 24) CP_WAIT1(); else CP_WAIT0();
        __syncthreads();
        int p = tap & 1, dy = tap / 5, dx = tap % 5;
        u32 tapoff = (u32)((dy*68 + dx)*144);
        u32 aH = su + tapoff, aL = su + 58752u + tapoff;
        u32 bP = (u32)(p*2)*9216u;

        #pragma unroll
        for (int ks = 0; ks < 4; ks++) {
            u32 ko = (u32)(ks*32);
            u32 ah[2][4], al[2][4], bh[4][2], bl[4][2];
            #pragma unroll
            for (int mt = 0; mt < 2; mt++) {
                ldsm4(ah[mt], aH + abase[mt] + ko);
                ldsm4(al[mt], aL + abase[mt] + ko);
            }
            #pragma unroll
            for (int nt = 0; nt < 4; nt++) {
                ldsm2(bh[nt], bbase[nt] + bP + ko);
                ldsm2(bl[nt], bbase[nt] + bP + 9216u + ko);
            }
            #pragma unroll
            for (int mt = 0; mt < 2; mt++)
                #pragma unroll
                for (int nt = 0; nt < 4; nt++) {
                    mma16816(acc[mt][nt], ah[mt], bh[nt]);
                    mma16816(acc[mt][nt], ah[mt], bl[nt]);
                    mma16816(acc[mt][nt], al[mt], bh[nt]);
                }
        }
        __syncthreads();
        if (tap + 2 <= 24) issueB(tap + 2, p);
    }

    // --- epilogue ---
    int g = lane >> 2, t4 = lane & 3;
    int h2 = H >> 1, w2 = W >> 1, L2 = h2*w2;
    #pragma unroll
    for (int mt = 0; mt < 2; mt++)
        #pragma unroll
        for (int half = 0; half < 2; half++) {
            int m = wm*32 + mt*16 + g + half*8;
            int y = Y0 + (m >> 6), gx = x0 + (m & 63);
            if (gx >= W) continue;
            #pragma unroll
            for (int nt = 0; nt < 4; nt++) {
                #pragma unroll
                for (int q = 0; q < 2; q++) {
                    int oc = wn*32 + nt*8 + 2*t4 + q;
                    float v = acc[mt][nt][half*2 + q];
                    if (OUTMODE == 0) {
                        outP[(((size_t)b*64 + oc)*H + y)*W + gx] = v;
                    } else {
                        int s = (y & 1)*2 + (gx & 1), hy = y >> 1, hx = gx >> 1;
                        if (s == 0) outLL[((size_t)b*64 + oc)*L2 + hx*h2 + hy] = v;
                        else        outP[((((size_t)b*64 + oc)*4 + s)*h2 + hy)*w2 + hx] = v;
                    }
                }
            }
        }
}

DEV float softplus_f(float x){ return fmaxf(x, 0.f) + log1pf(__expf(-fabsf(x))); }

// ---- GEMM C[M,N] = A[M,K] @ W[N,K]^T ----
template<int AMODE, int EPI>
__global__ void __launch_bounds__(256) gemm_k(const float* __restrict__ A, const float* __restrict__ W,
    float* __restrict__ out, const float* __restrict__ bias, int K, int lda, int L, float* __restrict__ base)
{
    __shared__ ull  At2[32 * 65];
    __shared__ float Wt[32 * 66];
    int t = threadIdx.x, tx = t & 15, ty = t >> 4;
    int m0 = blockIdx.x * 64, n0 = blockIdx.y * 64;
    int b = m0 / L, l0 = m0 % L;
    ull acc[4][2];
    #pragma unroll
    for (int i = 0; i < 4; i++) { acc[i][0] = 0ull; acc[i][1] = 0ull; }
    for (int kc = 0; kc < K; kc += 32) {
        __syncthreads();
        if (AMODE == 0) {
            for (int i = t; i < 512; i += 256) {
                int kq = i >> 6, ml = i & 63;
                float4 v = *(const float4*)(A + (size_t)(m0 + ml)*lda + kc + kq*4);
                At2[(kq*4+0)*65 + ml] = fdup(v.x);
                At2[(kq*4+1)*65 + ml] = fdup(v.y);
                At2[(kq*4+2)*65 + ml] = fdup(v.z);
                At2[(kq*4+3)*65 + ml] = fdup(v.w);
            }
        } else {
            for (int i = t; i < 2048; i += 256) {
                int k = i >> 6, ml = i & 63;
                At2[k*65 + ml] = fdup(A[((size_t)b*64 + kc + k)*L + l0 + ml]);
            }
        }
        for (int i = t; i < 512; i += 256) {
            int kq = i >> 6, nl = i & 63;
            float4 v = *(const float4*)(W + (size_t)(n0 + nl)*K + kc + kq*4);
            Wt[(kq*4+0)*66 + nl] = v.x;
            Wt[(kq*4+1)*66 + nl] = v.y;
            Wt[(kq*4+2)*66 + nl] = v.z;
            Wt[(kq*4+3)*66 + nl] = v.w;
        }
        __syncthreads();
        #pragma unroll 4
        for (int k = 0; k < 32; k++) {
            ull a0 = At2[k*65 + ty*4], a1 = At2[k*65 + ty*4 + 1];
            ull a2 = At2[k*65 + ty*4 + 2], a3 = At2[k*65 + ty*4 + 3];
            ull w0 = *(const ull*)&Wt[k*66 + tx*4], w1 = *(const ull*)&Wt[k*66 + tx*4 + 2];
            fma2(acc[0][0], a0, w0); fma2(acc[0][1], a0, w1);
            fma2(acc[1][0], a1, w0); fma2(acc[1][1], a1, w1);
            fma2(acc[2][0], a2, w0); fma2(acc[2][1], a2, w1);
            fma2(acc[3][0], a3, w0); fma2(acc[3][1], a3, w1);
        }
    }
    #pragma unroll
    for (int i = 0; i < 4; i++) {
        int m = m0 + ty*4 + i;
        #pragma unroll
        for (int j = 0; j < 2; j++) {
            float2 c = u2f(acc[i][j]);
            int n = n0 + tx*4 + j*2;
            if (EPI == 1) {
                out[(size_t)m*256 + n] = c.x;
                out[(size_t)m*256 + n + 1] = c.y;
            } else if (EPI == 2) {
                float cv[2] = {c.x, c.y};
                #pragma unroll
                for (int q = 0; q < 2; q++) {
                    int nn = n + q;
                    if (nn < 128)      base[O_DT + (size_t)m*128 + nn] = softplus_f(cv[q] + bias[nn]);
                    else if (nn < 160) base[O_BC + (size_t)m*32 + nn - 128] = cv[q];
                }
            } else {
                int l = l0 + ty*4 + i;
                out[((size_t)b*64 + n)*L + l]     = c.x;
                out[((size_t)b*64 + n + 1)*L + l] = c.y;
            }
        }
    }
}

__global__ void dwconv_k(const float* __restrict__ cw, const float* __restrict__ cb, int L, float* __restrict__ base)
{
    size_t g = (size_t)blockIdx.x * 256 + threadIdx.x;
    int d = (int)(g & 127);
    size_t m = g >> 7;
    int l = (int)(m % (size_t)L);
    const float* xz = base + O_XZ;
    float acc = cb[d];
    #pragma unroll
    for (int j = 0; j < 4; j++) {
        int lj = l - 3 + j;
        if (lj >= 0) acc = fmaf(cw[d*4 + j], xz[(m - 3 + j)*256 + d], acc);
    }
    base[O_XS + g] = acc * __fdividef(1.f, 1.f + __expf(-acc));
}

__global__ void scan1_k(int L, int NCH, float* __restrict__ base)
{
    int t = threadIdx.x, s = t & 15;
    int ch = blockIdx.y, b = blockIdx.z, d = blockIdx.x * 16 + (t >> 4);
    const float* dt = base + O_DT; const float* xs = base + O_XS; const float* bc = base + O_BC;
    float a = base[O_AB + d*16 + s];
    float h = 0.f, P = 1.f;
    size_t ml = (size_t)b*L + (size_t)ch*128;
    for (int i = 0; i < 128; i++) {
        size_t m = ml + i;
        float dtv = __ldg(dt + m*128 + d);
        float e = __expf(dtv * a);
        h = h*e + dtv*__ldg(xs + m*128 + d)*__ldg(bc + m*32 + s);
        P *= e;
    }
    size_t ix = (((size_t)(b*NCH + ch)*128) + d)*16 + s;
    base[O_AT + ix] = P;
    base[O_HL + ix] = h;
}

__global__ void scan2_k(int NCH, float* __restrict__ base)
{
    int g = blockIdx.x * 256 + threadIdx.x;
    int b = g >> 11, ds = g & 2047;
    float carry = 0.f;
    for (int ch = 0; ch < NCH; ch++) {
        size_t ix = ((size_t)(b*NCH + ch))*2048 + ds;
        base[O_HIN + ix] = carry;
        carry = carry * base[O_AT + ix] + base[O_HL + ix];
    }
}

__global__ void scan3_k(int L, int NCH, float* __restrict__ base)
{
    int t = threadIdx.x, s = t & 15;
    int ch = blockIdx.y, b = blockIdx.z, d = blockIdx.x * 16 + (t >> 4);
    const float* dt = base + O_DT; const float* xs = base + O_XS; const float* bc = base + O_BC;
    float a = base[O_AB + d*16 + s];
    size_t ix = (((size_t)(b*NCH + ch)*128) + d)*16 + s;
    float h = base[O_HIN + ix];
    size_t ml = (size_t)b*L + (size_t)ch*128;
    for (int i = 0; i < 128; i++) {
        size_t m = ml + i;
        float dtv = __ldg(dt + m*128 + d);
        float e = __expf(dtv * a);
        h = h*e + dtv*__ldg(xs + m*128 + d)*__ldg(bc + m*32 + s);
        float part = h * __ldg(bc + m*32 + 16 + s);
        part += __shfl_xor_sync(0xffffffffu, part, 8);
        part += __shfl_xor_sync(0xffffffffu, part, 4);
        part += __shfl_xor_sync(0xffffffffu, part, 2);
        part += __shfl_xor_sync(0xffffffffu, part, 1);
        if (s == 0) base[O_YS + m*128 + d] = part;
    }
}

__global__ void ymul_k(const float* __restrict__ Dp, float* __restrict__ base)
{
    size_t g = (size_t)blockIdx.x * 256 + threadIdx.x;
    int d = (int)(g & 127);
    size_t m = g >> 7;
    float z = base[O_XZ + m*256 + 128 + d];
    float sz = z * __fdividef(1.f, 1.f + __expf(-z));
    base[O_YS + g] = (base[O_YS + g] + base[O_XS + g] * Dp[d]) * sz;
}

extern "C" void kernel_launch(void* const* d_in, const int* in_sizes, int n_in,
                              void* d_out, int out_size)
{
    const float* x      = (const float*)d_in[0];
    const float* wt     = (const float*)d_in[1];
    const float* iwt    = (const float*)d_in[2];
    const float* W_in   = (const float*)d_in[3];
    const float* conv_w = (const float*)d_in[4];
    const float* conv_b = (const float*)d_in[5];
    const float* W_x    = (const float*)d_in[6];
    const float* W_dt   = (const float*)d_in[7];
    const float* b_dt   = (const float*)d_in[8];
    const float* A_log  = (const float*)d_in[9];
    const float* Dp     = (const float*)d_in[10];
    const float* W_out  = (const float*)d_in[11];
    (void)in_sizes; (void)n_in; (void)out_size;

    float* S = nullptr;
    cudaGetSymbolAddress((void**)&S, g_scratch);
    cudaFuncSetAttribute(convt_k, cudaFuncAttributeMaxDynamicSharedMemorySize, CSM);
    const u32* WB0 = (const u32*)S + O_WB;
    const u32* WB1 = WB0 + 102400;

    prep_k<<<800, 256>>>(wt, iwt, A_log, W_x, W_dt, S);

    auto mamba = [&](int L, int NCH, const float* llseq, float* llm) {
        int M = 4 * L;
        gemm_k<1,1><<<dim3(M/64, 4), 256>>>(llseq, W_in, S + O_XZ, nullptr, 64, 0, L, S);
        dwconv_k<<<(M*128)/256, 256>>>(conv_w, conv_b, L, S);
        gemm_k<0,2><<<dim3(M/64, 3), 256>>>(S + O_XS, S + O_WE, nullptr, b_dt, 128, 128, L, S);
        scan1_k<<<dim3(8, NCH, 4), 256>>>(L, NCH, S);
        scan2_k<<<32, 256>>>(NCH, S);
        scan3_k<<<dim3(8, NCH, 4), 256>>>(L, NCH, S);
        ymul_k<<<(M*128)/256, 256>>>(Dp, S);
        gemm_k<0,3><<<dim3(M/64, 1), 256>>>(S + O_YS, W_out, llm, nullptr, 128, 128, L, S);
    };

    pad_k<0><<<dim3(196,196,4), 64>>>(x, nullptr, nullptr, S + O_PAD, 192, 192);
    convt_k<<<dim3(3,96,4), 256, CSM>>>(S + O_PAD, WB0, S + O_HI0, S + O_LL0, 192, 192, 1);
    mamba(9216, 72, S + O_LL0, S + O_LM0);
    pad_k<1><<<dim3(100,100,4), 64>>>(S + O_LL0, nullptr, nullptr, S + O_PAD, 96, 96);
    convt_k<<<dim3(2,48,4), 256, CSM>>>(S + O_PAD, WB0, S + O_HI1, S + O_LL1, 96, 96, 1);
    mamba(2304, 18, S + O_LL1, S + O_LM1);
    pad_k<2><<<dim3(100,100,4), 64>>>(S + O_LM1, nullptr, S + O_HI1, S + O_PAD, 96, 96);
    convt_k<<<dim3(2,48,4), 256, CSM>>>(S + O_PAD, WB1, S + O_RC, nullptr, 96, 96, 0);
    pad_k<2><<<dim3(196,196,4), 64>>>(S + O_LM0, S + O_RC, S + O_HI0, S + O_PAD, 192, 192);
    convt_k<<<dim3(3,96,4), 256, CSM>>>(S + O_PAD, WB1, (float*)d_out, nullptr, 192, 192, 0);
}

// round 7
// speedup vs baseline: 1.6167x; 1.1100x over previous
#include <cuda_runtime.h>
#include <cuda_bf16.h>
#include <cstdint>

typedef unsigned int u32;
#define DEV static __device__ __forceinline__

DEV u32 bpack(float lo, float hi){ u32 r; asm("cvt.rn.bf16x2.f32 %0, %2, %1;" : "=r"(r) : "f"(lo), "f"(hi)); return r; }
DEV float bres(float a){ u32 t = bpack(a, a); return a - __uint_as_float(t & 0xFFFF0000u); }
DEV u32 s2u(const void* p){ u32 a; asm("{ .reg .u64 t; cvta.to.shared.u64 t, %1; cvt.u32.u64 %0, t; }" : "=r"(a) : "l"(p)); return a; }

DEV void ldsm4(u32* r, u32 a){ asm volatile("ldmatrix.sync.aligned.m8n8.x4.shared.b16 {%0,%1,%2,%3}, [%4];"
  : "=r"(r[0]),"=r"(r[1]),"=r"(r[2]),"=r"(r[3]) : "r"(a)); }
DEV void ldsm2(u32* r, u32 a){ asm volatile("ldmatrix.sync.aligned.m8n8.x2.shared.b16 {%0,%1}, [%2];"
  : "=r"(r[0]),"=r"(r[1]) : "r"(a)); }
DEV void mma16816(float* c, const u32* a, const u32* b){
  asm volatile("mma.sync.aligned.m16n8k16.row.col.f32.bf16.bf16.f32 {%0,%1,%2,%3},{%4,%5,%6,%7},{%8,%9},{%0,%1,%2,%3};"
    : "+f"(c[0]),"+f"(c[1]),"+f"(c[2]),"+f"(c[3])
    : "r"(a[0]),"r"(a[1]),"r"(a[2]),"r"(a[3]),"r"(b[0]),"r"(b[1]));
}
DEV void cpasync16(u32 dst, const void* src){
  asm volatile("cp.async.cg.shared.global [%0], [%1], 16;" :: "r"(dst), "l"(src) : "memory");
}
#define CP_COMMIT() asm volatile("cp.async.commit_group;" ::: "memory")
#define CP_WAIT1()  asm volatile("cp.async.wait_group 1;" ::: "memory")
#define CP_WAIT0()  asm volatile("cp.async.wait_group 0;" ::: "memory")

// ---- scratch offsets (floats) ----
#define O_LL0 0ull
#define O_HI0 2359296ull
#define O_LL1 11796480ull
#define O_HI1 12386304ull
#define O_LM0 14745600ull
#define O_LM1 17104896ull
#define O_RC  17694720ull
#define O_XZ  20054016ull
#define O_XS  29491200ull
#define O_DT  34209792ull
#define O_BC  38928384ull
#define O_YS  40108032ull
#define O_AT  44826624ull
#define O_HL  45416448ull
#define O_HIN 46006272ull
#define O_WB  46596096ull
#define O_AB  46800896ull
#define O_WE  46802944ull
#define O_PAD 46827520ull
#define O_WG  56662016ull
#define S_TOT 56711168ull

__device__ __align__(16) float g_scratch[S_TOT];

DEV float softplus_f(float x){ return fmaxf(x, 0.f) + log1pf(__expf(-fabsf(x))); }

// ---- prep: bf16 hi/lo conv-weight slabs, A=-exp(A_log), Weff ----
__global__ void prep_k(const float* __restrict__ wt, const float* __restrict__ iwt,
                       const float* __restrict__ A_log, const float* __restrict__ W_x,
                       const float* __restrict__ W_dt, float* __restrict__ base)
{
    int i = blockIdx.x * 256 + threadIdx.x;
    if (i < 204800) {
        int f = i / 102400, r = i % 102400, term = r / 51200;
        int tap = (r / 2048) % 25, r3 = r % 2048, oc = r3 >> 5, k2 = r3 & 31;
        const float* filt = f ? iwt : wt;
        float w0 = filt[(oc*64 + 2*k2)*25 + tap];
        float w1 = filt[(oc*64 + 2*k2 + 1)*25 + tap];
        u32 v = term ? bpack(bres(w0), bres(w1)) : bpack(w0, w1);
        ((u32*)base)[O_WB + i] = v;
    }
    if (i < 2048) base[O_AB + i] = -__expf(A_log[i]);
    if (i < 16384) {
        int d = i >> 7, k = i & 127;
        float s = 0.f;
        #pragma unroll
        for (int r = 0; r < 4; r++) s += W_dt[d*4 + r] * W_x[r*128 + k];
        base[O_WE + i] = s;
    }
    if (i < 8192) {
        int j = i >> 7, k = i & 127;
        base[O_WE + (size_t)(128 + j)*128 + k] = (j < 32) ? W_x[(4 + j)*128 + k] : 0.f;
    }
}

// ---- prep2: bf16 hi/lo GEMM weight slabs (W_in 256x64 | Weff 192x128 | W_out 64x128) ----
__global__ void prep2_k(const float* __restrict__ W_in, const float* __restrict__ W_out,
                        float* __restrict__ base)
{
    int i = blockIdx.x * 256 + threadIdx.x;
    if (i >= 49152) return;
    const float* src; int K, n, k2, term;
    if (i < 16384)      { term = i >> 13; int r = i & 8191;  n = r >> 5; k2 = r & 31; K = 64;  src = W_in; }
    else if (i < 40960) { int j = i - 16384; term = j / 12288; int r = j % 12288; n = r >> 6; k2 = r & 63; K = 128; src = base + O_WE; }
    else                { int j = i - 40960; term = j >> 12; int r = j & 4095;  n = r >> 6; k2 = r & 63; K = 128; src = W_out; }
    float w0 = src[(size_t)n*K + 2*k2], w1 = src[(size_t)n*K + 2*k2 + 1];
    ((u32*)base)[O_WG + i] = term ? bpack(bres(w0), bres(w1)) : bpack(w0, w1);
}

// ---- pad into NHWC. MODE: 0 plain NCHW, 1 transposed-seq, 2 depth-to-space ----
template<int MODE>
__global__ void pad_k(const float* __restrict__ in, const float* __restrict__ llB,
                      const float* __restrict__ high, float* __restrict__ PAD, int H, int W)
{
    int ic = threadIdx.x, xp = blockIdx.x, yp = blockIdx.y, b = blockIdx.z;
    int X = W + 4, xi = xp - 2, yi = yp - 2;
    float v = 0.f;
    if ((unsigned)xi < (unsigned)W && (unsigned)yi < (unsigned)H) {
        if (MODE == 0)      v = in[(((size_t)b*64 + ic)*H + yi)*W + xi];
        else if (MODE == 1) v = in[(((size_t)b*64 + ic)*W + xi)*H + yi];
        else {
            int h2 = H>>1, w2 = W>>1, L2 = h2*w2, s = (yi&1)*2 + (xi&1), hy = yi>>1, hx = xi>>1;
            if (s == 0) {
                v = in[((size_t)b*64 + ic)*L2 + hx*h2 + hy];
                if (llB) v += llB[(((size_t)b*64 + ic)*h2 + hy)*w2 + hx];
            } else v = high[((((size_t)b*64 + ic)*4 + s)*h2 + hy)*w2 + hx];
        }
    }
    PAD[(((size_t)b*(H+4) + yp)*X + xp)*64 + ic] = v;
}

// ---- warp-MMA bf16 3-term conv: M=128(2rows x 64px), N=64 oc, 25 taps x K=64 ic ----
#define CSM 154368
__global__ void __launch_bounds__(256, 1) convt_k(
    const float* __restrict__ PAD, const u32* __restrict__ WBu,
    float* __restrict__ outP, float* __restrict__ outLL, int H, int W, int OUTMODE)
{
    extern __shared__ char sm[];
    u32 su = s2u(sm);
    int tid = threadIdx.x, wid = tid >> 5, lane = tid & 31;
    int wm = wid & 3, wn = wid >> 2;
    int b = blockIdx.z, Y0 = blockIdx.y * 2, x0 = blockIdx.x * 64;
    int X = W + 4;

    for (int i = tid; i < 6528; i += 256) {
        int r = i / 1088, rem = i % 1088, xx = rem >> 4, kg = rem & 15;
        float4 v = make_float4(0.f,0.f,0.f,0.f);
        if (x0 + xx < X)
            v = *(const float4*)(PAD + (((size_t)b*(H+4) + Y0 + r)*X + x0 + xx)*64 + kg*4);
        u32 off = (u32)((r*68 + xx)*144 + kg*8);
        *(uint2*)(sm + off)         = make_uint2(bpack(v.x, v.y), bpack(v.z, v.w));
        *(uint2*)(sm + 58752 + off) = make_uint2(bpack(bres(v.x), bres(v.y)), bpack(bres(v.z), bres(v.w)));
    }

    const u32* WT = WBu;
    auto issueB = [&](int tap, int buf) {
        for (int it = 0; it < 4; it++) {
            int u = it*256 + tid, term = u >> 9, oc = (u >> 3) & 63, ch = u & 7;
            u32 dst = su + 117504u + (u32)(buf*2 + term)*9216u + (u32)(oc*144 + ch*16);
            cpasync16(dst, WT + ((size_t)(term*25 + tap)*64 + oc)*32 + ch*4);
        }
        CP_COMMIT();
    };
    issueB(0, 0);
    issueB(1, 1);
    __syncthreads();

    u32 abase[2], bbase[4];
    #pragma unroll
    for (int mt = 0; mt < 2; mt++) {
        int pix = wm*32 + mt*16 + (lane & 15);
        abase[mt] = (u32)(((pix >> 6)*68 + (pix & 63))*144 + ((lane >> 4)*16));
    }
    #pragma unroll
    for (int nt = 0; nt < 4; nt++) {
        int bn = wn*32 + nt*8 + (lane & 7);
        bbase[nt] = su + 117504u + (u32)(bn*144 + ((lane >> 3) & 1)*16);
    }

    float acc[2][4][4];
    #pragma unroll
    for (int mt = 0; mt < 2; mt++)
        #pragma unroll
        for (int nt = 0; nt < 4; nt++)
            #pragma unroll
            for (int q = 0; q < 4; q++) acc[mt][nt][q] = 0.f;

    for (int tap = 0; tap < 25; tap++) {
        if (tap < 24) CP_WAIT1(); else CP_WAIT0();
        __syncthreads();
        int p = tap & 1, dy = tap / 5, dx = tap % 5;
        u32 tapoff = (u32)((dy*68 + dx)*144);
        u32 aH = su + tapoff, aL = su + 58752u + tapoff;
        u32 bP = (u32)(p*2)*9216u;

        #pragma unroll
        for (int ks = 0; ks < 4; ks++) {
            u32 ko = (u32)(ks*32);
            u32 ah[2][4], al[2][4], bh[4][2], bl[4][2];
            #pragma unroll
            for (int mt = 0; mt < 2; mt++) {
                ldsm4(ah[mt], aH + abase[mt] + ko);
                ldsm4(al[mt], aL + abase[mt] + ko);
            }
            #pragma unroll
            for (int nt = 0; nt < 4; nt++) {
                ldsm2(bh[nt], bbase[nt] + bP + ko);
                ldsm2(bl[nt], bbase[nt] + bP + 9216u + ko);
            }
            #pragma unroll
            for (int mt = 0; mt < 2; mt++)
                #pragma unroll
                for (int nt = 0; nt < 4; nt++) {
                    mma16816(acc[mt][nt], ah[mt], bh[nt]);
                    mma16816(acc[mt][nt], ah[mt], bl[nt]);
                    mma16816(acc[mt][nt], al[mt], bh[nt]);
                }
        }
        __syncthreads();
        if (tap + 2 <= 24) issueB(tap + 2, p);
    }

    int g = lane >> 2, t4 = lane & 3;
    int h2 = H >> 1, w2 = W >> 1, L2 = h2*w2;
    #pragma unroll
    for (int mt = 0; mt < 2; mt++)
        #pragma unroll
        for (int half = 0; half < 2; half++) {
            int m = wm*32 + mt*16 + g + half*8;
            int y = Y0 + (m >> 6), gx = x0 + (m & 63);
            if (gx >= W) continue;
            #pragma unroll
            for (int nt = 0; nt < 4; nt++) {
                #pragma unroll
                for (int q = 0; q < 2; q++) {
                    int oc = wn*32 + nt*8 + 2*t4 + q;
                    float v = acc[mt][nt][half*2 + q];
                    if (OUTMODE == 0) {
                        outP[(((size_t)b*64 + oc)*H + y)*W + gx] = v;
                    } else {
                        int s = (y & 1)*2 + (gx & 1), hy = y >> 1, hx = gx >> 1;
                        if (s == 0) outLL[((size_t)b*64 + oc)*L2 + hx*h2 + hy] = v;
                        else        outP[((((size_t)b*64 + oc)*4 + s)*h2 + hy)*w2 + hx] = v;
                    }
                }
            }
        }
}

// ---- HMMA bf16 3-term GEMM: C[128m x 64n] = A[.,K] @ W[n,K]^T ----
// AMODE 0: A row-major (lda). AMODE 1: seq-gather A[(b*64+k)*L + l].
// EPI 1: xz (ldc=256). EPI 2: softplus->DT + BC split. EPI 3: scatter to seq layout.
template<int AMODE, int EPI, int K>
__global__ void __launch_bounds__(256) gemmt_k(const float* __restrict__ A, const u32* __restrict__ WG,
    u32 ws, float* __restrict__ out, const float* __restrict__ bias, int lda, int L, float* __restrict__ base)
{
    extern __shared__ char sm[];
    constexpr int rowB = (K + 8) * 2;
    constexpr u32 sAlo = 128u * rowB, sW = 256u * rowB;
    constexpr u32 wterm = 64u * rowB;   // sWlo - sW
    u32 su = s2u(sm);
    int tid = threadIdx.x, wid = tid >> 5, lane = tid & 31;
    int wm = wid & 3, wn = wid >> 2;
    int m0 = blockIdx.x * 128, n0 = blockIdx.y * 64;
    int b = m0 / L, l0 = m0 % L;

    if (AMODE == 0) {
        #pragma unroll
        for (int it = 0; it < K / 8; it++) {
            int i = it*256 + tid;
            int ml = i / (K / 4), kq = i % (K / 4);
            float4 v = *(const float4*)(A + (size_t)(m0 + ml)*lda + kq*4);
            *(uint2*)(sm + ml*rowB + kq*8) = make_uint2(bpack(v.x, v.y), bpack(v.z, v.w));
            *(uint2*)(sm + sAlo + ml*rowB + kq*8) =
                make_uint2(bpack(bres(v.x), bres(v.y)), bpack(bres(v.z), bres(v.w)));
        }
    } else {
        #pragma unroll
        for (int it = 0; it < K / 8; it++) {
            int i = it*256 + tid;
            int k = i >> 5, mq = i & 31;
            float4 v = *(const float4*)(A + ((size_t)b*64 + k)*L + l0 + mq*4);
            float vv[4] = {v.x, v.y, v.z, v.w};
            #pragma unroll
            for (int j = 0; j < 4; j++) {
                int ml = mq*4 + j;
                *(__nv_bfloat16*)(sm + ml*rowB + k*2) = __float2bfloat16(vv[j]);
                *(__nv_bfloat16*)(sm + sAlo + ml*rowB + k*2) = __float2bfloat16(bres(vv[j]));
            }
        }
    }
    constexpr int kw4 = K / 8;   // uint4 per W row
    #pragma unroll
    for (int it = 0; it < (2*64*kw4 + 255) / 256; it++) {
        int i = it*256 + tid;
        if (i < 2*64*kw4) {
            int term = i / (64*kw4), r = i % (64*kw4), n = r / kw4, kq = r % kw4;
            uint4 v = *(const uint4*)(WG + (size_t)term*ws + (size_t)(n0 + n)*(K/2) + kq*4);
            *(uint4*)(sm + sW + term*wterm + n*rowB + kq*16) = v;
        }
    }
    __syncthreads();

    u32 abase[2], bbase[4];
    #pragma unroll
    for (int mt = 0; mt < 2; mt++)
        abase[mt] = su + (u32)((wm*32 + mt*16 + (lane & 15))*rowB + (lane >> 4)*16);
    #pragma unroll
    for (int nt = 0; nt < 4; nt++)
        bbase[nt] = su + sW + (u32)((wn*32 + nt*8 + (lane & 7))*rowB + ((lane >> 3) & 1)*16);

    float acc[2][4][4];
    #pragma unroll
    for (int mt = 0; mt < 2; mt++)
        #pragma unroll
        for (int nt = 0; nt < 4; nt++)
            #pragma unroll
            for (int q = 0; q < 4; q++) acc[mt][nt][q] = 0.f;

    #pragma unroll
    for (int ks = 0; ks < K / 16; ks++) {
        u32 ko = (u32)(ks*32);
        u32 ah[2][4], al[2][4], bh[4][2], bl[4][2];
        #pragma unroll
        for (int mt = 0; mt < 2; mt++) {
            ldsm4(ah[mt], abase[mt] + ko);
            ldsm4(al[mt], abase[mt] + sAlo + ko);
        }
        #pragma unroll
        for (int nt = 0; nt < 4; nt++) {
            ldsm2(bh[nt], bbase[nt] + ko);
            ldsm2(bl[nt], bbase[nt] + wterm + ko);
        }
        #pragma unroll
        for (int mt = 0; mt < 2; mt++)
            #pragma unroll
            for (int nt = 0; nt < 4; nt++) {
                mma16816(acc[mt][nt], ah[mt], bh[nt]);
                mma16816(acc[mt][nt], ah[mt], bl[nt]);
                mma16816(acc[mt][nt], al[mt], bh[nt]);
            }
    }

    int g = lane >> 2, t4 = lane & 3;
    #pragma unroll
    for (int mt = 0; mt < 2; mt++)
        #pragma unroll
        for (int half = 0; half < 2; half++) {
            int mloc = wm*32 + mt*16 + g + half*8;
            int m = m0 + mloc;
            #pragma unroll
            for (int nt = 0; nt < 4; nt++)
                #pragma unroll
                for (int q = 0; q < 2; q++) {
                    int n = n0 + wn*32 + nt*8 + 2*t4 + q;
                    float v = acc[mt][nt][half*2 + q];
                    if (EPI == 1) {
                        out[(size_t)m*256 + n] = v;
                    } else if (EPI == 2) {
                        if (n < 128)      base[O_DT + (size_t)m*128 + n] = softplus_f(v + bias[n]);
                        else if (n < 160) base[O_BC + (size_t)m*32 + n - 128] = v;
                    } else {
                        out[((size_t)b*64 + n)*L + l0 + mloc] = v;
                    }
                }
        }
}

__global__ void dwconv_k(const float* __restrict__ cw, const float* __restrict__ cb, int L, float* __restrict__ base)
{
    size_t g = (size_t)blockIdx.x * 256 + threadIdx.x;
    int d = (int)(g & 127);
    size_t m = g >> 7;
    int l = (int)(m % (size_t)L);
    const float* xz = base + O_XZ;
    float acc = cb[d];
    #pragma unroll
    for (int j = 0; j < 4; j++) {
        int lj = l - 3 + j;
        if (lj >= 0) acc = fmaf(cw[d*4 + j], xz[(m - 3 + j)*256 + d], acc);
    }
    base[O_XS + g] = acc * __fdividef(1.f, 1.f + __expf(-acc));
}

__global__ void scan1_k(int L, int NCH, float* __restrict__ base)
{
    int t = threadIdx.x, s = t & 15;
    int ch = blockIdx.y, b = blockIdx.z, d = blockIdx.x * 16 + (t >> 4);
    const float* dt = base + O_DT; const float* xs = base + O_XS; const float* bc = base + O_BC;
    float a = base[O_AB + d*16 + s];
    float h = 0.f, P = 1.f;
    size_t ml = (size_t)b*L + (size_t)ch*128;
    for (int i = 0; i < 128; i++) {
        size_t m = ml + i;
        float dtv = __ldg(dt + m*128 + d);
        float e = __expf(dtv * a);
        h = h*e + dtv*__ldg(xs + m*128 + d)*__ldg(bc + m*32 + s);
        P *= e;
    }
    size_t ix = (((size_t)(b*NCH + ch)*128) + d)*16 + s;
    base[O_AT + ix] = P;
    base[O_HL + ix] = h;
}

__global__ void scan2_k(int NCH, float* __restrict__ base)
{
    int g = blockIdx.x * 256 + threadIdx.x;
    int b = g >> 11, ds = g & 2047;
    float carry = 0.f;
    for (int ch = 0; ch < NCH; ch++) {
        size_t ix = ((size_t)(b*NCH + ch))*2048 + ds;
        base[O_HIN + ix] = carry;
        carry = carry * base[O_AT + ix] + base[O_HL + ix];
    }
}

__global__ void scan3_k(int L, int NCH, float* __restrict__ base)
{
    int t = threadIdx.x, s = t & 15;
    int ch = blockIdx.y, b = blockIdx.z, d = blockIdx.x * 16 + (t >> 4);
    const float* dt = base + O_DT; const float* xs = base + O_XS; const float* bc = base + O_BC;
    float a = base[O_AB + d*16 + s];
    size_t ix = (((size_t)(b*NCH + ch)*128) + d)*16 + s;
    float h = base[O_HIN + ix];
    size_t ml = (size_t)b*L + (size_t)ch*128;
    for (int i = 0; i < 128; i++) {
        size_t m = ml + i;
        float dtv = __ldg(dt + m*128 + d);
        float e = __expf(dtv * a);
        h = h*e + dtv*__ldg(xs + m*128 + d)*__ldg(bc + m*32 + s);
        float part = h * __ldg(bc + m*32 + 16 + s);
        part += __shfl_xor_sync(0xffffffffu, part, 8);
        part += __shfl_xor_sync(0xffffffffu, part, 4);
        part += __shfl_xor_sync(0xffffffffu, part, 2);
        part += __shfl_xor_sync(0xffffffffu, part, 1);
        if (s == 0) base[O_YS + m*128 + d] = part;
    }
}

__global__ void ymul_k(const float* __restrict__ Dp, float* __restrict__ base)
{
    size_t g = (size_t)blockIdx.x * 256 + threadIdx.x;
    int d = (int)(g & 127);
    size_t m = g >> 7;
    float z = base[O_XZ + m*256 + 128 + d];
    float sz = z * __fdividef(1.f, 1.f + __expf(-z));
    base[O_YS + g] = (base[O_YS + g] + base[O_XS + g] * Dp[d]) * sz;
}

extern "C" void kernel_launch(void* const* d_in, const int* in_sizes, int n_in,
                              void* d_out, int out_size)
{
    const float* x      = (const float*)d_in[0];
    const float* wt     = (const float*)d_in[1];
    const float* iwt    = (const float*)d_in[2];
    const float* W_in   = (const float*)d_in[3];
    const float* conv_w = (const float*)d_in[4];
    const float* conv_b = (const float*)d_in[5];
    const float* W_x    = (const float*)d_in[6];
    const float* W_dt   = (const float*)d_in[7];
    const float* b_dt   = (const float*)d_in[8];
    const float* A_log  = (const float*)d_in[9];
    const float* Dp     = (const float*)d_in[10];
    const float* W_out  = (const float*)d_in[11];
    (void)in_sizes; (void)n_in; (void)out_size;

    float* S = nullptr;
    cudaGetSymbolAddress((void**)&S, g_scratch);
    cudaFuncSetAttribute(convt_k, cudaFuncAttributeMaxDynamicSharedMemorySize, CSM);
    cudaFuncSetAttribute(gemmt_k<1,1,64>,  cudaFuncAttributeMaxDynamicSharedMemorySize, 55296);
    cudaFuncSetAttribute(gemmt_k<0,2,128>, cudaFuncAttributeMaxDynamicSharedMemorySize, 104448);
    cudaFuncSetAttribute(gemmt_k<0,3,128>, cudaFuncAttributeMaxDynamicSharedMemorySize, 104448);
    const u32* WB0 = (const u32*)S + O_WB;
    const u32* WB1 = WB0 + 102400;
    const u32* WG  = (const u32*)S + O_WG;

    prep_k<<<800, 256>>>(wt, iwt, A_log, W_x, W_dt, S);
    prep2_k<<<192, 256>>>(W_in, W_out, S);

    auto mamba = [&](int L, int NCH, const float* llseq, float* llm) {
        int M = 4 * L;
        gemmt_k<1,1,64><<<dim3(M/128, 4), 256, 55296>>>(llseq, WG, 8192u, S + O_XZ, nullptr, 0, L, S);
        dwconv_k<<<(M*128)/256, 256>>>(conv_w, conv_b, L, S);
        gemmt_k<0,2,128><<<dim3(M/128, 3), 256, 104448>>>(S + O_XS, WG + 16384, 12288u, nullptr, b_dt, 128, L, S);
        scan1_k<<<dim3(8, NCH, 4), 256>>>(L, NCH, S);
        scan2_k<<<32, 256>>>(NCH, S);
        scan3_k<<<dim3(8, NCH, 4), 256>>>(L, NCH, S);
        ymul_k<<<(M*128)/256, 256>>>(Dp, S);
        gemmt_k<0,3,128><<<dim3(M/128, 1), 256, 104448>>>(S + O_YS, WG + 40960, 4096u, llm, nullptr, 128, L, S);
    };

    pad_k<0><<<dim3(196,196,4), 64>>>(x, nullptr, nullptr, S + O_PAD, 192, 192);
    convt_k<<<dim3(3,96,4), 256, CSM>>>(S + O_PAD, WB0, S + O_HI0, S + O_LL0, 192, 192, 1);
    mamba(9216, 72, S + O_LL0, S + O_LM0);
    pad_k<1><<<dim3(100,100,4), 64>>>(S + O_LL0, nullptr, nullptr, S + O_PAD, 96, 96);
    convt_k<<<dim3(2,48,4), 256, CSM>>>(S + O_PAD, WB0, S + O_HI1, S + O_LL1, 96, 96, 1);
    mamba(2304, 18, S + O_LL1, S + O_LM1);
    pad_k<2><<<dim3(100,100,4), 64>>>(S + O_LM1, nullptr, S + O_HI1, S + O_PAD, 96, 96);
    convt_k<<<dim3(2,48,4), 256, CSM>>>(S + O_PAD, WB1, S + O_RC, nullptr, 96, 96, 0);
    pad_k<2><<<dim3(196,196,4), 64>>>(S + O_LM0, S + O_RC, S + O_HI0, S + O_PAD, 192, 192);
    convt_k<<<dim3(3,96,4), 256, CSM>>>(S + O_PAD, WB1, (float*)d_out, nullptr, 192, 192, 0);
}

// round 8
// speedup vs baseline: 1.7524x; 1.0839x over previous
#include <cuda_runtime.h>
#include <cuda_bf16.h>
#include <cstdint>

typedef unsigned int u32;
#define DEV static __device__ __forceinline__

DEV u32 bpack(float lo, float hi){ u32 r; asm("cvt.rn.bf16x2.f32 %0, %2, %1;" : "=r"(r) : "f"(lo), "f"(hi)); return r; }
DEV float bres(float a){ u32 t = bpack(a, a); return a - __uint_as_float(t & 0xFFFF0000u); }
DEV u32 s2u(const void* p){ u32 a; asm("{ .reg .u64 t; cvta.to.shared.u64 t, %1; cvt.u32.u64 %0, t; }" : "=r"(a) : "l"(p)); return a; }

DEV void ldsm4(u32* r, u32 a){ asm volatile("ldmatrix.sync.aligned.m8n8.x4.shared.b16 {%0,%1,%2,%3}, [%4];"
  : "=r"(r[0]),"=r"(r[1]),"=r"(r[2]),"=r"(r[3]) : "r"(a)); }
DEV void ldsm2(u32* r, u32 a){ asm volatile("ldmatrix.sync.aligned.m8n8.x2.shared.b16 {%0,%1}, [%2];"
  : "=r"(r[0]),"=r"(r[1]) : "r"(a)); }
DEV void mma16816(float* c, const u32* a, const u32* b){
  asm volatile("mma.sync.aligned.m16n8k16.row.col.f32.bf16.bf16.f32 {%0,%1,%2,%3},{%4,%5,%6,%7},{%8,%9},{%0,%1,%2,%3};"
    : "+f"(c[0]),"+f"(c[1]),"+f"(c[2]),"+f"(c[3])
    : "r"(a[0]),"r"(a[1]),"r"(a[2]),"r"(a[3]),"r"(b[0]),"r"(b[1]));
}
DEV void cpasync16(u32 dst, const void* src){
  asm volatile("cp.async.cg.shared.global [%0], [%1], 16;" :: "r"(dst), "l"(src) : "memory");
}
#define CP_COMMIT() asm volatile("cp.async.commit_group;" ::: "memory")
#define CP_WAIT1()  asm volatile("cp.async.wait_group 1;" ::: "memory")
#define CP_WAIT0()  asm volatile("cp.async.wait_group 0;" ::: "memory")

// ---- scratch offsets (floats) ----
#define O_LL0 0ull
#define O_HI0 2359296ull
#define O_LL1 11796480ull
#define O_HI1 12386304ull
#define O_LM0 14745600ull
#define O_LM1 17104896ull
#define O_RC  17694720ull
#define O_WS0 20054016ull
#define O_WB  46596096ull
#define O_AB  46800896ull
#define O_WE  46802944ull
#define O_PAD 46827520ull
#define O_WG  56662016ull
#define O_WS1 56711168ull
#define S_TOT 63346688ull
// workspace layout (relative to ws, Mt = 4L floats rows):
//  XZ @0 (Mt*256) | XS @Mt*256 (Mt*128) | DT @Mt*384 | BC @Mt*512 (Mt*32)
//  YS @Mt*544 (Mt*128) | AT @Mt*672 | HL @Mt*688 | HIN @Mt*704 | total Mt*720

__device__ __align__(16) float g_scratch[S_TOT];

struct StreamInit {
    cudaStream_t s2; cudaEvent_t evF, evJ;
    StreamInit() {
        cudaStreamCreate(&s2);
        cudaEventCreateWithFlags(&evF, cudaEventDisableTiming);
        cudaEventCreateWithFlags(&evJ, cudaEventDisableTiming);
    }
};
static StreamInit g_si;

DEV float softplus_f(float x){ return fmaxf(x, 0.f) + log1pf(__expf(-fabsf(x))); }

// ---- prep: bf16 hi/lo conv-weight slabs, A=-exp(A_log), Weff ----
__global__ void prep_k(const float* __restrict__ wt, const float* __restrict__ iwt,
                       const float* __restrict__ A_log, const float* __restrict__ W_x,
                       const float* __restrict__ W_dt, float* __restrict__ base)
{
    int i = blockIdx.x * 256 + threadIdx.x;
    if (i < 204800) {
        int f = i / 102400, r = i % 102400, term = r / 51200;
        int tap = (r / 2048) % 25, r3 = r % 2048, oc = r3 >> 5, k2 = r3 & 31;
        const float* filt = f ? iwt : wt;
        float w0 = filt[(oc*64 + 2*k2)*25 + tap];
        float w1 = filt[(oc*64 + 2*k2 + 1)*25 + tap];
        u32 v = term ? bpack(bres(w0), bres(w1)) : bpack(w0, w1);
        ((u32*)base)[O_WB + i] = v;
    }
    if (i < 2048) base[O_AB + i] = -__expf(A_log[i]);
    if (i < 16384) {
        int d = i >> 7, k = i & 127;
        float s = 0.f;
        #pragma unroll
        for (int r = 0; r < 4; r++) s += W_dt[d*4 + r] * W_x[r*128 + k];
        base[O_WE + i] = s;
    }
    if (i < 8192) {
        int j = i >> 7, k = i & 127;
        base[O_WE + (size_t)(128 + j)*128 + k] = (j < 32) ? W_x[(4 + j)*128 + k] : 0.f;
    }
}

// ---- prep2: bf16 hi/lo GEMM weight slabs (W_in 256x64 | Weff 192x128 | W_out 64x128) ----
__global__ void prep2_k(const float* __restrict__ W_in, const float* __restrict__ W_out,
                        float* __restrict__ base)
{
    int i = blockIdx.x * 256 + threadIdx.x;
    if (i >= 49152) return;
    const float* src; int K, n, k2, term;
    if (i < 16384)      { term = i >> 13; int r = i & 8191;  n = r >> 5; k2 = r & 31; K = 64;  src = W_in; }
    else if (i < 40960) { int j = i - 16384; term = j / 12288; int r = j % 12288; n = r >> 6; k2 = r & 63; K = 128; src = base + O_WE; }
    else                { int j = i - 40960; term = j >> 12; int r = j & 4095;  n = r >> 6; k2 = r & 63; K = 128; src = W_out; }
    float w0 = src[(size_t)n*K + 2*k2], w1 = src[(size_t)n*K + 2*k2 + 1];
    ((u32*)base)[O_WG + i] = term ? bpack(bres(w0), bres(w1)) : bpack(w0, w1);
}

// ---- pad into NHWC. MODE: 0 plain NCHW, 1 transposed-seq, 2 depth-to-space ----
template<int MODE>
__global__ void pad_k(const float* __restrict__ in, const float* __restrict__ llB,
                      const float* __restrict__ high, float* __restrict__ PAD, int H, int W)
{
    int ic = threadIdx.x, xp = blockIdx.x, yp = blockIdx.y, b = blockIdx.z;
    int X = W + 4, xi = xp - 2, yi = yp - 2;
    float v = 0.f;
    if ((unsigned)xi < (unsigned)W && (unsigned)yi < (unsigned)H) {
        if (MODE == 0)      v = in[(((size_t)b*64 + ic)*H + yi)*W + xi];
        else if (MODE == 1) v = in[(((size_t)b*64 + ic)*W + xi)*H + yi];
        else {
            int h2 = H>>1, w2 = W>>1, L2 = h2*w2, s = (yi&1)*2 + (xi&1), hy = yi>>1, hx = xi>>1;
            if (s == 0) {
                v = in[((size_t)b*64 + ic)*L2 + hx*h2 + hy];
                if (llB) v += llB[(((size_t)b*64 + ic)*h2 + hy)*w2 + hx];
            } else v = high[((((size_t)b*64 + ic)*4 + s)*h2 + hy)*w2 + hx];
        }
    }
    PAD[(((size_t)b*(H+4) + yp)*X + xp)*64 + ic] = v;
}

// ---- warp-MMA bf16 3-term conv: M=64(2rows x 32px), N=64 oc, 25 taps x K=64 ic ----
// smem: A hi [6][36][144B] @0 (31104), A lo @31104, B @62208 [2buf][2term][64][144B]
#define CSM 99072
__global__ void __launch_bounds__(256, 2) convt_k(
    const float* __restrict__ PAD, const u32* __restrict__ WBu,
    float* __restrict__ outP, float* __restrict__ outLL, int H, int W, int OUTMODE)
{
    extern __shared__ char sm[];
    u32 su = s2u(sm);
    int tid = threadIdx.x, wid = tid >> 5, lane = tid & 31;
    int wm = wid & 1, wn = wid >> 1;
    int b = blockIdx.z, Y0 = blockIdx.y * 2, x0 = blockIdx.x * 32;
    int X = W + 4;

    // 6 rows x 36 x-pos x 64 ic window -> bf16 hi/lo
    for (int i = tid; i < 3456; i += 256) {
        int r = i / 576, rem = i % 576, xx = rem >> 4, kg = rem & 15;
        float4 v = *(const float4*)(PAD + (((size_t)b*(H+4) + Y0 + r)*X + x0 + xx)*64 + kg*4);
        u32 off = (u32)((r*36 + xx)*144 + kg*8);
        *(uint2*)(sm + off)         = make_uint2(bpack(v.x, v.y), bpack(v.z, v.w));
        *(uint2*)(sm + 31104 + off) = make_uint2(bpack(bres(v.x), bres(v.y)), bpack(bres(v.z), bres(v.w)));
    }

    auto issueB = [&](int tap, int buf) {
        #pragma unroll
        for (int it = 0; it < 4; it++) {
            int u = it*256 + tid, term = u >> 9, oc = (u >> 3) & 63, ch = u & 7;
            u32 dst = su + 62208u + (u32)(buf*2 + term)*9216u + (u32)(oc*144 + ch*16);
            cpasync16(dst, WBu + ((size_t)(term*25 + tap)*64 + oc)*32 + ch*4);
        }
        CP_COMMIT();
    };
    issueB(0, 0);
    issueB(1, 1);
    __syncthreads();

    u32 abase[2], bbase[2];
    #pragma unroll
    for (int mt = 0; mt < 2; mt++) {
        int pix = wm*32 + mt*16 + (lane & 15);
        abase[mt] = (u32)(((pix >> 5)*36 + (pix & 31))*144 + ((lane >> 4)*16));
    }
    #pragma unroll
    for (int nt = 0; nt < 2; nt++) {
        int bn = wn*16 + nt*8 + (lane & 7);
        bbase[nt] = su + 62208u + (u32)(bn*144 + ((lane >> 3) & 1)*16);
    }

    float acc[2][2][4];
    #pragma unroll
    for (int mt = 0; mt < 2; mt++)
        #pragma unroll
        for (int nt = 0; nt < 2; nt++)
            #pragma unroll
            for (int q = 0; q < 4; q++) acc[mt][nt][q] = 0.f;

    for (int tap = 0; tap < 25; tap++) {
        if (tap < 24) CP_WAIT1(); else CP_WAIT0();
        __syncthreads();
        int p = tap & 1, dy = tap / 5, dx = tap % 5;
        u32 tapoff = (u32)((dy*36 + dx)*144);
        u32 aH = su + tapoff, aL = su + 31104u + tapoff;
        u32 bP = (u32)(p*2)*9216u;

        #pragma unroll
        for (int ks = 0; ks < 4; ks++) {
            u32 ko = (u32)(ks*32);
            u32 ah[2][4], al[2][4], bh[2][2], bl[2][2];
            #pragma unroll
            for (int mt = 0; mt < 2; mt++) {
                ldsm4(ah[mt], aH + abase[mt] + ko);
                ldsm4(al[mt], aL + abase[mt] + ko);
            }
            #pragma unroll
            for (int nt = 0; nt < 2; nt++) {
                ldsm2(bh[nt], bbase[nt] + bP + ko);
                ldsm2(bl[nt], bbase[nt] + bP + 9216u + ko);
            }
            #pragma unroll
            for (int mt = 0; mt < 2; mt++)
                #pragma unroll
                for (int nt = 0; nt < 2; nt++) {
                    mma16816(acc[mt][nt], ah[mt], bh[nt]);
                    mma16816(acc[mt][nt], ah[mt], bl[nt]);
                    mma16816(acc[mt][nt], al[mt], bh[nt]);
                }
        }
        __syncthreads();
        if (tap + 2 <= 24) issueB(tap + 2, p);
    }

    int g = lane >> 2, t4 = lane & 3;
    int h2 = H >> 1, w2 = W >> 1, L2 = h2*w2;
    #pragma unroll
    for (int mt = 0; mt < 2; mt++)
        #pragma unroll
        for (int half = 0; half < 2; half++) {
            int m = wm*32 + mt*16 + g + half*8;
            int y = Y0 + (m >> 5), gx = x0 + (m & 31);
            #pragma unroll
            for (int nt = 0; nt < 2; nt++)
                #pragma unroll
                for (int q = 0; q < 2; q++) {
                    int oc = wn*16 + nt*8 + 2*t4 + q;
                    float v = acc[mt][nt][half*2 + q];
                    if (OUTMODE == 0) {
                        outP[(((size_t)b*64 + oc)*H + y)*W + gx] = v;
                    } else {
                        int s = (y & 1)*2 + (gx & 1), hy = y >> 1, hx = gx >> 1;
                        if (s == 0) outLL[((size_t)b*64 + oc)*L2 + hx*h2 + hy] = v;
                        else        outP[((((size_t)b*64 + oc)*4 + s)*h2 + hy)*w2 + hx] = v;
                    }
                }
        }
}

// ---- HMMA bf16 3-term GEMM: C[128m x 64n] = A[.,K] @ W[n,K]^T ----
template<int AMODE, int EPI, int K>
__global__ void __launch_bounds__(256) gemmt_k(const float* __restrict__ A, const u32* __restrict__ WG,
    u32 wsz, float* __restrict__ out, const float* __restrict__ bias, int lda, int L, float* __restrict__ ws)
{
    extern __shared__ char sm[];
    constexpr int rowB = (K + 8) * 2;
    constexpr u32 sAlo = 128u * rowB, sW = 256u * rowB;
    constexpr u32 wterm = 64u * rowB;
    u32 su = s2u(sm);
    int tid = threadIdx.x, wid = tid >> 5, lane = tid & 31;
    int wm = wid & 3, wn = wid >> 2;
    int m0 = blockIdx.x * 128, n0 = blockIdx.y * 64;
    int b = m0 / L, l0 = m0 % L;
    size_t Mt = (size_t)gridDim.x * 128;

    if (AMODE == 0) {
        #pragma unroll
        for (int it = 0; it < K / 8; it++) {
            int i = it*256 + tid;
            int ml = i / (K / 4), kq = i % (K / 4);
            float4 v = *(const float4*)(A + (size_t)(m0 + ml)*lda + kq*4);
            *(uint2*)(sm + ml*rowB + kq*8) = make_uint2(bpack(v.x, v.y), bpack(v.z, v.w));
            *(uint2*)(sm + sAlo + ml*rowB + kq*8) =
                make_uint2(bpack(bres(v.x), bres(v.y)), bpack(bres(v.z), bres(v.w)));
        }
    } else {
        #pragma unroll
        for (int it = 0; it < K / 8; it++) {
            int i = it*256 + tid;
            int k = i >> 5, mq = i & 31;
            float4 v = *(const float4*)(A + ((size_t)b*64 + k)*L + l0 + mq*4);
            float vv[4] = {v.x, v.y, v.z, v.w};
            #pragma unroll
            for (int j = 0; j < 4; j++) {
                int ml = mq*4 + j;
                *(__nv_bfloat16*)(sm + ml*rowB + k*2) = __float2bfloat16(vv[j]);
                *(__nv_bfloat16*)(sm + sAlo + ml*rowB + k*2) = __float2bfloat16(bres(vv[j]));
            }
        }
    }
    constexpr int kw4 = K / 8;
    #pragma unroll
    for (int it = 0; it < (2*64*kw4 + 255) / 256; it++) {
        int i = it*256 + tid;
        if (i < 2*64*kw4) {
            int term = i / (64*kw4), r = i % (64*kw4), n = r / kw4, kq = r % kw4;
            uint4 v = *(const uint4*)(WG + (size_t)term*wsz + (size_t)(n0 + n)*(K/2) + kq*4);
            *(uint4*)(sm + sW + term*wterm + n*rowB + kq*16) = v;
        }
    }
    __syncthreads();

    u32 abase[2], bbase[4];
    #pragma unroll
    for (int mt = 0; mt < 2; mt++)
        abase[mt] = su + (u32)((wm*32 + mt*16 + (lane & 15))*rowB + (lane >> 4)*16);
    #pragma unroll
    for (int nt = 0; nt < 4; nt++)
        bbase[nt] = su + sW + (u32)((wn*32 + nt*8 + (lane & 7))*rowB + ((lane >> 3) & 1)*16);

    float acc[2][4][4];
    #pragma unroll
    for (int mt = 0; mt < 2; mt++)
        #pragma unroll
        for (int nt = 0; nt < 4; nt++)
            #pragma unroll
            for (int q = 0; q < 4; q++) acc[mt][nt][q] = 0.f;

    #pragma unroll
    for (int ks = 0; ks < K / 16; ks++) {
        u32 ko = (u32)(ks*32);
        u32 ah[2][4], al[2][4], bh[4][2], bl[4][2];
        #pragma unroll
        for (int mt = 0; mt < 2; mt++) {
            ldsm4(ah[mt], abase[mt] + ko);
            ldsm4(al[mt], abase[mt] + sAlo + ko);
        }
        #pragma unroll
        for (int nt = 0; nt < 4; nt++) {
            ldsm2(bh[nt], bbase[nt] + ko);
            ldsm2(bl[nt], bbase[nt] + wterm + ko);
        }
        #pragma unroll
        for (int mt = 0; mt < 2; mt++)
            #pragma unroll
            for (int nt = 0; nt < 4; nt++) {
                mma16816(acc[mt][nt], ah[mt], bh[nt]);
                mma16816(acc[mt][nt], ah[mt], bl[nt]);
                mma16816(acc[mt][nt], al[mt], bh[nt]);
            }
    }

    int g = lane >> 2, t4 = lane & 3;
    #pragma unroll
    for (int mt = 0; mt < 2; mt++)
        #pragma unroll
        for (int half = 0; half < 2; half++) {
            int mloc = wm*32 + mt*16 + g + half*8;
            int m = m0 + mloc;
            #pragma unroll
            for (int nt = 0; nt < 4; nt++)
                #pragma unroll
                for (int q = 0; q < 2; q++) {
                    int n = n0 + wn*32 + nt*8 + 2*t4 + q;
                    float v = acc[mt][nt][half*2 + q];
                    if (EPI == 1) {
                        out[(size_t)m*256 + n] = v;
                    } else if (EPI == 2) {
                        if (n < 128)      ws[Mt*384 + (size_t)m*128 + n] = softplus_f(v + bias[n]);
                        else if (n < 160) ws[Mt*512 + (size_t)m*32 + n - 128] = v;
                    } else {
                        out[((size_t)b*64 + n)*L + l0 + mloc] = v;
                    }
                }
        }
}

__global__ void dwconv_k(const float* __restrict__ cw, const float* __restrict__ cb, int L, float* __restrict__ ws)
{
    size_t Mt = (size_t)gridDim.x * 2;
    size_t g = (size_t)blockIdx.x * 256 + threadIdx.x;
    int d = (int)(g & 127);
    size_t m = g >> 7;
    int l = (int)(m % (size_t)L);
    float acc = cb[d];
    #pragma unroll
    for (int j = 0; j < 4; j++) {
        int lj = l - 3 + j;
        if (lj >= 0) acc = fmaf(cw[d*4 + j], ws[(m - 3 + j)*256 + d], acc);
    }
    ws[Mt*256 + g] = acc * __fdividef(1.f, 1.f + __expf(-acc));
}

__global__ void scan1_k(int L, int NCH, float* __restrict__ ws, const float* __restrict__ Ab)
{
    size_t Mt = (size_t)4 * L;
    const float* dt = ws + Mt*384; const float* xs = ws + Mt*256; const float* bc = ws + Mt*512;
    int t = threadIdx.x, s = t & 15;
    int ch = blockIdx.y, b = blockIdx.z, d = blockIdx.x * 16 + (t >> 4);
    float a = Ab[d*16 + s];
    float h = 0.f, P = 1.f;
    size_t ml = (size_t)b*L + (size_t)ch*128;
    for (int i = 0; i < 128; i++) {
        size_t m = ml + i;
        float dtv = __ldg(dt + m*128 + d);
        float e = __expf(dtv * a);
        h = h*e + dtv*__ldg(xs + m*128 + d)*__ldg(bc + m*32 + s);
        P *= e;
    }
    size_t ix = (((size_t)(b*NCH + ch)*128) + d)*16 + s;
    ws[Mt*672 + ix] = P;
    ws[Mt*688 + ix] = h;
}

__global__ void scan2_k(int L, int NCH, float* __restrict__ ws)
{
    size_t Mt = (size_t)4 * L;
    int g = blockIdx.x * 256 + threadIdx.x;
    int b = g >> 11, ds = g & 2047;
    float carry = 0.f;
    for (int ch = 0; ch < NCH; ch++) {
        size_t ix = ((size_t)(b*NCH + ch))*2048 + ds;
        ws[Mt*704 + ix] = carry;
        carry = carry * ws[Mt*672 + ix] + ws[Mt*688 + ix];
    }
}

__global__ void scan3_k(int L, int NCH, float* __restrict__ ws, const float* __restrict__ Ab)
{
    size_t Mt = (size_t)4 * L;
    const float* dt = ws + Mt*384; const float* xs = ws + Mt*256; const float* bc = ws + Mt*512;
    int t = threadIdx.x, s = t & 15;
    int ch = blockIdx.y, b = blockIdx.z, d = blockIdx.x * 16 + (t >> 4);
    float a = Ab[d*16 + s];
    size_t ix = (((size_t)(b*NCH + ch)*128) + d)*16 + s;
    float h = ws[Mt*704 + ix];
    size_t ml = (size_t)b*L + (size_t)ch*128;
    for (int i = 0; i < 128; i++) {
        size_t m = ml + i;
        float dtv = __ldg(dt + m*128 + d);
        float e = __expf(dtv * a);
        h = h*e + dtv*__ldg(xs + m*128 + d)*__ldg(bc + m*32 + s);
        float part = h * __ldg(bc + m*32 + 16 + s);
        part += __shfl_xor_sync(0xffffffffu, part, 8);
        part += __shfl_xor_sync(0xffffffffu, part, 4);
        part += __shfl_xor_sync(0xffffffffu, part, 2);
        part += __shfl_xor_sync(0xffffffffu, part, 1);
        if (s == 0) ws[Mt*544 + m*128 + d] = part;
    }
}

__global__ void ymul_k(const float* __restrict__ Dp, float* __restrict__ ws)
{
    size_t Mt = (size_t)gridDim.x * 2;
    size_t g = (size_t)blockIdx.x * 256 + threadIdx.x;
    int d = (int)(g & 127);
    size_t m = g >> 7;
    float z = ws[m*256 + 128 + d];
    float sz = z * __fdividef(1.f, 1.f + __expf(-z));
    ws[Mt*544 + g] = (ws[Mt*544 + g] + ws[Mt*256 + g] * Dp[d]) * sz;
}

extern "C" void kernel_launch(void* const* d_in, const int* in_sizes, int n_in,
                              void* d_out, int out_size)
{
    const float* x      = (const float*)d_in[0];
    const float* wt     = (const float*)d_in[1];
    const float* iwt    = (const float*)d_in[2];
    const float* W_in   = (const float*)d_in[3];
    const float* conv_w = (const float*)d_in[4];
    const float* conv_b = (const float*)d_in[5];
    const float* W_x    = (const float*)d_in[6];
    const float* W_dt   = (const float*)d_in[7];
    const float* b_dt   = (const float*)d_in[8];
    const float* A_log  = (const float*)d_in[9];
    const float* Dp     = (const float*)d_in[10];
    const float* W_out  = (const float*)d_in[11];
    (void)in_sizes; (void)n_in; (void)out_size;

    float* S = nullptr;
    cudaGetSymbolAddress((void**)&S, g_scratch);
    cudaFuncSetAttribute(convt_k, cudaFuncAttributeMaxDynamicSharedMemorySize, CSM);
    cudaFuncSetAttribute(gemmt_k<1,1,64>,  cudaFuncAttributeMaxDynamicSharedMemorySize, 55296);
    cudaFuncSetAttribute(gemmt_k<0,2,128>, cudaFuncAttributeMaxDynamicSharedMemorySize, 104448);
    cudaFuncSetAttribute(gemmt_k<0,3,128>, cudaFuncAttributeMaxDynamicSharedMemorySize, 104448);
    const u32* WB0 = (const u32*)S + O_WB;
    const u32* WB1 = WB0 + 102400;
    const u32* WG  = (const u32*)S + O_WG;
    const float* Ab = S + O_AB;
    cudaStream_t s2 = g_si.s2;

    prep_k<<<800, 256>>>(wt, iwt, A_log, W_x, W_dt, S);
    prep2_k<<<192, 256>>>(W_in, W_out, S);

    auto mamba = [&](int L, int NCH, const float* llseq, float* llm, float* ws, cudaStream_t st) {
        int M = 4 * L;
        gemmt_k<1,1,64><<<dim3(M/128, 4), 256, 55296, st>>>(llseq, WG, 8192u, ws, nullptr, 0, L, ws);
        dwconv_k<<<(M*128)/256, 256, 0, st>>>(conv_w, conv_b, L, ws);
        gemmt_k<0,2,128><<<dim3(M/128, 3), 256, 104448, st>>>(ws + (size_t)M*256, WG + 16384, 12288u, nullptr, b_dt, 128, L, ws);
        scan1_k<<<dim3(8, NCH, 4), 256, 0, st>>>(L, NCH, ws, Ab);
        scan2_k<<<32, 256, 0, st>>>(L, NCH, ws);
        scan3_k<<<dim3(8, NCH, 4), 256, 0, st>>>(L, NCH, ws, Ab);
        ymul_k<<<(M*128)/256, 256, 0, st>>>(Dp, ws);
        gemmt_k<0,3,128><<<dim3(M/128, 1), 256, 104448, st>>>(ws + (size_t)M*544, WG + 40960, 4096u, llm, nullptr, 128, L, ws);
    };

    // level-0 decomposition
    pad_k<0><<<dim3(196,196,4), 64>>>(x, nullptr, nullptr, S + O_PAD, 192, 192);
    convt_k<<<dim3(6,96,4), 256, CSM>>>(S + O_PAD, WB0, S + O_HI0, S + O_LL0, 192, 192, 1);

    // fork: chain A (default stream) = mamba level-0; chain B (s2) = full level-1 subtree
    cudaEventRecord(g_si.evF, 0);
    cudaStreamWaitEvent(s2, g_si.evF, 0);

    mamba(9216, 72, S + O_LL0, S + O_LM0, S + O_WS0, 0);

    pad_k<1><<<dim3(100,100,4), 64, 0, s2>>>(S + O_LL0, nullptr, nullptr, S + O_PAD, 96, 96);
    convt_k<<<dim3(3,48,4), 256, CSM, s2>>>(S + O_PAD, WB0, S + O_HI1, S + O_LL1, 96, 96, 1);
    mamba(2304, 18, S + O_LL1, S + O_LM1, S + O_WS1, s2);
    pad_k<2><<<dim3(100,100,4), 64, 0, s2>>>(S + O_LM1, nullptr, S + O_HI1, S + O_PAD, 96, 96);
    convt_k<<<dim3(3,48,4), 256, CSM, s2>>>(S + O_PAD, WB1, S + O_RC, nullptr, 96, 96, 0);

    // join
    cudaEventRecord(g_si.evJ, s2);
    cudaStreamWaitEvent(0, g_si.evJ, 0);

    pad_k<2><<<dim3(196,196,4), 64>>>(S + O_LM0, S + O_RC, S + O_HI0, S + O_PAD, 192, 192);
    convt_k<<<dim3(6,96,4), 256, CSM>>>(S + O_PAD, WB1, (float*)d_out, nullptr, 192, 192, 0);
}

// round 9
// speedup vs baseline: 1.9719x; 1.1252x over previous
#include <cuda_runtime.h>
#include <cuda_bf16.h>
#include <cstdint>

typedef unsigned int u32;
#define DEV static __device__ __forceinline__

DEV u32 bpack(float lo, float hi){ u32 r; asm("cvt.rn.bf16x2.f32 %0, %2, %1;" : "=r"(r) : "f"(lo), "f"(hi)); return r; }
DEV float bres(float a){ u32 t = bpack(a, a); return a - __uint_as_float(t & 0xFFFF0000u); }
DEV u32 s2u(const void* p){ u32 a; asm("{ .reg .u64 t; cvta.to.shared.u64 t, %1; cvt.u32.u64 %0, t; }" : "=r"(a) : "l"(p)); return a; }

DEV void ldsm4(u32* r, u32 a){ asm volatile("ldmatrix.sync.aligned.m8n8.x4.shared.b16 {%0,%1,%2,%3}, [%4];"
  : "=r"(r[0]),"=r"(r[1]),"=r"(r[2]),"=r"(r[3]) : "r"(a)); }
DEV void ldsm2(u32* r, u32 a){ asm volatile("ldmatrix.sync.aligned.m8n8.x2.shared.b16 {%0,%1}, [%2];"
  : "=r"(r[0]),"=r"(r[1]) : "r"(a)); }
DEV void mma16816(float* c, const u32* a, const u32* b){
  asm volatile("mma.sync.aligned.m16n8k16.row.col.f32.bf16.bf16.f32 {%0,%1,%2,%3},{%4,%5,%6,%7},{%8,%9},{%0,%1,%2,%3};"
    : "+f"(c[0]),"+f"(c[1]),"+f"(c[2]),"+f"(c[3])
    : "r"(a[0]),"r"(a[1]),"r"(a[2]),"r"(a[3]),"r"(b[0]),"r"(b[1]));
}
DEV void cpasync16(u32 dst, const void* src){
  asm volatile("cp.async.cg.shared.global [%0], [%1], 16;" :: "r"(dst), "l"(src) : "memory");
}
#define CP_COMMIT() asm volatile("cp.async.commit_group;" ::: "memory")
#define CP_WAIT1()  asm volatile("cp.async.wait_group 1;" ::: "memory")
#define CP_WAIT0()  asm volatile("cp.async.wait_group 0;" ::: "memory")

// ---- scratch offsets (floats) ----
#define O_LL0 0ull
#define O_HI0 2359296ull
#define O_LL1 11796480ull
#define O_HI1 12386304ull
#define O_LM0 14745600ull
#define O_LM1 17104896ull
#define O_RC  17694720ull
#define O_WS0 20054016ull
#define O_WB  46596096ull
#define O_AB  46800896ull
#define O_WE  46802944ull
#define O_PAD 46827520ull
#define O_WG  56662016ull
#define O_WS1 56711168ull
#define S_TOT 63346688ull

__device__ __align__(16) float g_scratch[S_TOT];

struct StreamInit {
    cudaStream_t s2; cudaEvent_t evF, evJ;
    StreamInit() {
        cudaStreamCreate(&s2);
        cudaEventCreateWithFlags(&evF, cudaEventDisableTiming);
        cudaEventCreateWithFlags(&evJ, cudaEventDisableTiming);
    }
};
static StreamInit g_si;

DEV float softplus_f(float x){ return fmaxf(x, 0.f) + log1pf(__expf(-fabsf(x))); }

// ---- prep: bf16 hi/lo conv-weight slabs, A=-exp(A_log), Weff ----
__global__ void prep_k(const float* __restrict__ wt, const float* __restrict__ iwt,
                       const float* __restrict__ A_log, const float* __restrict__ W_x,
                       const float* __restrict__ W_dt, float* __restrict__ base)
{
    int i = blockIdx.x * 256 + threadIdx.x;
    if (i < 204800) {
        int f = i / 102400, r = i % 102400, term = r / 51200;
        int tap = (r / 2048) % 25, r3 = r % 2048, oc = r3 >> 5, k2 = r3 & 31;
        const float* filt = f ? iwt : wt;
        float w0 = filt[(oc*64 + 2*k2)*25 + tap];
        float w1 = filt[(oc*64 + 2*k2 + 1)*25 + tap];
        u32 v = term ? bpack(bres(w0), bres(w1)) : bpack(w0, w1);
        ((u32*)base)[O_WB + i] = v;
    }
    if (i < 2048) base[O_AB + i] = -__expf(A_log[i]);
    if (i < 16384) {
        int d = i >> 7, k = i & 127;
        float s = 0.f;
        #pragma unroll
        for (int r = 0; r < 4; r++) s += W_dt[d*4 + r] * W_x[r*128 + k];
        base[O_WE + i] = s;
    }
    if (i < 8192) {
        int j = i >> 7, k = i & 127;
        base[O_WE + (size_t)(128 + j)*128 + k] = (j < 32) ? W_x[(4 + j)*128 + k] : 0.f;
    }
}

// ---- prep2: bf16 hi/lo GEMM weight slabs ----
__global__ void prep2_k(const float* __restrict__ W_in, const float* __restrict__ W_out,
                        float* __restrict__ base)
{
    int i = blockIdx.x * 256 + threadIdx.x;
    if (i >= 49152) return;
    const float* src; int K, n, k2, term;
    if (i < 16384)      { term = i >> 13; int r = i & 8191;  n = r >> 5; k2 = r & 31; K = 64;  src = W_in; }
    else if (i < 40960) { int j = i - 16384; term = j / 12288; int r = j % 12288; n = r >> 6; k2 = r & 63; K = 128; src = base + O_WE; }
    else                { int j = i - 40960; term = j >> 12; int r = j & 4095;  n = r >> 6; k2 = r & 63; K = 128; src = W_out; }
    float w0 = src[(size_t)n*K + 2*k2], w1 = src[(size_t)n*K + 2*k2 + 1];
    ((u32*)base)[O_WG + i] = term ? bpack(bres(w0), bres(w1)) : bpack(w0, w1);
}

// ---- pad into NHWC, 4 px per block. MODE: 0 plain, 1 transposed-seq, 2 depth-to-space ----
template<int MODE>
__global__ void pad_k(const float* __restrict__ in, const float* __restrict__ llB,
                      const float* __restrict__ high, float* __restrict__ PAD, int H, int W)
{
    int ic = threadIdx.x & 63, xp = blockIdx.x*4 + (threadIdx.x >> 6);
    int yp = blockIdx.y, b = blockIdx.z;
    int X = W + 4, xi = xp - 2, yi = yp - 2;
    float v = 0.f;
    if ((unsigned)xi < (unsigned)W && (unsigned)yi < (unsigned)H) {
        if (MODE == 0)      v = in[(((size_t)b*64 + ic)*H + yi)*W + xi];
        else if (MODE == 1) v = in[(((size_t)b*64 + ic)*W + xi)*H + yi];
        else {
            int h2 = H>>1, w2 = W>>1, L2 = h2*w2, s = (yi&1)*2 + (xi&1), hy = yi>>1, hx = xi>>1;
            if (s == 0) {
                v = in[((size_t)b*64 + ic)*L2 + hx*h2 + hy];
                if (llB) v += llB[(((size_t)b*64 + ic)*h2 + hy)*w2 + hx];
            } else v = high[((((size_t)b*64 + ic)*4 + s)*h2 + hy)*w2 + hx];
        }
    }
    PAD[(((size_t)b*(H+4) + yp)*X + xp)*64 + ic] = v;
}

// ---- warp-MMA bf16 3-term conv: M=64(4rows x 16px), N=64 oc, 25 taps x K=64 ic ----
// smem (swizzled, stride 128): A hi [8][20][128B] @0 (20480), A lo @20480,
// B @40960: 3 bufs x 2 terms x 8192
#define CSM 90112
__global__ void __launch_bounds__(256, 2) convt_k(
    const float* __restrict__ PAD, const u32* __restrict__ WBu,
    float* __restrict__ outP, float* __restrict__ outLL, int H, int W, int OUTMODE)
{
    extern __shared__ char sm[];
    u32 su = s2u(sm);
    int tid = threadIdx.x, wid = tid >> 5, lane = tid & 31;
    int wm = wid & 1, wn = wid >> 1;
    int b = blockIdx.z, Y0 = blockIdx.y * 4, x0 = blockIdx.x * 16;
    int X = W + 4;

    // A window: 8 rows x 20 xpos x 64 ic -> bf16 hi/lo, XOR-swizzled
    for (int i = tid; i < 2560; i += 256) {
        int r = i / 320, rem = i % 320, xx = rem >> 4, kg = rem & 15;
        float4 v = *(const float4*)(PAD + (((size_t)b*(H+4) + Y0 + r)*X + x0 + xx)*64 + kg*4);
        int rid = r*20 + xx;
        u32 off = (u32)(rid*128 + (((kg>>1) ^ (rid&7))*16) + (kg&1)*8);
        *(uint2*)(sm + off)         = make_uint2(bpack(v.x, v.y), bpack(v.z, v.w));
        *(uint2*)(sm + 20480 + off) = make_uint2(bpack(bres(v.x), bres(v.y)), bpack(bres(v.z), bres(v.w)));
    }

    auto issueB = [&](int tap, int buf) {
        #pragma unroll
        for (int it = 0; it < 4; it++) {
            int u = it*256 + tid, term = u >> 9, oc = (u >> 3) & 63, ch = u & 7;
            u32 dst = su + 40960u + (u32)buf*16384u + (u32)term*8192u
                    + (u32)(oc*128 + ((ch ^ (oc & 7))*16));
            cpasync16(dst, WBu + ((size_t)(term*25 + tap)*64 + oc)*32 + ch*4);
        }
        CP_COMMIT();
    };
    issueB(0, 0);
    issueB(1, 1);
    __syncthreads();

    // lane constants
    int pixrow[2], hi16 = lane >> 4;
    #pragma unroll
    for (int mt = 0; mt < 2; mt++) {
        int pix = wm*32 + mt*16 + (lane & 15);
        pixrow[mt] = (pix >> 4)*20 + (pix & 15);
    }
    u32 bnoff[2]; int b7[2]; int bhalf = (lane >> 3) & 1;
    #pragma unroll
    for (int nt = 0; nt < 2; nt++) {
        int bn = wn*16 + nt*8 + (lane & 7);
        bnoff[nt] = su + 40960u + (u32)(bn*128);
        b7[nt] = bn & 7;
    }

    float acc[2][2][4];
    #pragma unroll
    for (int mt = 0; mt < 2; mt++)
        #pragma unroll
        for (int nt = 0; nt < 2; nt++)
            #pragma unroll
            for (int q = 0; q < 4; q++) acc[mt][nt][q] = 0.f;

    for (int tap = 0; tap < 25; tap++) {
        if (tap < 24) CP_WAIT1(); else CP_WAIT0();
        __syncthreads();
        if (tap + 2 <= 24) issueB(tap + 2, (tap + 2) % 3);

        int drow = (tap/5)*20 + (tap%5);
        u32 aaddr[2]; int ar7[2];
        #pragma unroll
        for (int mt = 0; mt < 2; mt++) {
            int rid = pixrow[mt] + drow;
            ar7[mt] = rid & 7;
            aaddr[mt] = su + (u32)(rid*128);
        }
        u32 bbuf = (u32)(tap % 3)*16384u;

        #pragma unroll
        for (int ks = 0; ks < 4; ks++) {
            int cA = ks*2 + hi16, cB = ks*2 + bhalf;
            u32 ah[2][4], al[2][4], bh[2][2], bl[2][2];
            #pragma unroll
            for (int mt = 0; mt < 2; mt++) {
                u32 sw = (u32)(((cA ^ ar7[mt]))*16);
                ldsm4(ah[mt], aaddr[mt] + sw);
                ldsm4(al[mt], aaddr[mt] + 20480u + sw);
            }
            #pragma unroll
            for (int nt = 0; nt < 2; nt++) {
                u32 sw = (u32)(((cB ^ b7[nt]))*16);
                ldsm2(bh[nt], bnoff[nt] + bbuf + sw);
                ldsm2(bl[nt], bnoff[nt] + bbuf + 8192u + sw);
            }
            #pragma unroll
            for (int mt = 0; mt < 2; mt++)
                #pragma unroll
                for (int nt = 0; nt < 2; nt++) {
                    mma16816(acc[mt][nt], ah[mt], bh[nt]);
                    mma16816(acc[mt][nt], ah[mt], bl[nt]);
                    mma16816(acc[mt][nt], al[mt], bh[nt]);
                }
        }
    }

    int g = lane >> 2, t4 = lane & 3;
    int h2 = H >> 1, w2 = W >> 1, L2 = h2*w2;
    #pragma unroll
    for (int mt = 0; mt < 2; mt++)
        #pragma unroll
        for (int half = 0; half < 2; half++) {
            int m = wm*32 + mt*16 + g + half*8;
            int y = Y0 + (m >> 4), gx = x0 + (m & 15);
            #pragma unroll
            for (int nt = 0; nt < 2; nt++)
                #pragma unroll
                for (int q = 0; q < 2; q++) {
                    int oc = wn*16 + nt*8 + 2*t4 + q;
                    float v = acc[mt][nt][half*2 + q];
                    if (OUTMODE == 0) {
                        outP[(((size_t)b*64 + oc)*H + y)*W + gx] = v;
                    } else {
                        int s = (y & 1)*2 + (gx & 1), hy = y >> 1, hx = gx >> 1;
                        if (s == 0) outLL[((size_t)b*64 + oc)*L2 + hx*h2 + hy] = v;
                        else        outP[((((size_t)b*64 + oc)*4 + s)*h2 + hy)*w2 + hx] = v;
                    }
                }
        }
}

// ---- HMMA bf16 3-term GEMM: C[128m x 64n] = A[.,K] @ W[n,K]^T ----
template<int AMODE, int EPI, int K>
__global__ void __launch_bounds__(256) gemmt_k(const float* __restrict__ A, const u32* __restrict__ WG,
    u32 wsz, float* __restrict__ out, const float* __restrict__ bias, int lda, int L, float* __restrict__ ws)
{
    extern __shared__ char sm[];
    constexpr int rowB = (K + 8) * 2;
    constexpr u32 sAlo = 128u * rowB, sW = 256u * rowB;
    constexpr u32 wterm = 64u * rowB;
    u32 su = s2u(sm);
    int tid = threadIdx.x, wid = tid >> 5, lane = tid & 31;
    int wm = wid & 3, wn = wid >> 2;
    int m0 = blockIdx.x * 128, n0 = blockIdx.y * 64;
    int b = m0 / L, l0 = m0 % L;
    size_t Mt = (size_t)gridDim.x * 128;

    if (AMODE == 0) {
        #pragma unroll
        for (int it = 0; it < K / 8; it++) {
            int i = it*256 + tid;
            int ml = i / (K / 4), kq = i % (K / 4);
            float4 v = *(const float4*)(A + (size_t)(m0 + ml)*lda + kq*4);
            *(uint2*)(sm + ml*rowB + kq*8) = make_uint2(bpack(v.x, v.y), bpack(v.z, v.w));
            *(uint2*)(sm + sAlo + ml*rowB + kq*8) =
                make_uint2(bpack(bres(v.x), bres(v.y)), bpack(bres(v.z), bres(v.w)));
        }
    } else {
        #pragma unroll
        for (int it = 0; it < K / 8; it++) {
            int i = it*256 + tid;
            int k = i >> 5, mq = i & 31;
            float4 v = *(const float4*)(A + ((size_t)b*64 + k)*L + l0 + mq*4);
            float vv[4] = {v.x, v.y, v.z, v.w};
            #pragma unroll
            for (int j = 0; j < 4; j++) {
                int ml = mq*4 + j;
                *(__nv_bfloat16*)(sm + ml*rowB + k*2) = __float2bfloat16(vv[j]);
                *(__nv_bfloat16*)(sm + sAlo + ml*rowB + k*2) = __float2bfloat16(bres(vv[j]));
            }
        }
    }
    constexpr int kw4 = K / 8;
    #pragma unroll
    for (int it = 0; it < (2*64*kw4 + 255) / 256; it++) {
        int i = it*256 + tid;
        if (i < 2*64*kw4) {
            int term = i / (64*kw4), r = i % (64*kw4), n = r / kw4, kq = r % kw4;
            uint4 v = *(const uint4*)(WG + (size_t)term*wsz + (size_t)(n0 + n)*(K/2) + kq*4);
            *(uint4*)(sm + sW + term*wterm + n*rowB + kq*16) = v;
        }
    }
    __syncthreads();

    u32 abase[2], bbase[4];
    #pragma unroll
    for (int mt = 0; mt < 2; mt++)
        abase[mt] = su + (u32)((wm*32 + mt*16 + (lane & 15))*rowB + (lane >> 4)*16);
    #pragma unroll
    for (int nt = 0; nt < 4; nt++)
        bbase[nt] = su + sW + (u32)((wn*32 + nt*8 + (lane & 7))*rowB + ((lane >> 3) & 1)*16);

    float acc[2][4][4];
    #pragma unroll
    for (int mt = 0; mt < 2; mt++)
        #pragma unroll
        for (int nt = 0; nt < 4; nt++)
            #pragma unroll
            for (int q = 0; q < 4; q++) acc[mt][nt][q] = 0.f;

    #pragma unroll
    for (int ks = 0; ks < K / 16; ks++) {
        u32 ko = (u32)(ks*32);
        u32 ah[2][4], al[2][4], bh[4][2], bl[4][2];
        #pragma unroll
        for (int mt = 0; mt < 2; mt++) {
            ldsm4(ah[mt], abase[mt] + ko);
            ldsm4(al[mt], abase[mt] + sAlo + ko);
        }
        #pragma unroll
        for (int nt = 0; nt < 4; nt++) {
            ldsm2(bh[nt], bbase[nt] + ko);
            ldsm2(bl[nt], bbase[nt] + wterm + ko);
        }
        #pragma unroll
        for (int mt = 0; mt < 2; mt++)
            #pragma unroll
            for (int nt = 0; nt < 4; nt++) {
                mma16816(acc[mt][nt], ah[mt], bh[nt]);
                mma16816(acc[mt][nt], ah[mt], bl[nt]);
                mma16816(acc[mt][nt], al[mt], bh[nt]);
            }
    }

    int g = lane >> 2, t4 = lane & 3;
    #pragma unroll
    for (int mt = 0; mt < 2; mt++)
        #pragma unroll
        for (int half = 0; half < 2; half++) {
            int mloc = wm*32 + mt*16 + g + half*8;
            int m = m0 + mloc;
            #pragma unroll
            for (int nt = 0; nt < 4; nt++)
                #pragma unroll
                for (int q = 0; q < 2; q++) {
                    int n = n0 + wn*32 + nt*8 + 2*t4 + q;
                    float v = acc[mt][nt][half*2 + q];
                    if (EPI == 1) {
                        out[(size_t)m*256 + n] = v;
                    } else if (EPI == 2) {
                        if (n < 128)      ws[Mt*384 + (size_t)m*128 + n] = softplus_f(v + bias[n]);
                        else if (n < 160) ws[Mt*512 + (size_t)m*32 + n - 128] = v;
                    } else {
                        out[((size_t)b*64 + n)*L + l0 + mloc] = v;
                    }
                }
        }
}

__global__ void dwconv_k(const float* __restrict__ cw, const float* __restrict__ cb, int L, float* __restrict__ ws)
{
    size_t Mt = (size_t)gridDim.x * 2;
    size_t g = (size_t)blockIdx.x * 256 + threadIdx.x;
    int d = (int)(g & 127);
    size_t m = g >> 7;
    int l = (int)(m % (size_t)L);
    float acc = cb[d];
    #pragma unroll
    for (int j = 0; j < 4; j++) {
        int lj = l - 3 + j;
        if (lj >= 0) acc = fmaf(cw[d*4 + j], ws[(m - 3 + j)*256 + d], acc);
    }
    ws[Mt*256 + g] = acc * __fdividef(1.f, 1.f + __expf(-acc));
}

__global__ void scan1_k(int L, int NCH, float* __restrict__ ws, const float* __restrict__ Ab)
{
    size_t Mt = (size_t)4 * L;
    const float* dt = ws + Mt*384; const float* xs = ws + Mt*256; const float* bc = ws + Mt*512;
    int t = threadIdx.x, s = t & 15;
    int ch = blockIdx.y, b = blockIdx.z, d = blockIdx.x * 16 + (t >> 4);
    float a = Ab[d*16 + s];
    float h = 0.f, P = 1.f;
    size_t ml = (size_t)b*L + (size_t)ch*128;
    for (int i = 0; i < 128; i++) {
        size_t m = ml + i;
        float dtv = __ldg(dt + m*128 + d);
        float e = __expf(dtv * a);
        h = h*e + dtv*__ldg(xs + m*128 + d)*__ldg(bc + m*32 + s);
        P *= e;
    }
    size_t ix = (((size_t)(b*NCH + ch)*128) + d)*16 + s;
    ws[Mt*672 + ix] = P;
    ws[Mt*688 + ix] = h;
}

__global__ void scan2_k(int L, int NCH, float* __restrict__ ws)
{
    size_t Mt = (size_t)4 * L;
    int g = blockIdx.x * 256 + threadIdx.x;
    int b = g >> 11, ds = g & 2047;
    float carry = 0.f;
    for (int ch = 0; ch < NCH; ch++) {
        size_t ix = ((size_t)(b*NCH + ch))*2048 + ds;
        ws[Mt*704 + ix] = carry;
        carry = carry * ws[Mt*672 + ix] + ws[Mt*688 + ix];
    }
}

__global__ void scan3_k(int L, int NCH, float* __restrict__ ws, const float* __restrict__ Ab)
{
    size_t Mt = (size_t)4 * L;
    const float* dt = ws + Mt*384; const float* xs = ws + Mt*256; const float* bc = ws + Mt*512;
    int t = threadIdx.x, s = t & 15;
    int ch = blockIdx.y, b = blockIdx.z, d = blockIdx.x * 16 + (t >> 4);
    float a = Ab[d*16 + s];
    size_t ix = (((size_t)(b*NCH + ch)*128) + d)*16 + s;
    float h = ws[Mt*704 + ix];
    size_t ml = (size_t)b*L + (size_t)ch*128;
    for (int i = 0; i < 128; i++) {
        size_t m = ml + i;
        float dtv = __ldg(dt + m*128 + d);
        float e = __expf(dtv * a);
        h = h*e + dtv*__ldg(xs + m*128 + d)*__ldg(bc + m*32 + s);
        float part = h * __ldg(bc + m*32 + 16 + s);
        part += __shfl_xor_sync(0xffffffffu, part, 8);
        part += __shfl_xor_sync(0xffffffffu, part, 4);
        part += __shfl_xor_sync(0xffffffffu, part, 2);
        part += __shfl_xor_sync(0xffffffffu, part, 1);
        if (s == 0) ws[Mt*544 + m*128 + d] = part;
    }
}

__global__ void ymul_k(const float* __restrict__ Dp, float* __restrict__ ws)
{
    size_t Mt = (size_t)gridDim.x * 2;
    size_t g = (size_t)blockIdx.x * 256 + threadIdx.x;
    int d = (int)(g & 127);
    size_t m = g >> 7;
    float z = ws[m*256 + 128 + d];
    float sz = z * __fdividef(1.f, 1.f + __expf(-z));
    ws[Mt*544 + g] = (ws[Mt*544 + g] + ws[Mt*256 + g] * Dp[d]) * sz;
}

extern "C" void kernel_launch(void* const* d_in, const int* in_sizes, int n_in,
                              void* d_out, int out_size)
{
    const float* x      = (const float*)d_in[0];
    const float* wt     = (const float*)d_in[1];
    const float* iwt    = (const float*)d_in[2];
    const float* W_in   = (const float*)d_in[3];
    const float* conv_w = (const float*)d_in[4];
    const float* conv_b = (const float*)d_in[5];
    const float* W_x    = (const float*)d_in[6];
    const float* W_dt   = (const float*)d_in[7];
    const float* b_dt   = (const float*)d_in[8];
    const float* A_log  = (const float*)d_in[9];
    const float* Dp     = (const float*)d_in[10];
    const float* W_out  = (const float*)d_in[11];
    (void)in_sizes; (void)n_in; (void)out_size;

    float* S = nullptr;
    cudaGetSymbolAddress((void**)&S, g_scratch);
    cudaFuncSetAttribute(convt_k, cudaFuncAttributeMaxDynamicSharedMemorySize, CSM);
    cudaFuncSetAttribute(gemmt_k<1,1,64>,  cudaFuncAttributeMaxDynamicSharedMemorySize, 55296);
    cudaFuncSetAttribute(gemmt_k<0,2,128>, cudaFuncAttributeMaxDynamicSharedMemorySize, 104448);
    cudaFuncSetAttribute(gemmt_k<0,3,128>, cudaFuncAttributeMaxDynamicSharedMemorySize, 104448);
    const u32* WB0 = (const u32*)S + O_WB;
    const u32* WB1 = WB0 + 102400;
    const u32* WG  = (const u32*)S + O_WG;
    const float* Ab = S + O_AB;
    cudaStream_t s2 = g_si.s2;

    prep_k<<<800, 256>>>(wt, iwt, A_log, W_x, W_dt, S);
    prep2_k<<<192, 256>>>(W_in, W_out, S);

    auto mamba = [&](int L, int NCH, const float* llseq, float* llm, float* ws, cudaStream_t st) {
        int M = 4 * L;
        gemmt_k<1,1,64><<<dim3(M/128, 4), 256, 55296, st>>>(llseq, WG, 8192u, ws, nullptr, 0, L, ws);
        dwconv_k<<<(M*128)/256, 256, 0, st>>>(conv_w, conv_b, L, ws);
        gemmt_k<0,2,128><<<dim3(M/128, 3), 256, 104448, st>>>(ws + (size_t)M*256, WG + 16384, 12288u, nullptr, b_dt, 128, L, ws);
        scan1_k<<<dim3(8, NCH, 4), 256, 0, st>>>(L, NCH, ws, Ab);
        scan2_k<<<32, 256, 0, st>>>(L, NCH, ws);
        scan3_k<<<dim3(8, NCH, 4), 256, 0, st>>>(L, NCH, ws, Ab);
        ymul_k<<<(M*128)/256, 256, 0, st>>>(Dp, ws);
        gemmt_k<0,3,128><<<dim3(M/128, 1), 256, 104448, st>>>(ws + (size_t)M*544, WG + 40960, 4096u, llm, nullptr, 128, L, ws);
    };

    // level-0 decomposition
    pad_k<0><<<dim3(49,196,4), 256>>>(x, nullptr, nullptr, S + O_PAD, 192, 192);
    convt_k<<<dim3(12,48,4), 256, CSM>>>(S + O_PAD, WB0, S + O_HI0, S + O_LL0, 192, 192, 1);

    // fork: chain A (default stream) = mamba level-0; chain B (s2) = full level-1 subtree
    cudaEventRecord(g_si.evF, 0);
    cudaStreamWaitEvent(s2, g_si.evF, 0);

    mamba(9216, 72, S + O_LL0, S + O_LM0, S + O_WS0, 0);

    pad_k<1><<<dim3(25,100,4), 256, 0, s2>>>(S + O_LL0, nullptr, nullptr, S + O_PAD, 96, 96);
    convt_k<<<dim3(6,24,4), 256, CSM, s2>>>(S + O_PAD, WB0, S + O_HI1, S + O_LL1, 96, 96, 1);
    mamba(2304, 18, S + O_LL1, S + O_LM1, S + O_WS1, s2);
    pad_k<2><<<dim3(25,100,4), 256, 0, s2>>>(S + O_LM1, nullptr, S + O_HI1, S + O_PAD, 96, 96);
    convt_k<<<dim3(6,24,4), 256, CSM, s2>>>(S + O_PAD, WB1, S + O_RC, nullptr, 96, 96, 0);

    // join
    cudaEventRecord(g_si.evJ, s2);
    cudaStreamWaitEvent(0, g_si.evJ, 0);

    pad_k<2><<<dim3(49,196,4), 256>>>(S + O_LM0, S + O_RC, S + O_HI0, S + O_PAD, 192, 192);
    convt_k<<<dim3(12,48,4), 256, CSM>>>(S + O_PAD, WB1, (float*)d_out, nullptr, 192, 192, 0);
}

// round 10
// speedup vs baseline: 2.0775x; 1.0536x over previous
#include <cuda_runtime.h>
#include <cuda_bf16.h>
#include <cstdint>

typedef unsigned int u32;
#define DEV static __device__ __forceinline__

DEV u32 bpack(float lo, float hi){ u32 r; asm("cvt.rn.bf16x2.f32 %0, %2, %1;" : "=r"(r) : "f"(lo), "f"(hi)); return r; }
DEV float bres(float a){ u32 t = bpack(a, a); return a - __uint_as_float(t & 0xFFFF0000u); }
DEV u32 s2u(const void* p){ u32 a; asm("{ .reg .u64 t; cvta.to.shared.u64 t, %1; cvt.u32.u64 %0, t; }" : "=r"(a) : "l"(p)); return a; }

DEV void ldsm4(u32* r, u32 a){ asm volatile("ldmatrix.sync.aligned.m8n8.x4.shared.b16 {%0,%1,%2,%3}, [%4];"
  : "=r"(r[0]),"=r"(r[1]),"=r"(r[2]),"=r"(r[3]) : "r"(a)); }
DEV void ldsm2(u32* r, u32 a){ asm volatile("ldmatrix.sync.aligned.m8n8.x2.shared.b16 {%0,%1}, [%2];"
  : "=r"(r[0]),"=r"(r[1]) : "r"(a)); }
DEV void mma16816(float* c, const u32* a, const u32* b){
  asm volatile("mma.sync.aligned.m16n8k16.row.col.f32.bf16.bf16.f32 {%0,%1,%2,%3},{%4,%5,%6,%7},{%8,%9},{%0,%1,%2,%3};"
    : "+f"(c[0]),"+f"(c[1]),"+f"(c[2]),"+f"(c[3])
    : "r"(a[0]),"r"(a[1]),"r"(a[2]),"r"(a[3]),"r"(b[0]),"r"(b[1]));
}
DEV void cpasync16(u32 dst, const void* src){
  asm volatile("cp.async.cg.shared.global [%0], [%1], 16;" :: "r"(dst), "l"(src) : "memory");
}
#define CP_COMMIT() asm volatile("cp.async.commit_group;" ::: "memory")
#define CP_WAIT1()  asm volatile("cp.async.wait_group 1;" ::: "memory")
#define CP_WAIT0()  asm volatile("cp.async.wait_group 0;" ::: "memory")

// ---- scratch offsets (floats) ----
#define O_LL0 0ull
#define O_HI0 2359296ull
#define O_LL1 11796480ull
#define O_HI1 12386304ull
#define O_LM0 14745600ull
#define O_LM1 17104896ull
#define O_RC  17694720ull
#define O_WS0 20054016ull
#define O_WB  46596096ull
#define O_AB  46800896ull
#define O_WE  46802944ull
#define O_PAD 46827520ull
#define O_WG  56662016ull
#define O_WS1 56711168ull
#define S_TOT 63346688ull

__device__ __align__(16) float g_scratch[S_TOT];

struct StreamInit {
    cudaStream_t s2; cudaEvent_t evF, evJ;
    StreamInit() {
        cudaStreamCreate(&s2);
        cudaEventCreateWithFlags(&evF, cudaEventDisableTiming);
        cudaEventCreateWithFlags(&evJ, cudaEventDisableTiming);
    }
};
static StreamInit g_si;

DEV float softplus_f(float x){ return fmaxf(x, 0.f) + log1pf(__expf(-fabsf(x))); }

// ---- prep: bf16 hi/lo conv-weight slabs, A=-exp(A_log), Weff ----
__global__ void prep_k(const float* __restrict__ wt, const float* __restrict__ iwt,
                       const float* __restrict__ A_log, const float* __restrict__ W_x,
                       const float* __restrict__ W_dt, float* __restrict__ base)
{
    int i = blockIdx.x * 256 + threadIdx.x;
    if (i < 204800) {
        int f = i / 102400, r = i % 102400, term = r / 51200;
        int tap = (r / 2048) % 25, r3 = r % 2048, oc = r3 >> 5, k2 = r3 & 31;
        const float* filt = f ? iwt : wt;
        float w0 = filt[(oc*64 + 2*k2)*25 + tap];
        float w1 = filt[(oc*64 + 2*k2 + 1)*25 + tap];
        u32 v = term ? bpack(bres(w0), bres(w1)) : bpack(w0, w1);
        ((u32*)base)[O_WB + i] = v;
    }
    if (i < 2048) base[O_AB + i] = -__expf(A_log[i]);
    if (i < 16384) {
        int d = i >> 7, k = i & 127;
        float s = 0.f;
        #pragma unroll
        for (int r = 0; r < 4; r++) s += W_dt[d*4 + r] * W_x[r*128 + k];
        base[O_WE + i] = s;
    }
    if (i < 8192) {
        int j = i >> 7, k = i & 127;
        base[O_WE + (size_t)(128 + j)*128 + k] = (j < 32) ? W_x[(4 + j)*128 + k] : 0.f;
    }
}

// ---- prep2: bf16 hi/lo GEMM weight slabs ----
__global__ void prep2_k(const float* __restrict__ W_in, const float* __restrict__ W_out,
                        float* __restrict__ base)
{
    int i = blockIdx.x * 256 + threadIdx.x;
    if (i >= 49152) return;
    const float* src; int K, n, k2, term;
    if (i < 16384)      { term = i >> 13; int r = i & 8191;  n = r >> 5; k2 = r & 31; K = 64;  src = W_in; }
    else if (i < 40960) { int j = i - 16384; term = j / 12288; int r = j % 12288; n = r >> 6; k2 = r & 63; K = 128; src = base + O_WE; }
    else                { int j = i - 40960; term = j >> 12; int r = j & 4095;  n = r >> 6; k2 = r & 63; K = 128; src = W_out; }
    float w0 = src[(size_t)n*K + 2*k2], w1 = src[(size_t)n*K + 2*k2 + 1];
    ((u32*)base)[O_WG + i] = term ? bpack(bres(w0), bres(w1)) : bpack(w0, w1);
}

// ---- pad into NHWC, 4 px per block. MODE: 0 plain, 1 transposed-seq, 2 depth-to-space ----
template<int MODE>
__global__ void pad_k(const float* __restrict__ in, const float* __restrict__ llB,
                      const float* __restrict__ high, float* __restrict__ PAD, int H, int W)
{
    int ic = threadIdx.x & 63, xp = blockIdx.x*4 + (threadIdx.x >> 6);
    int yp = blockIdx.y, b = blockIdx.z;
    int X = W + 4, xi = xp - 2, yi = yp - 2;
    float v = 0.f;
    if ((unsigned)xi < (unsigned)W && (unsigned)yi < (unsigned)H) {
        if (MODE == 0)      v = in[(((size_t)b*64 + ic)*H + yi)*W + xi];
        else if (MODE == 1) v = in[(((size_t)b*64 + ic)*W + xi)*H + yi];
        else {
            int h2 = H>>1, w2 = W>>1, L2 = h2*w2, s = (yi&1)*2 + (xi&1), hy = yi>>1, hx = xi>>1;
            if (s == 0) {
                v = in[((size_t)b*64 + ic)*L2 + hx*h2 + hy];
                if (llB) v += llB[(((size_t)b*64 + ic)*h2 + hy)*w2 + hx];
            } else v = high[((((size_t)b*64 + ic)*4 + s)*h2 + hy)*w2 + hx];
        }
    }
    PAD[(((size_t)b*(H+4) + yp)*X + xp)*64 + ic] = v;
}

// ---- warp-MMA bf16 3-term conv: M=64(4rows x 16px), N=64 oc, 25 taps x K=64 ic ----
// smem (swizzled, stride 128): A hi [8][20][128B] @0 (20480), A lo @20480,
// B @40960: 2 bufs x 2 terms x 8192 (32KB). Total 72KB -> 3 CTAs/SM.
#define CSM 73728
__global__ void __launch_bounds__(256, 3) convt_k(
    const float* __restrict__ PAD, const u32* __restrict__ WBu,
    float* __restrict__ outP, float* __restrict__ outLL, int H, int W, int OUTMODE)
{
    extern __shared__ char sm[];
    u32 su = s2u(sm);
    int tid = threadIdx.x, wid = tid >> 5, lane = tid & 31;
    int wm = wid & 1, wn = wid >> 1;
    int b = blockIdx.z, Y0 = blockIdx.y * 4, x0 = blockIdx.x * 16;
    int X = W + 4;

    // A window: 8 rows x 20 xpos x 64 ic -> bf16 hi/lo, XOR-swizzled
    for (int i = tid; i < 2560; i += 256) {
        int r = i / 320, rem = i % 320, xx = rem >> 4, kg = rem & 15;
        float4 v = *(const float4*)(PAD + (((size_t)b*(H+4) + Y0 + r)*X + x0 + xx)*64 + kg*4);
        int rid = r*20 + xx;
        u32 off = (u32)(rid*128 + (((kg>>1) ^ (rid&7))*16) + (kg&1)*8);
        *(uint2*)(sm + off)         = make_uint2(bpack(v.x, v.y), bpack(v.z, v.w));
        *(uint2*)(sm + 20480 + off) = make_uint2(bpack(bres(v.x), bres(v.y)), bpack(bres(v.z), bres(v.w)));
    }

    auto issueB = [&](int tap, int buf) {
        #pragma unroll
        for (int it = 0; it < 4; it++) {
            int u = it*256 + tid, term = u >> 9, oc = (u >> 3) & 63, ch = u & 7;
            u32 dst = su + 40960u + (u32)buf*16384u + (u32)term*8192u
                    + (u32)(oc*128 + ((ch ^ (oc & 7))*16));
            cpasync16(dst, WBu + ((size_t)(term*25 + tap)*64 + oc)*32 + ch*4);
        }
        CP_COMMIT();
    };
    issueB(0, 0);

    // lane constants
    int pixrow[2], hi16 = lane >> 4;
    #pragma unroll
    for (int mt = 0; mt < 2; mt++) {
        int pix = wm*32 + mt*16 + (lane & 15);
        pixrow[mt] = (pix >> 4)*20 + (pix & 15);
    }
    // B ldsm4 lane mapping: oc = wn*16 + ((lane>>4)<<3) + (lane&7); chunk parity = (lane>>3)&1
    int boc = wn*16 + ((lane >> 4) << 3) + (lane & 7);
    u32 bnoff = su + 40960u + (u32)(boc*128);
    int b7 = boc & 7, bhalf = (lane >> 3) & 1;

    float acc[2][2][4];
    #pragma unroll
    for (int mt = 0; mt < 2; mt++)
        #pragma unroll
        for (int nt = 0; nt < 2; nt++)
            #pragma unroll
            for (int q = 0; q < 4; q++) acc[mt][nt][q] = 0.f;

    for (int tap = 0; tap < 25; tap++) {
        CP_WAIT0();
        __syncthreads();
        if (tap < 24) issueB(tap + 1, (tap + 1) & 1);

        int drow = (tap/5)*20 + (tap%5);
        u32 aaddr[2]; int ar7[2];
        #pragma unroll
        for (int mt = 0; mt < 2; mt++) {
            int rid = pixrow[mt] + drow;
            ar7[mt] = rid & 7;
            aaddr[mt] = su + (u32)(rid*128);
        }
        u32 bbuf = (u32)(tap & 1)*16384u;

        #pragma unroll
        for (int ks = 0; ks < 4; ks++) {
            int cA = ks*2 + hi16, cB = ks*2 + bhalf;
            u32 ah[2][4], al[2][4], bh[4], bl[4];
            #pragma unroll
            for (int mt = 0; mt < 2; mt++) {
                u32 sw = (u32)(((cA ^ ar7[mt]))*16);
                ldsm4(ah[mt], aaddr[mt] + sw);
                ldsm4(al[mt], aaddr[mt] + 20480u + sw);
            }
            {
                u32 sw = (u32)(((cB ^ b7))*16);
                ldsm4(bh, bnoff + bbuf + sw);
                ldsm4(bl, bnoff + bbuf + 8192u + sw);
            }
            #pragma unroll
            for (int mt = 0; mt < 2; mt++)
                #pragma unroll
                for (int nt = 0; nt < 2; nt++) {
                    mma16816(acc[mt][nt], ah[mt], bh + nt*2);
                    mma16816(acc[mt][nt], ah[mt], bl + nt*2);
                    mma16816(acc[mt][nt], al[mt], bh + nt*2);
                }
        }
    }

    int g = lane >> 2, t4 = lane & 3;
    int h2 = H >> 1, w2 = W >> 1, L2 = h2*w2;
    #pragma unroll
    for (int mt = 0; mt < 2; mt++)
        #pragma unroll
        for (int half = 0; half < 2; half++) {
            int m = wm*32 + mt*16 + g + half*8;
            int y = Y0 + (m >> 4), gx = x0 + (m & 15);
            #pragma unroll
            for (int nt = 0; nt < 2; nt++)
                #pragma unroll
                for (int q = 0; q < 2; q++) {
                    int oc = wn*16 + nt*8 + 2*t4 + q;
                    float v = acc[mt][nt][half*2 + q];
                    if (OUTMODE == 0) {
                        outP[(((size_t)b*64 + oc)*H + y)*W + gx] = v;
                    } else {
                        int s = (y & 1)*2 + (gx & 1), hy = y >> 1, hx = gx >> 1;
                        if (s == 0) outLL[((size_t)b*64 + oc)*L2 + hx*h2 + hy] = v;
                        else        outP[((((size_t)b*64 + oc)*4 + s)*h2 + hy)*w2 + hx] = v;
                    }
                }
        }
}

// ---- HMMA bf16 3-term GEMM: C[128m x 64n] = A[.,K] @ W[n,K]^T ----
template<int AMODE, int EPI, int K>
__global__ void __launch_bounds__(256) gemmt_k(const float* __restrict__ A, const u32* __restrict__ WG,
    u32 wsz, float* __restrict__ out, const float* __restrict__ bias, int lda, int L, float* __restrict__ ws)
{
    extern __shared__ char sm[];
    constexpr int rowB = (K + 8) * 2;
    constexpr u32 sAlo = 128u * rowB, sW = 256u * rowB;
    constexpr u32 wterm = 64u * rowB;
    u32 su = s2u(sm);
    int tid = threadIdx.x, wid = tid >> 5, lane = tid & 31;
    int wm = wid & 3, wn = wid >> 2;
    int m0 = blockIdx.x * 128, n0 = blockIdx.y * 64;
    int b = m0 / L, l0 = m0 % L;
    size_t Mt = (size_t)gridDim.x * 128;

    if (AMODE == 0) {
        #pragma unroll
        for (int it = 0; it < K / 8; it++) {
            int i = it*256 + tid;
            int ml = i / (K / 4), kq = i % (K / 4);
            float4 v = *(const float4*)(A + (size_t)(m0 + ml)*lda + kq*4);
            *(uint2*)(sm + ml*rowB + kq*8) = make_uint2(bpack(v.x, v.y), bpack(v.z, v.w));
            *(uint2*)(sm + sAlo + ml*rowB + kq*8) =
                make_uint2(bpack(bres(v.x), bres(v.y)), bpack(bres(v.z), bres(v.w)));
        }
    } else {
        #pragma unroll
        for (int it = 0; it < K / 8; it++) {
            int i = it*256 + tid;
            int k = i >> 5, mq = i & 31;
            float4 v = *(const float4*)(A + ((size_t)b*64 + k)*L + l0 + mq*4);
            float vv[4] = {v.x, v.y, v.z, v.w};
            #pragma unroll
            for (int j = 0; j < 4; j++) {
                int ml = mq*4 + j;
                *(__nv_bfloat16*)(sm + ml*rowB + k*2) = __float2bfloat16(vv[j]);
                *(__nv_bfloat16*)(sm + sAlo + ml*rowB + k*2) = __float2bfloat16(bres(vv[j]));
            }
        }
    }
    constexpr int kw4 = K / 8;
    #pragma unroll
    for (int it = 0; it < (2*64*kw4 + 255) / 256; it++) {
        int i = it*256 + tid;
        if (i < 2*64*kw4) {
            int term = i / (64*kw4), r = i % (64*kw4), n = r / kw4, kq = r % kw4;
            uint4 v = *(const uint4*)(WG + (size_t)term*wsz + (size_t)(n0 + n)*(K/2) + kq*4);
            *(uint4*)(sm + sW + term*wterm + n*rowB + kq*16) = v;
        }
    }
    __syncthreads();

    u32 abase[2], bbase[4];
    #pragma unroll
    for (int mt = 0; mt < 2; mt++)
        abase[mt] = su + (u32)((wm*32 + mt*16 + (lane & 15))*rowB + (lane >> 4)*16);
    #pragma unroll
    for (int nt = 0; nt < 4; nt++)
        bbase[nt] = su + sW + (u32)((wn*32 + nt*8 + (lane & 7))*rowB + ((lane >> 3) & 1)*16);

    float acc[2][4][4];
    #pragma unroll
    for (int mt = 0; mt < 2; mt++)
        #pragma unroll
        for (int nt = 0; nt < 4; nt++)
            #pragma unroll
            for (int q = 0; q < 4; q++) acc[mt][nt][q] = 0.f;

    #pragma unroll
    for (int ks = 0; ks < K / 16; ks++) {
        u32 ko = (u32)(ks*32);
        u32 ah[2][4], al[2][4], bh[4][2], bl[4][2];
        #pragma unroll
        for (int mt = 0; mt < 2; mt++) {
            ldsm4(ah[mt], abase[mt] + ko);
            ldsm4(al[mt], abase[mt] + sAlo + ko);
        }
        #pragma unroll
        for (int nt = 0; nt < 4; nt++) {
            ldsm2(bh[nt], bbase[nt] + ko);
            ldsm2(bl[nt], bbase[nt] + wterm + ko);
        }
        #pragma unroll
        for (int mt = 0; mt < 2; mt++)
            #pragma unroll
            for (int nt = 0; nt < 4; nt++) {
                mma16816(acc[mt][nt], ah[mt], bh[nt]);
                mma16816(acc[mt][nt], ah[mt], bl[nt]);
                mma16816(acc[mt][nt], al[mt], bh[nt]);
            }
    }

    int g = lane >> 2, t4 = lane & 3;
    #pragma unroll
    for (int mt = 0; mt < 2; mt++)
        #pragma unroll
        for (int half = 0; half < 2; half++) {
            int mloc = wm*32 + mt*16 + g + half*8;
            int m = m0 + mloc;
            #pragma unroll
            for (int nt = 0; nt < 4; nt++)
                #pragma unroll
                for (int q = 0; q < 2; q++) {
                    int n = n0 + wn*32 + nt*8 + 2*t4 + q;
                    float v = acc[mt][nt][half*2 + q];
                    if (EPI == 1) {
                        out[(size_t)m*256 + n] = v;
                    } else if (EPI == 2) {
                        if (n < 128)      ws[Mt*384 + (size_t)m*128 + n] = softplus_f(v + bias[n]);
                        else if (n < 160) ws[Mt*512 + (size_t)m*32 + n - 128] = v;
                    } else {
                        out[((size_t)b*64 + n)*L + l0 + mloc] = v;
                    }
                }
        }
}

__global__ void dwconv_k(const float* __restrict__ cw, const float* __restrict__ cb, int L, float* __restrict__ ws)
{
    size_t Mt = (size_t)gridDim.x * 2;
    size_t g = (size_t)blockIdx.x * 256 + threadIdx.x;
    int d = (int)(g & 127);
    size_t m = g >> 7;
    int l = (int)(m % (size_t)L);
    float acc = cb[d];
    #pragma unroll
    for (int j = 0; j < 4; j++) {
        int lj = l - 3 + j;
        if (lj >= 0) acc = fmaf(cw[d*4 + j], ws[(m - 3 + j)*256 + d], acc);
    }
    ws[Mt*256 + g] = acc * __fdividef(1.f, 1.f + __expf(-acc));
}

__global__ void scan1_k(int L, int NCH, float* __restrict__ ws, const float* __restrict__ Ab)
{
    size_t Mt = (size_t)4 * L;
    const float* dt = ws + Mt*384; const float* xs = ws + Mt*256; const float* bc = ws + Mt*512;
    int t = threadIdx.x, s = t & 15;
    int ch = blockIdx.y, b = blockIdx.z, d = blockIdx.x * 16 + (t >> 4);
    float a = Ab[d*16 + s];
    float h = 0.f, P = 1.f;
    size_t ml = (size_t)b*L + (size_t)ch*128;
    for (int i = 0; i < 128; i++) {
        size_t m = ml + i;
        float dtv = __ldg(dt + m*128 + d);
        float e = __expf(dtv * a);
        h = h*e + dtv*__ldg(xs + m*128 + d)*__ldg(bc + m*32 + s);
        P *= e;
    }
    size_t ix = (((size_t)(b*NCH + ch)*128) + d)*16 + s;
    ws[Mt*672 + ix] = P;
    ws[Mt*688 + ix] = h;
}

__global__ void scan2_k(int L, int NCH, float* __restrict__ ws)
{
    size_t Mt = (size_t)4 * L;
    int g = blockIdx.x * 256 + threadIdx.x;
    int b = g >> 11, ds = g & 2047;
    float carry = 0.f;
    for (int ch = 0; ch < NCH; ch++) {
        size_t ix = ((size_t)(b*NCH + ch))*2048 + ds;
        ws[Mt*704 + ix] = carry;
        carry = carry * ws[Mt*672 + ix] + ws[Mt*688 + ix];
    }
}

__global__ void scan3_k(int L, int NCH, float* __restrict__ ws, const float* __restrict__ Ab)
{
    size_t Mt = (size_t)4 * L;
    const float* dt = ws + Mt*384; const float* xs = ws + Mt*256; const float* bc = ws + Mt*512;
    int t = threadIdx.x, s = t & 15;
    int ch = blockIdx.y, b = blockIdx.z, d = blockIdx.x * 16 + (t >> 4);
    float a = Ab[d*16 + s];
    size_t ix = (((size_t)(b*NCH + ch)*128) + d)*16 + s;
    float h = ws[Mt*704 + ix];
    size_t ml = (size_t)b*L + (size_t)ch*128;
    for (int i = 0; i < 128; i++) {
        size_t m = ml + i;
        float dtv = __ldg(dt + m*128 + d);
        float e = __expf(dtv * a);
        h = h*e + dtv*__ldg(xs + m*128 + d)*__ldg(bc + m*32 + s);
        float part = h * __ldg(bc + m*32 + 16 + s);
        part += __shfl_xor_sync(0xffffffffu, part, 8);
        part += __shfl_xor_sync(0xffffffffu, part, 4);
        part += __shfl_xor_sync(0xffffffffu, part, 2);
        part += __shfl_xor_sync(0xffffffffu, part, 1);
        if (s == 0) ws[Mt*544 + m*128 + d] = part;
    }
}

__global__ void ymul_k(const float* __restrict__ Dp, float* __restrict__ ws)
{
    size_t Mt = (size_t)gridDim.x * 2;
    size_t g = (size_t)blockIdx.x * 256 + threadIdx.x;
    int d = (int)(g & 127);
    size_t m = g >> 7;
    float z = ws[m*256 + 128 + d];
    float sz = z * __fdividef(1.f, 1.f + __expf(-z));
    ws[Mt*544 + g] = (ws[Mt*544 + g] + ws[Mt*256 + g] * Dp[d]) * sz;
}

extern "C" void kernel_launch(void* const* d_in, const int* in_sizes, int n_in,
                              void* d_out, int out_size)
{
    const float* x      = (const float*)d_in[0];
    const float* wt     = (const float*)d_in[1];
    const float* iwt    = (const float*)d_in[2];
    const float* W_in   = (const float*)d_in[3];
    const float* conv_w = (const float*)d_in[4];
    const float* conv_b = (const float*)d_in[5];
    const float* W_x    = (const float*)d_in[6];
    const float* W_dt   = (const float*)d_in[7];
    const float* b_dt   = (const float*)d_in[8];
    const float* A_log  = (const float*)d_in[9];
    const float* Dp     = (const float*)d_in[10];
    const float* W_out  = (const float*)d_in[11];
    (void)in_sizes; (void)n_in; (void)out_size;

    float* S = nullptr;
    cudaGetSymbolAddress((void**)&S, g_scratch);
    cudaFuncSetAttribute(convt_k, cudaFuncAttributeMaxDynamicSharedMemorySize, CSM);
    cudaFuncSetAttribute(gemmt_k<1,1,64>,  cudaFuncAttributeMaxDynamicSharedMemorySize, 55296);
    cudaFuncSetAttribute(gemmt_k<0,2,128>, cudaFuncAttributeMaxDynamicSharedMemorySize, 104448);
    cudaFuncSetAttribute(gemmt_k<0,3,128>, cudaFuncAttributeMaxDynamicSharedMemorySize, 104448);
    const u32* WB0 = (const u32*)S + O_WB;
    const u32* WB1 = WB0 + 102400;
    const u32* WG  = (const u32*)S + O_WG;
    const float* Ab = S + O_AB;
    cudaStream_t s2 = g_si.s2;

    prep_k<<<800, 256>>>(wt, iwt, A_log, W_x, W_dt, S);
    prep2_k<<<192, 256>>>(W_in, W_out, S);

    auto mamba = [&](int L, int NCH, const float* llseq, float* llm, float* ws, cudaStream_t st) {
        int M = 4 * L;
        gemmt_k<1,1,64><<<dim3(M/128, 4), 256, 55296, st>>>(llseq, WG, 8192u, ws, nullptr, 0, L, ws);
        dwconv_k<<<(M*128)/256, 256, 0, st>>>(conv_w, conv_b, L, ws);
        gemmt_k<0,2,128><<<dim3(M/128, 3), 256, 104448, st>>>(ws + (size_t)M*256, WG + 16384, 12288u, nullptr, b_dt, 128, L, ws);
        scan1_k<<<dim3(8, NCH, 4), 256, 0, st>>>(L, NCH, ws, Ab);
        scan2_k<<<32, 256, 0, st>>>(L, NCH, ws);
        scan3_k<<<dim3(8, NCH, 4), 256, 0, st>>>(L, NCH, ws, Ab);
        ymul_k<<<(M*128)/256, 256, 0, st>>>(Dp, ws);
        gemmt_k<0,3,128><<<dim3(M/128, 1), 256, 104448, st>>>(ws + (size_t)M*544, WG + 40960, 4096u, llm, nullptr, 128, L, ws);
    };

    // level-0 decomposition
    pad_k<0><<<dim3(49,196,4), 256>>>(x, nullptr, nullptr, S + O_PAD, 192, 192);
    convt_k<<<dim3(12,48,4), 256, CSM>>>(S + O_PAD, WB0, S + O_HI0, S + O_LL0, 192, 192, 1);

    // fork: chain A (default stream) = mamba level-0; chain B (s2) = full level-1 subtree
    cudaEventRecord(g_si.evF, 0);
    cudaStreamWaitEvent(s2, g_si.evF, 0);

    mamba(9216, 72, S + O_LL0, S + O_LM0, S + O_WS0, 0);

    pad_k<1><<<dim3(25,100,4), 256, 0, s2>>>(S + O_LL0, nullptr, nullptr, S + O_PAD, 96, 96);
    convt_k<<<dim3(6,24,4), 256, CSM, s2>>>(S + O_PAD, WB0, S + O_HI1, S + O_LL1, 96, 96, 1);
    mamba(2304, 18, S + O_LL1, S + O_LM1, S + O_WS1, s2);
    pad_k<2><<<dim3(25,100,4), 256, 0, s2>>>(S + O_LM1, nullptr, S + O_HI1, S + O_PAD, 96, 96);
    convt_k<<<dim3(6,24,4), 256, CSM, s2>>>(S + O_PAD, WB1, S + O_RC, nullptr, 96, 96, 0);

    // join
    cudaEventRecord(g_si.evJ, s2);
    cudaStreamWaitEvent(0, g_si.evJ, 0);

    pad_k<2><<<dim3(49,196,4), 256>>>(S + O_LM0, S + O_RC, S + O_HI0, S + O_PAD, 192, 192);
    convt_k<<<dim3(12,48,4), 256, CSM>>>(S + O_PAD, WB1, (float*)d_out, nullptr, 192, 192, 0);
}

// round 11
// speedup vs baseline: 2.1555x; 1.0375x over previous
#include <cuda_runtime.h>
#include <cuda_bf16.h>
#include <cstdint>

typedef unsigned int u32;
#define DEV static __device__ __forceinline__

DEV u32 bpack(float lo, float hi){ u32 r; asm("cvt.rn.bf16x2.f32 %0, %2, %1;" : "=r"(r) : "f"(lo), "f"(hi)); return r; }
DEV float bres(float a){ u32 t = bpack(a, a); return a - __uint_as_float(t & 0xFFFF0000u); }
DEV u32 s2u(const void* p){ u32 a; asm("{ .reg .u64 t; cvta.to.shared.u64 t, %1; cvt.u32.u64 %0, t; }" : "=r"(a) : "l"(p)); return a; }

DEV void ldsm4(u32* r, u32 a){ asm volatile("ldmatrix.sync.aligned.m8n8.x4.shared.b16 {%0,%1,%2,%3}, [%4];"
  : "=r"(r[0]),"=r"(r[1]),"=r"(r[2]),"=r"(r[3]) : "r"(a)); }
DEV void ldsm2(u32* r, u32 a){ asm volatile("ldmatrix.sync.aligned.m8n8.x2.shared.b16 {%0,%1}, [%2];"
  : "=r"(r[0]),"=r"(r[1]) : "r"(a)); }
DEV void mma16816(float* c, const u32* a, const u32* b){
  asm volatile("mma.sync.aligned.m16n8k16.row.col.f32.bf16.bf16.f32 {%0,%1,%2,%3},{%4,%5,%6,%7},{%8,%9},{%0,%1,%2,%3};"
    : "+f"(c[0]),"+f"(c[1]),"+f"(c[2]),"+f"(c[3])
    : "r"(a[0]),"r"(a[1]),"r"(a[2]),"r"(a[3]),"r"(b[0]),"r"(b[1]));
}
DEV void cpasync16(u32 dst, const void* src){
  asm volatile("cp.async.cg.shared.global [%0], [%1], 16;" :: "r"(dst), "l"(src) : "memory");
}
#define CP_COMMIT() asm volatile("cp.async.commit_group;" ::: "memory")
#define CP_WAIT0()  asm volatile("cp.async.wait_group 0;" ::: "memory")

// ---- scratch offsets (floats) ----
#define O_LL0 0ull
#define O_HI0 2359296ull
#define O_LL1 11796480ull
#define O_HI1 12386304ull
#define O_LM0 14745600ull
#define O_LM1 17104896ull
#define O_RC  17694720ull
#define O_WS0 20054016ull
#define O_WB  46596096ull
#define O_AB  46800896ull
#define O_WE  46802944ull
#define O_PAD 46827520ull
#define O_WG  56662016ull
#define O_WS1 56711168ull
#define S_TOT 63346688ull

__device__ __align__(16) float g_scratch[S_TOT];

struct StreamInit {
    cudaStream_t s2; cudaEvent_t evF, evJ;
    StreamInit() {
        cudaStreamCreate(&s2);
        cudaEventCreateWithFlags(&evF, cudaEventDisableTiming);
        cudaEventCreateWithFlags(&evJ, cudaEventDisableTiming);
    }
};
static StreamInit g_si;

DEV float softplus_f(float x){ return fmaxf(x, 0.f) + log1pf(__expf(-fabsf(x))); }

// ---- prep: bf16 hi/lo conv-weight slabs, A=-exp(A_log), Weff ----
__global__ void prep_k(const float* __restrict__ wt, const float* __restrict__ iwt,
                       const float* __restrict__ A_log, const float* __restrict__ W_x,
                       const float* __restrict__ W_dt, float* __restrict__ base)
{
    int i = blockIdx.x * 256 + threadIdx.x;
    if (i < 204800) {
        int f = i / 102400, r = i % 102400, term = r / 51200;
        int tap = (r / 2048) % 25, r3 = r % 2048, oc = r3 >> 5, k2 = r3 & 31;
        const float* filt = f ? iwt : wt;
        float w0 = filt[(oc*64 + 2*k2)*25 + tap];
        float w1 = filt[(oc*64 + 2*k2 + 1)*25 + tap];
        u32 v = term ? bpack(bres(w0), bres(w1)) : bpack(w0, w1);
        ((u32*)base)[O_WB + i] = v;
    }
    if (i < 2048) base[O_AB + i] = -__expf(A_log[i]);
    if (i < 16384) {
        int d = i >> 7, k = i & 127;
        float s = 0.f;
        #pragma unroll
        for (int r = 0; r < 4; r++) s += W_dt[d*4 + r] * W_x[r*128 + k];
        base[O_WE + i] = s;
    }
    if (i < 8192) {
        int j = i >> 7, k = i & 127;
        base[O_WE + (size_t)(128 + j)*128 + k] = (j < 32) ? W_x[(4 + j)*128 + k] : 0.f;
    }
}

// ---- prep2: bf16 hi/lo GEMM weight slabs ----
__global__ void prep2_k(const float* __restrict__ W_in, const float* __restrict__ W_out,
                        float* __restrict__ base)
{
    int i = blockIdx.x * 256 + threadIdx.x;
    if (i >= 49152) return;
    const float* src; int K, n, k2, term;
    if (i < 16384)      { term = i >> 13; int r = i & 8191;  n = r >> 5; k2 = r & 31; K = 64;  src = W_in; }
    else if (i < 40960) { int j = i - 16384; term = j / 12288; int r = j % 12288; n = r >> 6; k2 = r & 63; K = 128; src = base + O_WE; }
    else                { int j = i - 40960; term = j >> 12; int r = j & 4095;  n = r >> 6; k2 = r & 63; K = 128; src = W_out; }
    float w0 = src[(size_t)n*K + 2*k2], w1 = src[(size_t)n*K + 2*k2 + 1];
    ((u32*)base)[O_WG + i] = term ? bpack(bres(w0), bres(w1)) : bpack(w0, w1);
}

// ---- pad into NHWC, 4 px per block. MODE: 0 plain, 1 transposed-seq, 2 depth-to-space ----
template<int MODE>
__global__ void pad_k(const float* __restrict__ in, const float* __restrict__ llB,
                      const float* __restrict__ high, float* __restrict__ PAD, int H, int W)
{
    int ic = threadIdx.x & 63, xp = blockIdx.x*4 + (threadIdx.x >> 6);
    int yp = blockIdx.y, b = blockIdx.z;
    int X = W + 4, xi = xp - 2, yi = yp - 2;
    float v = 0.f;
    if ((unsigned)xi < (unsigned)W && (unsigned)yi < (unsigned)H) {
        if (MODE == 0)      v = in[(((size_t)b*64 + ic)*H + yi)*W + xi];
        else if (MODE == 1) v = in[(((size_t)b*64 + ic)*W + xi)*H + yi];
        else {
            int h2 = H>>1, w2 = W>>1, L2 = h2*w2, s = (yi&1)*2 + (xi&1), hy = yi>>1, hx = xi>>1;
            if (s == 0) {
                v = in[((size_t)b*64 + ic)*L2 + hx*h2 + hy];
                if (llB) v += llB[(((size_t)b*64 + ic)*h2 + hy)*w2 + hx];
            } else v = high[((((size_t)b*64 + ic)*4 + s)*h2 + hy)*w2 + hx];
        }
    }
    PAD[(((size_t)b*(H+4) + yp)*X + xp)*64 + ic] = v;
}

// ---- warp-MMA bf16 3-term conv: M=128(8rows x 16px), N=64 oc, 25 taps x K=64 ic ----
// warps 4(wm) x 2(wn): Mw=32, Nw=32.
// smem (swizzled, stride 128): A hi [12][20][128B] @0 (30720), A lo @30720,
// B @61440: 2 bufs x 2 terms x 8192 (32KB). Total 94208 -> 2 CTAs/SM.
#define CSM 94208
__global__ void __launch_bounds__(256, 2) convt_k(
    const float* __restrict__ PAD, const u32* __restrict__ WBu,
    float* __restrict__ outP, float* __restrict__ outLL, int H, int W, int OUTMODE)
{
    extern __shared__ char sm[];
    u32 su = s2u(sm);
    int tid = threadIdx.x, wid = tid >> 5, lane = tid & 31;
    int wm = wid & 3, wn = wid >> 2;
    int b = blockIdx.z, Y0 = blockIdx.y * 8, x0 = blockIdx.x * 16;
    int X = W + 4;

    // A window: 12 rows x 20 xpos x 64 ic -> bf16 hi/lo, XOR-swizzled
    for (int i = tid; i < 3840; i += 256) {
        int r = i / 320, rem = i % 320, xx = rem >> 4, kg = rem & 15;
        float4 v = *(const float4*)(PAD + (((size_t)b*(H+4) + Y0 + r)*X + x0 + xx)*64 + kg*4);
        int rid = r*20 + xx;
        u32 off = (u32)(rid*128 + (((kg>>1) ^ (rid&7))*16) + (kg&1)*8);
        *(uint2*)(sm + off)         = make_uint2(bpack(v.x, v.y), bpack(v.z, v.w));
        *(uint2*)(sm + 30720 + off) = make_uint2(bpack(bres(v.x), bres(v.y)), bpack(bres(v.z), bres(v.w)));
    }

    auto issueB = [&](int tap, int buf) {
        #pragma unroll
        for (int it = 0; it < 4; it++) {
            int u = it*256 + tid, term = u >> 9, oc = (u >> 3) & 63, ch = u & 7;
            u32 dst = su + 61440u + (u32)buf*16384u + (u32)term*8192u
                    + (u32)(oc*128 + ((ch ^ (oc & 7))*16));
            cpasync16(dst, WBu + ((size_t)(term*25 + tap)*64 + oc)*32 + ch*4);
        }
        CP_COMMIT();
    };
    issueB(0, 0);

    // lane constants
    int pixrow[2], hi16 = lane >> 4;
    #pragma unroll
    for (int mt = 0; mt < 2; mt++) {
        int pix = wm*32 + mt*16 + (lane & 15);
        pixrow[mt] = (pix >> 4)*20 + (pix & 15);
    }
    // B ldsm4 lane mapping per 16-row group g2: oc = wn*32 + g2*16 + ((lane>>4)<<3) + (lane&7)
    u32 bnoff[2]; int b7[2]; int bhalf = (lane >> 3) & 1;
    #pragma unroll
    for (int g2 = 0; g2 < 2; g2++) {
        int boc = wn*32 + g2*16 + ((lane >> 4) << 3) + (lane & 7);
        bnoff[g2] = su + 61440u + (u32)(boc*128);
        b7[g2] = boc & 7;
    }

    float acc[2][4][4];
    #pragma unroll
    for (int mt = 0; mt < 2; mt++)
        #pragma unroll
        for (int nt = 0; nt < 4; nt++)
            #pragma unroll
            for (int q = 0; q < 4; q++) acc[mt][nt][q] = 0.f;

    for (int tap = 0; tap < 25; tap++) {
        CP_WAIT0();
        __syncthreads();
        if (tap < 24) issueB(tap + 1, (tap + 1) & 1);

        int drow = (tap/5)*20 + (tap%5);
        u32 aaddr[2]; int ar7[2];
        #pragma unroll
        for (int mt = 0; mt < 2; mt++) {
            int rid = pixrow[mt] + drow;
            ar7[mt] = rid & 7;
            aaddr[mt] = su + (u32)(rid*128);
        }
        u32 bbuf = (u32)(tap & 1)*16384u;

        #pragma unroll
        for (int ks = 0; ks < 4; ks++) {
            int cA = ks*2 + hi16, cB = ks*2 + bhalf;
            u32 ah[2][4], al[2][4], bh[8], bl[8];
            #pragma unroll
            for (int mt = 0; mt < 2; mt++) {
                u32 sw = (u32)(((cA ^ ar7[mt]))*16);
                ldsm4(ah[mt], aaddr[mt] + sw);
                ldsm4(al[mt], aaddr[mt] + 30720u + sw);
            }
            #pragma unroll
            for (int g2 = 0; g2 < 2; g2++) {
                u32 sw = (u32)(((cB ^ b7[g2]))*16);
                ldsm4(bh + g2*4, bnoff[g2] + bbuf + sw);
                ldsm4(bl + g2*4, bnoff[g2] + bbuf + 8192u + sw);
            }
            #pragma unroll
            for (int mt = 0; mt < 2; mt++)
                #pragma unroll
                for (int nt = 0; nt < 4; nt++) {
                    mma16816(acc[mt][nt], ah[mt], bh + nt*2);
                    mma16816(acc[mt][nt], ah[mt], bl + nt*2);
                    mma16816(acc[mt][nt], al[mt], bh + nt*2);
                }
        }
    }

    int g = lane >> 2, t4 = lane & 3;
    int h2 = H >> 1, w2 = W >> 1, L2 = h2*w2;
    #pragma unroll
    for (int mt = 0; mt < 2; mt++)
        #pragma unroll
        for (int half = 0; half < 2; half++) {
            int m = wm*32 + mt*16 + g + half*8;
            int y = Y0 + (m >> 4), gx = x0 + (m & 15);
            #pragma unroll
            for (int nt = 0; nt < 4; nt++)
                #pragma unroll
                for (int q = 0; q < 2; q++) {
                    int oc = wn*32 + nt*8 + 2*t4 + q;
                    float v = acc[mt][nt][half*2 + q];
                    if (OUTMODE == 0) {
                        outP[(((size_t)b*64 + oc)*H + y)*W + gx] = v;
                    } else {
                        int s = (y & 1)*2 + (gx & 1), hy = y >> 1, hx = gx >> 1;
                        if (s == 0) outLL[((size_t)b*64 + oc)*L2 + hx*h2 + hy] = v;
                        else        outP[((((size_t)b*64 + oc)*4 + s)*h2 + hy)*w2 + hx] = v;
                    }
                }
        }
}

// ---- HMMA bf16 3-term GEMM: C[128m x 64n] = A[.,K] @ W[n,K]^T ----
template<int AMODE, int EPI, int K>
__global__ void __launch_bounds__(256) gemmt_k(const float* __restrict__ A, const u32* __restrict__ WG,
    u32 wsz, float* __restrict__ out, const float* __restrict__ bias, int lda, int L, float* __restrict__ ws)
{
    extern __shared__ char sm[];
    constexpr int rowB = (K + 8) * 2;
    constexpr u32 sAlo = 128u * rowB, sW = 256u * rowB;
    constexpr u32 wterm = 64u * rowB;
    u32 su = s2u(sm);
    int tid = threadIdx.x, wid = tid >> 5, lane = tid & 31;
    int wm = wid & 3, wn = wid >> 2;
    int m0 = blockIdx.x * 128, n0 = blockIdx.y * 64;
    int b = m0 / L, l0 = m0 % L;
    size_t Mt = (size_t)gridDim.x * 128;

    if (AMODE == 0) {
        #pragma unroll
        for (int it = 0; it < K / 8; it++) {
            int i = it*256 + tid;
            int ml = i / (K / 4), kq = i % (K / 4);
            float4 v = *(const float4*)(A + (size_t)(m0 + ml)*lda + kq*4);
            *(uint2*)(sm + ml*rowB + kq*8) = make_uint2(bpack(v.x, v.y), bpack(v.z, v.w));
            *(uint2*)(sm + sAlo + ml*rowB + kq*8) =
                make_uint2(bpack(bres(v.x), bres(v.y)), bpack(bres(v.z), bres(v.w)));
        }
    } else {
        #pragma unroll
        for (int it = 0; it < K / 8; it++) {
            int i = it*256 + tid;
            int k = i >> 5, mq = i & 31;
            float4 v = *(const float4*)(A + ((size_t)b*64 + k)*L + l0 + mq*4);
            float vv[4] = {v.x, v.y, v.z, v.w};
            #pragma unroll
            for (int j = 0; j < 4; j++) {
                int ml = mq*4 + j;
                *(__nv_bfloat16*)(sm + ml*rowB + k*2) = __float2bfloat16(vv[j]);
                *(__nv_bfloat16*)(sm + sAlo + ml*rowB + k*2) = __float2bfloat16(bres(vv[j]));
            }
        }
    }
    constexpr int kw4 = K / 8;
    #pragma unroll
    for (int it = 0; it < (2*64*kw4 + 255) / 256; it++) {
        int i = it*256 + tid;
        if (i < 2*64*kw4) {
            int term = i / (64*kw4), r = i % (64*kw4), n = r / kw4, kq = r % kw4;
            uint4 v = *(const uint4*)(WG + (size_t)term*wsz + (size_t)(n0 + n)*(K/2) + kq*4);
            *(uint4*)(sm + sW + term*wterm + n*rowB + kq*16) = v;
        }
    }
    __syncthreads();

    u32 abase[2], bbase[4];
    #pragma unroll
    for (int mt = 0; mt < 2; mt++)
        abase[mt] = su + (u32)((wm*32 + mt*16 + (lane & 15))*rowB + (lane >> 4)*16);
    #pragma unroll
    for (int nt = 0; nt < 4; nt++)
        bbase[nt] = su + sW + (u32)((wn*32 + nt*8 + (lane & 7))*rowB + ((lane >> 3) & 1)*16);

    float acc[2][4][4];
    #pragma unroll
    for (int mt = 0; mt < 2; mt++)
        #pragma unroll
        for (int nt = 0; nt < 4; nt++)
            #pragma unroll
            for (int q = 0; q < 4; q++) acc[mt][nt][q] = 0.f;

    #pragma unroll
    for (int ks = 0; ks < K / 16; ks++) {
        u32 ko = (u32)(ks*32);
        u32 ah[2][4], al[2][4], bh[4][2], bl[4][2];
        #pragma unroll
        for (int mt = 0; mt < 2; mt++) {
            ldsm4(ah[mt], abase[mt] + ko);
            ldsm4(al[mt], abase[mt] + sAlo + ko);
        }
        #pragma unroll
        for (int nt = 0; nt < 4; nt++) {
            ldsm2(bh[nt], bbase[nt] + ko);
            ldsm2(bl[nt], bbase[nt] + wterm + ko);
        }
        #pragma unroll
        for (int mt = 0; mt < 2; mt++)
            #pragma unroll
            for (int nt = 0; nt < 4; nt++) {
                mma16816(acc[mt][nt], ah[mt], bh[nt]);
                mma16816(acc[mt][nt], ah[mt], bl[nt]);
                mma16816(acc[mt][nt], al[mt], bh[nt]);
            }
    }

    int g = lane >> 2, t4 = lane & 3;
    #pragma unroll
    for (int mt = 0; mt < 2; mt++)
        #pragma unroll
        for (int half = 0; half < 2; half++) {
            int mloc = wm*32 + mt*16 + g + half*8;
            int m = m0 + mloc;
            #pragma unroll
            for (int nt = 0; nt < 4; nt++)
                #pragma unroll
                for (int q = 0; q < 2; q++) {
                    int n = n0 + wn*32 + nt*8 + 2*t4 + q;
                    float v = acc[mt][nt][half*2 + q];
                    if (EPI == 1) {
                        out[(size_t)m*256 + n] = v;
                    } else if (EPI == 2) {
                        if (n < 128)      ws[Mt*384 + (size_t)m*128 + n] = softplus_f(v + bias[n]);
                        else if (n < 160) ws[Mt*512 + (size_t)m*32 + n - 128] = v;
                    } else {
                        out[((size_t)b*64 + n)*L + l0 + mloc] = v;
                    }
                }
        }
}

__global__ void dwconv_k(const float* __restrict__ cw, const float* __restrict__ cb, int L, float* __restrict__ ws)
{
    size_t Mt = (size_t)gridDim.x * 2;
    size_t g = (size_t)blockIdx.x * 256 + threadIdx.x;
    int d = (int)(g & 127);
    size_t m = g >> 7;
    int l = (int)(m % (size_t)L);
    float acc = cb[d];
    #pragma unroll
    for (int j = 0; j < 4; j++) {
        int lj = l - 3 + j;
        if (lj >= 0) acc = fmaf(cw[d*4 + j], ws[(m - 3 + j)*256 + d], acc);
    }
    ws[Mt*256 + g] = acc * __fdividef(1.f, 1.f + __expf(-acc));
}

__global__ void scan1_k(int L, int NCH, float* __restrict__ ws, const float* __restrict__ Ab)
{
    size_t Mt = (size_t)4 * L;
    const float* dt = ws + Mt*384; const float* xs = ws + Mt*256; const float* bc = ws + Mt*512;
    int t = threadIdx.x, s = t & 15;
    int ch = blockIdx.y, b = blockIdx.z, d = blockIdx.x * 16 + (t >> 4);
    float a = Ab[d*16 + s];
    float h = 0.f, P = 1.f;
    size_t ml = (size_t)b*L + (size_t)ch*128;
    for (int i = 0; i < 128; i++) {
        size_t m = ml + i;
        float dtv = __ldg(dt + m*128 + d);
        float e = __expf(dtv * a);
        h = h*e + dtv*__ldg(xs + m*128 + d)*__ldg(bc + m*32 + s);
        P *= e;
    }
    size_t ix = (((size_t)(b*NCH + ch)*128) + d)*16 + s;
    ws[Mt*672 + ix] = P;
    ws[Mt*688 + ix] = h;
}

__global__ void scan2_k(int L, int NCH, float* __restrict__ ws)
{
    size_t Mt = (size_t)4 * L;
    int g = blockIdx.x * 256 + threadIdx.x;
    int b = g >> 11, ds = g & 2047;
    float carry = 0.f;
    for (int ch = 0; ch < NCH; ch++) {
        size_t ix = ((size_t)(b*NCH + ch))*2048 + ds;
        ws[Mt*704 + ix] = carry;
        carry = carry * ws[Mt*672 + ix] + ws[Mt*688 + ix];
    }
}

__global__ void scan3_k(int L, int NCH, float* __restrict__ ws, const float* __restrict__ Ab)
{
    size_t Mt = (size_t)4 * L;
    const float* dt = ws + Mt*384; const float* xs = ws + Mt*256; const float* bc = ws + Mt*512;
    int t = threadIdx.x, s = t & 15;
    int ch = blockIdx.y, b = blockIdx.z, d = blockIdx.x * 16 + (t >> 4);
    float a = Ab[d*16 + s];
    size_t ix = (((size_t)(b*NCH + ch)*128) + d)*16 + s;
    float h = ws[Mt*704 + ix];
    size_t ml = (size_t)b*L + (size_t)ch*128;
    for (int i = 0; i < 128; i++) {
        size_t m = ml + i;
        float dtv = __ldg(dt + m*128 + d);
        float e = __expf(dtv * a);
        h = h*e + dtv*__ldg(xs + m*128 + d)*__ldg(bc + m*32 + s);
        float part = h * __ldg(bc + m*32 + 16 + s);
        part += __shfl_xor_sync(0xffffffffu, part, 8);
        part += __shfl_xor_sync(0xffffffffu, part, 4);
        part += __shfl_xor_sync(0xffffffffu, part, 2);
        part += __shfl_xor_sync(0xffffffffu, part, 1);
        if (s == 0) ws[Mt*544 + m*128 + d] = part;
    }
}

__global__ void ymul_k(const float* __restrict__ Dp, float* __restrict__ ws)
{
    size_t Mt = (size_t)gridDim.x * 2;
    size_t g = (size_t)blockIdx.x * 256 + threadIdx.x;
    int d = (int)(g & 127);
    size_t m = g >> 7;
    float z = ws[m*256 + 128 + d];
    float sz = z * __fdividef(1.f, 1.f + __expf(-z));
    ws[Mt*544 + g] = (ws[Mt*544 + g] + ws[Mt*256 + g] * Dp[d]) * sz;
}

extern "C" void kernel_launch(void* const* d_in, const int* in_sizes, int n_in,
                              void* d_out, int out_size)
{
    const float* x      = (const float*)d_in[0];
    const float* wt     = (const float*)d_in[1];
    const float* iwt    = (const float*)d_in[2];
    const float* W_in   = (const float*)d_in[3];
    const float* conv_w = (const float*)d_in[4];
    const float* conv_b = (const float*)d_in[5];
    const float* W_x    = (const float*)d_in[6];
    const float* W_dt   = (const float*)d_in[7];
    const float* b_dt   = (const float*)d_in[8];
    const float* A_log  = (const float*)d_in[9];
    const float* Dp     = (const float*)d_in[10];
    const float* W_out  = (const float*)d_in[11];
    (void)in_sizes; (void)n_in; (void)out_size;

    float* S = nullptr;
    cudaGetSymbolAddress((void**)&S, g_scratch);
    cudaFuncSetAttribute(convt_k, cudaFuncAttributeMaxDynamicSharedMemorySize, CSM);
    cudaFuncSetAttribute(gemmt_k<1,1,64>,  cudaFuncAttributeMaxDynamicSharedMemorySize, 55296);
    cudaFuncSetAttribute(gemmt_k<0,2,128>, cudaFuncAttributeMaxDynamicSharedMemorySize, 104448);
    cudaFuncSetAttribute(gemmt_k<0,3,128>, cudaFuncAttributeMaxDynamicSharedMemorySize, 104448);
    const u32* WB0 = (const u32*)S + O_WB;
    const u32* WB1 = WB0 + 102400;
    const u32* WG  = (const u32*)S + O_WG;
    const float* Ab = S + O_AB;
    cudaStream_t s2 = g_si.s2;

    prep_k<<<800, 256>>>(wt, iwt, A_log, W_x, W_dt, S);
    prep2_k<<<192, 256>>>(W_in, W_out, S);

    auto mamba = [&](int L, int NCH, const float* llseq, float* llm, float* ws, cudaStream_t st) {
        int M = 4 * L;
        gemmt_k<1,1,64><<<dim3(M/128, 4), 256, 55296, st>>>(llseq, WG, 8192u, ws, nullptr, 0, L, ws);
        dwconv_k<<<(M*128)/256, 256, 0, st>>>(conv_w, conv_b, L, ws);
        gemmt_k<0,2,128><<<dim3(M/128, 3), 256, 104448, st>>>(ws + (size_t)M*256, WG + 16384, 12288u, nullptr, b_dt, 128, L, ws);
        scan1_k<<<dim3(8, NCH, 4), 256, 0, st>>>(L, NCH, ws, Ab);
        scan2_k<<<32, 256, 0, st>>>(L, NCH, ws);
        scan3_k<<<dim3(8, NCH, 4), 256, 0, st>>>(L, NCH, ws, Ab);
        ymul_k<<<(M*128)/256, 256, 0, st>>>(Dp, ws);
        gemmt_k<0,3,128><<<dim3(M/128, 1), 256, 104448, st>>>(ws + (size_t)M*544, WG + 40960, 4096u, llm, nullptr, 128, L, ws);
    };

    // level-0 decomposition
    pad_k<0><<<dim3(49,196,4), 256>>>(x, nullptr, nullptr, S + O_PAD, 192, 192);
    convt_k<<<dim3(12,24,4), 256, CSM>>>(S + O_PAD, WB0, S + O_HI0, S + O_LL0, 192, 192, 1);

    // fork: chain A (default stream) = mamba level-0; chain B (s2) = full level-1 subtree
    cudaEventRecord(g_si.evF, 0);
    cudaStreamWaitEvent(s2, g_si.evF, 0);

    mamba(9216, 72, S + O_LL0, S + O_LM0, S + O_WS0, 0);

    pad_k<1><<<dim3(25,100,4), 256, 0, s2>>>(S + O_LL0, nullptr, nullptr, S + O_PAD, 96, 96);
    convt_k<<<dim3(6,12,4), 256, CSM, s2>>>(S + O_PAD, WB0, S + O_HI1, S + O_LL1, 96, 96, 1);
    mamba(2304, 18, S + O_LL1, S + O_LM1, S + O_WS1, s2);
    pad_k<2><<<dim3(25,100,4), 256, 0, s2>>>(S + O_LM1, nullptr, S + O_HI1, S + O_PAD, 96, 96);
    convt_k<<<dim3(6,12,4), 256, CSM, s2>>>(S + O_PAD, WB1, S + O_RC, nullptr, 96, 96, 0);

    // join
    cudaEventRecord(g_si.evJ, s2);
    cudaStreamWaitEvent(0, g_si.evJ, 0);

    pad_k<2><<<dim3(49,196,4), 256>>>(S + O_LM0, S + O_RC, S + O_HI0, S + O_PAD, 192, 192);
    convt_k<<<dim3(12,24,4), 256, CSM>>>(S + O_PAD, WB1, (float*)d_out, nullptr, 192, 192, 0);
}

// round 12
// speedup vs baseline: 2.2208x; 1.0303x over previous
#include <cuda_runtime.h>
#include <cuda_bf16.h>
#include <cstdint>

typedef unsigned int u32;
#define DEV static __device__ __forceinline__

DEV u32 bpack(float lo, float hi){ u32 r; asm("cvt.rn.bf16x2.f32 %0, %2, %1;" : "=r"(r) : "f"(lo), "f"(hi)); return r; }
DEV float bres(float a){ u32 t = bpack(a, a); return a - __uint_as_float(t & 0xFFFF0000u); }
DEV u32 s2u(const void* p){ u32 a; asm("{ .reg .u64 t; cvta.to.shared.u64 t, %1; cvt.u32.u64 %0, t; }" : "=r"(a) : "l"(p)); return a; }

DEV void ldsm4(u32* r, u32 a){ asm volatile("ldmatrix.sync.aligned.m8n8.x4.shared.b16 {%0,%1,%2,%3}, [%4];"
  : "=r"(r[0]),"=r"(r[1]),"=r"(r[2]),"=r"(r[3]) : "r"(a)); }
DEV void ldsm2(u32* r, u32 a){ asm volatile("ldmatrix.sync.aligned.m8n8.x2.shared.b16 {%0,%1}, [%2];"
  : "=r"(r[0]),"=r"(r[1]) : "r"(a)); }
DEV void mma16816(float* c, const u32* a, const u32* b){
  asm volatile("mma.sync.aligned.m16n8k16.row.col.f32.bf16.bf16.f32 {%0,%1,%2,%3},{%4,%5,%6,%7},{%8,%9},{%0,%1,%2,%3};"
    : "+f"(c[0]),"+f"(c[1]),"+f"(c[2]),"+f"(c[3])
    : "r"(a[0]),"r"(a[1]),"r"(a[2]),"r"(a[3]),"r"(b[0]),"r"(b[1]));
}
DEV void cpasync16(u32 dst, const void* src){
  asm volatile("cp.async.cg.shared.global [%0], [%1], 16;" :: "r"(dst), "l"(src) : "memory");
}
#define CP_COMMIT() asm volatile("cp.async.commit_group;" ::: "memory")
#define CP_WAIT0()  asm volatile("cp.async.wait_group 0;" ::: "memory")

// ---- scratch offsets (floats) ----
#define O_LL0 0ull
#define O_HI0 2359296ull
#define O_LL1 11796480ull
#define O_HI1 12386304ull
#define O_LM0 14745600ull
#define O_LM1 17104896ull
#define O_RC  17694720ull
#define O_WS0 20054016ull
#define O_WB  46596096ull
#define O_AB  46800896ull
#define O_WE  46802944ull
#define O_PAD 46827520ull
#define O_WG  56662016ull
#define O_WS1 56711168ull
#define S_TOT 63346688ull

__device__ __align__(16) float g_scratch[S_TOT];

struct StreamInit {
    cudaStream_t s2; cudaEvent_t evF, evJ;
    StreamInit() {
        cudaStreamCreate(&s2);
        cudaEventCreateWithFlags(&evF, cudaEventDisableTiming);
        cudaEventCreateWithFlags(&evJ, cudaEventDisableTiming);
    }
};
static StreamInit g_si;

DEV float softplus_f(float x){ return fmaxf(x, 0.f) + log1pf(__expf(-fabsf(x))); }

// ---- prep: bf16 hi/lo conv-weight slabs, A=-exp(A_log), Weff ----
__global__ void prep_k(const float* __restrict__ wt, const float* __restrict__ iwt,
                       const float* __restrict__ A_log, const float* __restrict__ W_x,
                       const float* __restrict__ W_dt, float* __restrict__ base)
{
    int i = blockIdx.x * 256 + threadIdx.x;
    if (i < 204800) {
        int f = i / 102400, r = i % 102400, term = r / 51200;
        int tap = (r / 2048) % 25, r3 = r % 2048, oc = r3 >> 5, k2 = r3 & 31;
        const float* filt = f ? iwt : wt;
        float w0 = filt[(oc*64 + 2*k2)*25 + tap];
        float w1 = filt[(oc*64 + 2*k2 + 1)*25 + tap];
        u32 v = term ? bpack(bres(w0), bres(w1)) : bpack(w0, w1);
        ((u32*)base)[O_WB + i] = v;
    }
    if (i < 2048) base[O_AB + i] = -__expf(A_log[i]);
    if (i < 16384) {
        int d = i >> 7, k = i & 127;
        float s = 0.f;
        #pragma unroll
        for (int r = 0; r < 4; r++) s += W_dt[d*4 + r] * W_x[r*128 + k];
        base[O_WE + i] = s;
    }
    if (i < 8192) {
        int j = i >> 7, k = i & 127;
        base[O_WE + (size_t)(128 + j)*128 + k] = (j < 32) ? W_x[(4 + j)*128 + k] : 0.f;
    }
}

// ---- prep2: bf16 hi/lo GEMM weight slabs ----
__global__ void prep2_k(const float* __restrict__ W_in, const float* __restrict__ W_out,
                        float* __restrict__ base)
{
    int i = blockIdx.x * 256 + threadIdx.x;
    if (i >= 49152) return;
    const float* src; int K, n, k2, term;
    if (i < 16384)      { term = i >> 13; int r = i & 8191;  n = r >> 5; k2 = r & 31; K = 64;  src = W_in; }
    else if (i < 40960) { int j = i - 16384; term = j / 12288; int r = j % 12288; n = r >> 6; k2 = r & 63; K = 128; src = base + O_WE; }
    else                { int j = i - 40960; term = j >> 12; int r = j & 4095;  n = r >> 6; k2 = r & 63; K = 128; src = W_out; }
    float w0 = src[(size_t)n*K + 2*k2], w1 = src[(size_t)n*K + 2*k2 + 1];
    ((u32*)base)[O_WG + i] = term ? bpack(bres(w0), bres(w1)) : bpack(w0, w1);
}

// ---- pad into NHWC bf16 hi/lo planes, 4 px per block ----
template<int MODE>
__global__ void pad_k(const float* __restrict__ in, const float* __restrict__ llB,
                      const float* __restrict__ high, void* __restrict__ PADB, int H, int W)
{
    int ic = threadIdx.x & 63, xp = blockIdx.x*4 + (threadIdx.x >> 6);
    int yp = blockIdx.y, b = blockIdx.z;
    int X = W + 4, xi = xp - 2, yi = yp - 2;
    float v = 0.f;
    if ((unsigned)xi < (unsigned)W && (unsigned)yi < (unsigned)H) {
        if (MODE == 0)      v = in[(((size_t)b*64 + ic)*H + yi)*W + xi];
        else if (MODE == 1) v = in[(((size_t)b*64 + ic)*W + xi)*H + yi];
        else {
            int h2 = H>>1, w2 = W>>1, L2 = h2*w2, s = (yi&1)*2 + (xi&1), hy = yi>>1, hx = xi>>1;
            if (s == 0) {
                v = in[((size_t)b*64 + ic)*L2 + hx*h2 + hy];
                if (llB) v += llB[(((size_t)b*64 + ic)*h2 + hy)*w2 + hx];
            } else v = high[((((size_t)b*64 + ic)*4 + s)*h2 + hy)*w2 + hx];
        }
    }
    __nv_bfloat16* PH = (__nv_bfloat16*)PADB;
    __nv_bfloat16* PL = PH + (size_t)4*(H+4)*X*64;
    size_t idx = (((size_t)b*(H+4) + yp)*X + xp)*64 + ic;
    __nv_bfloat16 hv = __float2bfloat16(v);
    PH[idx] = hv;
    PL[idx] = __float2bfloat16(v - __bfloat162float(hv));
}

// ---- warp-MMA bf16 3-term conv: M=128(8rows x 16px), N=64 oc, 25 taps x K=64 ic ----
// warps 4(wm) x 2(wn): Mw=32, Nw=32. A staged via cp.async from pre-converted bf16 planes.
// smem (swizzled, stride 128): A hi [12][20][128B] @0 (30720), A lo @30720,
// B @61440: 2 bufs x 2 terms x 8192 (32KB). Total 94208 -> 2 CTAs/SM.
#define CSM 94208
__global__ void __launch_bounds__(256, 2) convt_k(
    const void* __restrict__ PADB, const u32* __restrict__ WBu,
    float* __restrict__ outP, float* __restrict__ outLL, int H, int W, int OUTMODE)
{
    extern __shared__ char sm[];
    u32 su = s2u(sm);
    int tid = threadIdx.x, wid = tid >> 5, lane = tid & 31;
    int wm = wid & 3, wn = wid >> 2;
    int b = blockIdx.z, Y0 = blockIdx.y * 8, x0 = blockIdx.x * 16;
    int X = W + 4;

    // A window: 12 rows x 20 xpos x 64 ic, hi+lo planes, via cp.async (pre-swizzled dst)
    {
        const char* PB = (const char*)PADB;
        size_t termoff = (size_t)4*(H+4)*X*64*2;   // bytes per plane
        #pragma unroll
        for (int it = 0; it < 15; it++) {
            int i = it*256 + tid;
            int term = i / 1920, r2 = i % 1920, rid = r2 >> 3, ch = r2 & 7;
            int r = rid / 20, xx = rid % 20;
            u32 dst = su + (u32)term*30720u + (u32)(rid*128 + ((ch ^ (rid & 7))*16));
            const char* src = PB + (size_t)term*termoff
                            + ((((size_t)b*(H+4) + Y0 + r)*X + x0 + xx)*64 + ch*8)*2;
            cpasync16(dst, src);
        }
        CP_COMMIT();
    }

    auto issueB = [&](int tap, int buf) {
        #pragma unroll
        for (int it = 0; it < 4; it++) {
            int u = it*256 + tid, term = u >> 9, oc = (u >> 3) & 63, ch = u & 7;
            u32 dst = su + 61440u + (u32)buf*16384u + (u32)term*8192u
                    + (u32)(oc*128 + ((ch ^ (oc & 7))*16));
            cpasync16(dst, WBu + ((size_t)(term*25 + tap)*64 + oc)*32 + ch*4);
        }
        CP_COMMIT();
    };
    issueB(0, 0);

    // lane constants
    int pixrow[2], hi16 = lane >> 4;
    #pragma unroll
    for (int mt = 0; mt < 2; mt++) {
        int pix = wm*32 + mt*16 + (lane & 15);
        pixrow[mt] = (pix >> 4)*20 + (pix & 15);
    }
    u32 bnoff[2]; int b7[2]; int bhalf = (lane >> 3) & 1;
    #pragma unroll
    for (int g2 = 0; g2 < 2; g2++) {
        int boc = wn*32 + g2*16 + ((lane >> 4) << 3) + (lane & 7);
        bnoff[g2] = su + 61440u + (u32)(boc*128);
        b7[g2] = boc & 7;
    }

    float acc[2][4][4];
    #pragma unroll
    for (int mt = 0; mt < 2; mt++)
        #pragma unroll
        for (int nt = 0; nt < 4; nt++)
            #pragma unroll
            for (int q = 0; q < 4; q++) acc[mt][nt][q] = 0.f;

    for (int tap = 0; tap < 25; tap++) {
        CP_WAIT0();
        __syncthreads();
        if (tap < 24) issueB(tap + 1, (tap + 1) & 1);

        int drow = (tap/5)*20 + (tap%5);
        u32 aaddr[2]; int ar7[2];
        #pragma unroll
        for (int mt = 0; mt < 2; mt++) {
            int rid = pixrow[mt] + drow;
            ar7[mt] = rid & 7;
            aaddr[mt] = su + (u32)(rid*128);
        }
        u32 bbuf = (u32)(tap & 1)*16384u;

        #pragma unroll
        for (int ks = 0; ks < 4; ks++) {
            int cA = ks*2 + hi16, cB = ks*2 + bhalf;
            u32 ah[2][4], al[2][4], bh[8], bl[8];
            #pragma unroll
            for (int mt = 0; mt < 2; mt++) {
                u32 sw = (u32)(((cA ^ ar7[mt]))*16);
                ldsm4(ah[mt], aaddr[mt] + sw);
                ldsm4(al[mt], aaddr[mt] + 30720u + sw);
            }
            #pragma unroll
            for (int g2 = 0; g2 < 2; g2++) {
                u32 sw = (u32)(((cB ^ b7[g2]))*16);
                ldsm4(bh + g2*4, bnoff[g2] + bbuf + sw);
                ldsm4(bl + g2*4, bnoff[g2] + bbuf + 8192u + sw);
            }
            #pragma unroll
            for (int mt = 0; mt < 2; mt++)
                #pragma unroll
                for (int nt = 0; nt < 4; nt++) {
                    mma16816(acc[mt][nt], ah[mt], bh + nt*2);
                    mma16816(acc[mt][nt], ah[mt], bl + nt*2);
                    mma16816(acc[mt][nt], al[mt], bh + nt*2);
                }
        }
    }

    int g = lane >> 2, t4 = lane & 3;
    int h2 = H >> 1, w2 = W >> 1, L2 = h2*w2;
    #pragma unroll
    for (int mt = 0; mt < 2; mt++)
        #pragma unroll
        for (int half = 0; half < 2; half++) {
            int m = wm*32 + mt*16 + g + half*8;
            int y = Y0 + (m >> 4), gx = x0 + (m & 15);
            #pragma unroll
            for (int nt = 0; nt < 4; nt++)
                #pragma unroll
                for (int q = 0; q < 2; q++) {
                    int oc = wn*32 + nt*8 + 2*t4 + q;
                    float v = acc[mt][nt][half*2 + q];
                    if (OUTMODE == 0) {
                        outP[(((size_t)b*64 + oc)*H + y)*W + gx] = v;
                    } else {
                        int s = (y & 1)*2 + (gx & 1), hy = y >> 1, hx = gx >> 1;
                        if (s == 0) outLL[((size_t)b*64 + oc)*L2 + hx*h2 + hy] = v;
                        else        outP[((((size_t)b*64 + oc)*4 + s)*h2 + hy)*w2 + hx] = v;
                    }
                }
        }
}

// ---- HMMA bf16 3-term GEMM: C[128m x 64n] = A[.,K] @ W[n,K]^T ----
template<int AMODE, int EPI, int K>
__global__ void __launch_bounds__(256) gemmt_k(const float* __restrict__ A, const u32* __restrict__ WG,
    u32 wsz, float* __restrict__ out, const float* __restrict__ bias, int lda, int L, float* __restrict__ ws)
{
    extern __shared__ char sm[];
    constexpr int rowB = (K + 8) * 2;
    constexpr u32 sAlo = 128u * rowB, sW = 256u * rowB;
    constexpr u32 wterm = 64u * rowB;
    u32 su = s2u(sm);
    int tid = threadIdx.x, wid = tid >> 5, lane = tid & 31;
    int wm = wid & 3, wn = wid >> 2;
    int m0 = blockIdx.x * 128, n0 = blockIdx.y * 64;
    int b = m0 / L, l0 = m0 % L;
    size_t Mt = (size_t)gridDim.x * 128;

    if (AMODE == 0) {
        #pragma unroll
        for (int it = 0; it < K / 8; it++) {
            int i = it*256 + tid;
            int ml = i / (K / 4), kq = i % (K / 4);
            float4 v = *(const float4*)(A + (size_t)(m0 + ml)*lda + kq*4);
            *(uint2*)(sm + ml*rowB + kq*8) = make_uint2(bpack(v.x, v.y), bpack(v.z, v.w));
            *(uint2*)(sm + sAlo + ml*rowB + kq*8) =
                make_uint2(bpack(bres(v.x), bres(v.y)), bpack(bres(v.z), bres(v.w)));
        }
    } else {
        #pragma unroll
        for (int it = 0; it < K / 8; it++) {
            int i = it*256 + tid;
            int k = i >> 5, mq = i & 31;
            float4 v = *(const float4*)(A + ((size_t)b*64 + k)*L + l0 + mq*4);
            float vv[4] = {v.x, v.y, v.z, v.w};
            #pragma unroll
            for (int j = 0; j < 4; j++) {
                int ml = mq*4 + j;
                *(__nv_bfloat16*)(sm + ml*rowB + k*2) = __float2bfloat16(vv[j]);
                *(__nv_bfloat16*)(sm + sAlo + ml*rowB + k*2) = __float2bfloat16(bres(vv[j]));
            }
        }
    }
    constexpr int kw4 = K / 8;
    #pragma unroll
    for (int it = 0; it < (2*64*kw4 + 255) / 256; it++) {
        int i = it*256 + tid;
        if (i < 2*64*kw4) {
            int term = i / (64*kw4), r = i % (64*kw4), n = r / kw4, kq = r % kw4;
            uint4 v = *(const uint4*)(WG + (size_t)term*wsz + (size_t)(n0 + n)*(K/2) + kq*4);
            *(uint4*)(sm + sW + term*wterm + n*rowB + kq*16) = v;
        }
    }
    __syncthreads();

    u32 abase[2], bbase[4];
    #pragma unroll
    for (int mt = 0; mt < 2; mt++)
        abase[mt] = su + (u32)((wm*32 + mt*16 + (lane & 15))*rowB + (lane >> 4)*16);
    #pragma unroll
    for (int nt = 0; nt < 4; nt++)
        bbase[nt] = su + sW + (u32)((wn*32 + nt*8 + (lane & 7))*rowB + ((lane >> 3) & 1)*16);

    float acc[2][4][4];
    #pragma unroll
    for (int mt = 0; mt < 2; mt++)
        #pragma unroll
        for (int nt = 0; nt < 4; nt++)
            #pragma unroll
            for (int q = 0; q < 4; q++) acc[mt][nt][q] = 0.f;

    #pragma unroll
    for (int ks = 0; ks < K / 16; ks++) {
        u32 ko = (u32)(ks*32);
        u32 ah[2][4], al[2][4], bh[4][2], bl[4][2];
        #pragma unroll
        for (int mt = 0; mt < 2; mt++) {
            ldsm4(ah[mt], abase[mt] + ko);
            ldsm4(al[mt], abase[mt] + sAlo + ko);
        }
        #pragma unroll
        for (int nt = 0; nt < 4; nt++) {
            ldsm2(bh[nt], bbase[nt] + ko);
            ldsm2(bl[nt], bbase[nt] + wterm + ko);
        }
        #pragma unroll
        for (int mt = 0; mt < 2; mt++)
            #pragma unroll
            for (int nt = 0; nt < 4; nt++) {
                mma16816(acc[mt][nt], ah[mt], bh[nt]);
                mma16816(acc[mt][nt], ah[mt], bl[nt]);
                mma16816(acc[mt][nt], al[mt], bh[nt]);
            }
    }

    int g = lane >> 2, t4 = lane & 3;
    #pragma unroll
    for (int mt = 0; mt < 2; mt++)
        #pragma unroll
        for (int half = 0; half < 2; half++) {
            int mloc = wm*32 + mt*16 + g + half*8;
            int m = m0 + mloc;
            #pragma unroll
            for (int nt = 0; nt < 4; nt++)
                #pragma unroll
                for (int q = 0; q < 2; q++) {
                    int n = n0 + wn*32 + nt*8 + 2*t4 + q;
                    float v = acc[mt][nt][half*2 + q];
                    if (EPI == 1) {
                        out[(size_t)m*256 + n] = v;
                    } else if (EPI == 2) {
                        if (n < 128)      ws[Mt*384 + (size_t)m*128 + n] = softplus_f(v + bias[n]);
                        else if (n < 160) ws[Mt*512 + (size_t)m*32 + n - 128] = v;
                    } else {
                        out[((size_t)b*64 + n)*L + l0 + mloc] = v;
                    }
                }
        }
}

__global__ void dwconv_k(const float* __restrict__ cw, const float* __restrict__ cb, int L, float* __restrict__ ws)
{
    size_t Mt = (size_t)gridDim.x * 2;
    size_t g = (size_t)blockIdx.x * 256 + threadIdx.x;
    int d = (int)(g & 127);
    size_t m = g >> 7;
    int l = (int)(m % (size_t)L);
    float acc = cb[d];
    #pragma unroll
    for (int j = 0; j < 4; j++) {
        int lj = l - 3 + j;
        if (lj >= 0) acc = fmaf(cw[d*4 + j], ws[(m - 3 + j)*256 + d], acc);
    }
    ws[Mt*256 + g] = acc * __fdividef(1.f, 1.f + __expf(-acc));
}

__global__ void scan1_k(int L, int NCH, float* __restrict__ ws, const float* __restrict__ Ab)
{
    size_t Mt = (size_t)4 * L;
    const float* dt = ws + Mt*384; const float* xs = ws + Mt*256; const float* bc = ws + Mt*512;
    int t = threadIdx.x, s = t & 15;
    int ch = blockIdx.y, b = blockIdx.z, d = blockIdx.x * 16 + (t >> 4);
    float a = Ab[d*16 + s];
    float h = 0.f, P = 1.f;
    size_t ml = (size_t)b*L + (size_t)ch*128;
    for (int i = 0; i < 128; i++) {
        size_t m = ml + i;
        float dtv = __ldg(dt + m*128 + d);
        float e = __expf(dtv * a);
        h = h*e + dtv*__ldg(xs + m*128 + d)*__ldg(bc + m*32 + s);
        P *= e;
    }
    size_t ix = (((size_t)(b*NCH + ch)*128) + d)*16 + s;
    ws[Mt*672 + ix] = P;
    ws[Mt*688 + ix] = h;
}

__global__ void scan2_k(int L, int NCH, float* __restrict__ ws)
{
    size_t Mt = (size_t)4 * L;
    int g = blockIdx.x * 256 + threadIdx.x;
    int b = g >> 11, ds = g & 2047;
    float carry = 0.f;
    for (int ch = 0; ch < NCH; ch++) {
        size_t ix = ((size_t)(b*NCH + ch))*2048 + ds;
        ws[Mt*704 + ix] = carry;
        carry = carry * ws[Mt*672 + ix] + ws[Mt*688 + ix];
    }
}

__global__ void scan3_k(int L, int NCH, float* __restrict__ ws, const float* __restrict__ Ab)
{
    size_t Mt = (size_t)4 * L;
    const float* dt = ws + Mt*384; const float* xs = ws + Mt*256; const float* bc = ws + Mt*512;
    int t = threadIdx.x, s = t & 15;
    int ch = blockIdx.y, b = blockIdx.z, d = blockIdx.x * 16 + (t >> 4);
    float a = Ab[d*16 + s];
    size_t ix = (((size_t)(b*NCH + ch)*128) + d)*16 + s;
    float h = ws[Mt*704 + ix];
    size_t ml = (size_t)b*L + (size_t)ch*128;
    for (int i = 0; i < 128; i++) {
        size_t m = ml + i;
        float dtv = __ldg(dt + m*128 + d);
        float e = __expf(dtv * a);
        h = h*e + dtv*__ldg(xs + m*128 + d)*__ldg(bc + m*32 + s);
        float part = h * __ldg(bc + m*32 + 16 + s);
        part += __shfl_xor_sync(0xffffffffu, part, 8);
        part += __shfl_xor_sync(0xffffffffu, part, 4);
        part += __shfl_xor_sync(0xffffffffu, part, 2);
        part += __shfl_xor_sync(0xffffffffu, part, 1);
        if (s == 0) ws[Mt*544 + m*128 + d] = part;
    }
}

__global__ void ymul_k(const float* __restrict__ Dp, float* __restrict__ ws)
{
    size_t Mt = (size_t)gridDim.x * 2;
    size_t g = (size_t)blockIdx.x * 256 + threadIdx.x;
    int d = (int)(g & 127);
    size_t m = g >> 7;
    float z = ws[m*256 + 128 + d];
    float sz = z * __fdividef(1.f, 1.f + __expf(-z));
    ws[Mt*544 + g] = (ws[Mt*544 + g] + ws[Mt*256 + g] * Dp[d]) * sz;
}

extern "C" void kernel_launch(void* const* d_in, const int* in_sizes, int n_in,
                              void* d_out, int out_size)
{
    const float* x      = (const float*)d_in[0];
    const float* wt     = (const float*)d_in[1];
    const float* iwt    = (const float*)d_in[2];
    const float* W_in   = (const float*)d_in[3];
    const float* conv_w = (const float*)d_in[4];
    const float* conv_b = (const float*)d_in[5];
    const float* W_x    = (const float*)d_in[6];
    const float* W_dt   = (const float*)d_in[7];
    const float* b_dt   = (const float*)d_in[8];
    const float* A_log  = (const float*)d_in[9];
    const float* Dp     = (const float*)d_in[10];
    const float* W_out  = (const float*)d_in[11];
    (void)in_sizes; (void)n_in; (void)out_size;

    float* S = nullptr;
    cudaGetSymbolAddress((void**)&S, g_scratch);
    cudaFuncSetAttribute(convt_k, cudaFuncAttributeMaxDynamicSharedMemorySize, CSM);
    cudaFuncSetAttribute(gemmt_k<1,1,64>,  cudaFuncAttributeMaxDynamicSharedMemorySize, 55296);
    cudaFuncSetAttribute(gemmt_k<0,2,128>, cudaFuncAttributeMaxDynamicSharedMemorySize, 104448);
    cudaFuncSetAttribute(gemmt_k<0,3,128>, cudaFuncAttributeMaxDynamicSharedMemorySize, 104448);
    const u32* WB0 = (const u32*)S + O_WB;
    const u32* WB1 = WB0 + 102400;
    const u32* WG  = (const u32*)S + O_WG;
    const float* Ab = S + O_AB;
    void* PADB = (void*)(S + O_PAD);
    cudaStream_t s2 = g_si.s2;

    prep_k<<<800, 256>>>(wt, iwt, A_log, W_x, W_dt, S);
    prep2_k<<<192, 256>>>(W_in, W_out, S);

    auto mamba = [&](int L, int NCH, const float* llseq, float* llm, float* ws, cudaStream_t st) {
        int M = 4 * L;
        gemmt_k<1,1,64><<<dim3(M/128, 4), 256, 55296, st>>>(llseq, WG, 8192u, ws, nullptr, 0, L, ws);
        dwconv_k<<<(M*128)/256, 256, 0, st>>>(conv_w, conv_b, L, ws);
        gemmt_k<0,2,128><<<dim3(M/128, 3), 256, 104448, st>>>(ws + (size_t)M*256, WG + 16384, 12288u, nullptr, b_dt, 128, L, ws);
        scan1_k<<<dim3(8, NCH, 4), 256, 0, st>>>(L, NCH, ws, Ab);
        scan2_k<<<32, 256, 0, st>>>(L, NCH, ws);
        scan3_k<<<dim3(8, NCH, 4), 256, 0, st>>>(L, NCH, ws, Ab);
        ymul_k<<<(M*128)/256, 256, 0, st>>>(Dp, ws);
        gemmt_k<0,3,128><<<dim3(M/128, 1), 256, 104448, st>>>(ws + (size_t)M*544, WG + 40960, 4096u, llm, nullptr, 128, L, ws);
    };

    // level-0 decomposition
    pad_k<0><<<dim3(49,196,4), 256>>>(x, nullptr, nullptr, PADB, 192, 192);
    convt_k<<<dim3(12,24,4), 256, CSM>>>(PADB, WB0, S + O_HI0, S + O_LL0, 192, 192, 1);

    // fork: chain A (default stream) = mamba level-0; chain B (s2) = full level-1 subtree
    cudaEventRecord(g_si.evF, 0);
    cudaStreamWaitEvent(s2, g_si.evF, 0);

    mamba(9216, 72, S + O_LL0, S + O_LM0, S + O_WS0, 0);

    pad_k<1><<<dim3(25,100,4), 256, 0, s2>>>(S + O_LL0, nullptr, nullptr, PADB, 96, 96);
    convt_k<<<dim3(6,12,4), 256, CSM, s2>>>(PADB, WB0, S + O_HI1, S + O_LL1, 96, 96, 1);
    mamba(2304, 18, S + O_LL1, S + O_LM1, S + O_WS1, s2);
    pad_k<2><<<dim3(25,100,4), 256, 0, s2>>>(S + O_LM1, nullptr, S + O_HI1, PADB, 96, 96);
    convt_k<<<dim3(6,12,4), 256, CSM, s2>>>(PADB, WB1, S + O_RC, nullptr, 96, 96, 0);

    // join
    cudaEventRecord(g_si.evJ, s2);
    cudaStreamWaitEvent(0, g_si.evJ, 0);

    pad_k<2><<<dim3(49,196,4), 256>>>(S + O_LM0, S + O_RC, S + O_HI0, PADB, 192, 192);
    convt_k<<<dim3(12,24,4), 256, CSM>>>(PADB, WB1, (float*)d_out, nullptr, 192, 192, 0);
}

// round 13
// speedup vs baseline: 2.6828x; 1.2080x over previous
#include <cuda_runtime.h>
#include <cuda_bf16.h>
#include <cuda_fp16.h>
#include <cstdint>

typedef unsigned int u32;
#define DEV static __device__ __forceinline__

DEV u32 bpack(float lo, float hi){ u32 r; asm("cvt.rn.bf16x2.f32 %0, %2, %1;" : "=r"(r) : "f"(lo), "f"(hi)); return r; }
DEV float bres(float a){ u32 t = bpack(a, a); return a - __uint_as_float(t & 0xFFFF0000u); }
DEV u32 s2u(const void* p){ u32 a; asm("{ .reg .u64 t; cvta.to.shared.u64 t, %1; cvt.u32.u64 %0, t; }" : "=r"(a) : "l"(p)); return a; }

DEV void ldsm4(u32* r, u32 a){ asm volatile("ldmatrix.sync.aligned.m8n8.x4.shared.b16 {%0,%1,%2,%3}, [%4];"
  : "=r"(r[0]),"=r"(r[1]),"=r"(r[2]),"=r"(r[3]) : "r"(a)); }
DEV void ldsm2(u32* r, u32 a){ asm volatile("ldmatrix.sync.aligned.m8n8.x2.shared.b16 {%0,%1}, [%2];"
  : "=r"(r[0]),"=r"(r[1]) : "r"(a)); }
DEV void mma16816(float* c, const u32* a, const u32* b){
  asm volatile("mma.sync.aligned.m16n8k16.row.col.f32.bf16.bf16.f32 {%0,%1,%2,%3},{%4,%5,%6,%7},{%8,%9},{%0,%1,%2,%3};"
    : "+f"(c[0]),"+f"(c[1]),"+f"(c[2]),"+f"(c[3])
    : "r"(a[0]),"r"(a[1]),"r"(a[2]),"r"(a[3]),"r"(b[0]),"r"(b[1]));
}
DEV void mma16816h(float* c, const u32* a, const u32* b){
  asm volatile("mma.sync.aligned.m16n8k16.row.col.f32.f16.f16.f32 {%0,%1,%2,%3},{%4,%5,%6,%7},{%8,%9},{%0,%1,%2,%3};"
    : "+f"(c[0]),"+f"(c[1]),"+f"(c[2]),"+f"(c[3])
    : "r"(a[0]),"r"(a[1]),"r"(a[2]),"r"(a[3]),"r"(b[0]),"r"(b[1]));
}
DEV void cpasync16(u32 dst, const void* src){
  asm volatile("cp.async.cg.shared.global [%0], [%1], 16;" :: "r"(dst), "l"(src) : "memory");
}
#define CP_COMMIT() asm volatile("cp.async.commit_group;" ::: "memory")
#define CP_WAIT0()  asm volatile("cp.async.wait_group 0;" ::: "memory")

// ---- scratch offsets (floats) ----
#define O_LL0 0ull
#define O_HI0 2359296ull
#define O_LL1 11796480ull
#define O_HI1 12386304ull
#define O_LM0 14745600ull
#define O_LM1 17104896ull
#define O_RC  17694720ull
#define O_WS0 20054016ull
#define O_WB  46596096ull
#define O_AB  46800896ull
#define O_WE  46802944ull
#define O_PAD 46827520ull
#define O_WG  56662016ull
#define O_WS1 56711168ull
#define S_TOT 63346688ull

__device__ __align__(16) float g_scratch[S_TOT];

struct StreamInit {
    cudaStream_t s2; cudaEvent_t evF, evJ;
    StreamInit() {
        cudaStreamCreate(&s2);
        cudaEventCreateWithFlags(&evF, cudaEventDisableTiming);
        cudaEventCreateWithFlags(&evJ, cudaEventDisableTiming);
    }
};
static StreamInit g_si;

DEV float softplus_f(float x){ return fmaxf(x, 0.f) + log1pf(__expf(-fabsf(x))); }

// ---- prep: fp16 conv-weight slabs (single term), A=-exp(A_log), Weff ----
__global__ void prep_k(const float* __restrict__ wt, const float* __restrict__ iwt,
                       const float* __restrict__ A_log, const float* __restrict__ W_x,
                       const float* __restrict__ W_dt, float* __restrict__ base)
{
    int i = blockIdx.x * 256 + threadIdx.x;
    if (i < 102400) {
        int f = i / 51200, r = i % 51200;
        int tap = r / 2048, r3 = r % 2048, oc = r3 >> 5, k2 = r3 & 31;
        const float* filt = f ? iwt : wt;
        float w0 = filt[(oc*64 + 2*k2)*25 + tap];
        float w1 = filt[(oc*64 + 2*k2 + 1)*25 + tap];
        __half2 h = __floats2half2_rn(w0, w1);
        ((u32*)base)[O_WB + i] = *(u32*)&h;
    }
    if (i < 2048) base[O_AB + i] = -__expf(A_log[i]);
    if (i < 16384) {
        int d = i >> 7, k = i & 127;
        float s = 0.f;
        #pragma unroll
        for (int r = 0; r < 4; r++) s += W_dt[d*4 + r] * W_x[r*128 + k];
        base[O_WE + i] = s;
    }
    if (i < 8192) {
        int j = i >> 7, k = i & 127;
        base[O_WE + (size_t)(128 + j)*128 + k] = (j < 32) ? W_x[(4 + j)*128 + k] : 0.f;
    }
}

// ---- prep2: bf16 hi/lo GEMM weight slabs ----
__global__ void prep2_k(const float* __restrict__ W_in, const float* __restrict__ W_out,
                        float* __restrict__ base)
{
    int i = blockIdx.x * 256 + threadIdx.x;
    if (i >= 49152) return;
    const float* src; int K, n, k2, term;
    if (i < 16384)      { term = i >> 13; int r = i & 8191;  n = r >> 5; k2 = r & 31; K = 64;  src = W_in; }
    else if (i < 40960) { int j = i - 16384; term = j / 12288; int r = j % 12288; n = r >> 6; k2 = r & 63; K = 128; src = base + O_WE; }
    else                { int j = i - 40960; term = j >> 12; int r = j & 4095;  n = r >> 6; k2 = r & 63; K = 128; src = W_out; }
    float w0 = src[(size_t)n*K + 2*k2], w1 = src[(size_t)n*K + 2*k2 + 1];
    ((u32*)base)[O_WG + i] = term ? bpack(bres(w0), bres(w1)) : bpack(w0, w1);
}

// ---- pad into NHWC fp16 hi/lo planes, 4 px per block ----
template<int MODE>
__global__ void pad_k(const float* __restrict__ in, const float* __restrict__ llB,
                      const float* __restrict__ high, void* __restrict__ PADB, int H, int W)
{
    int ic = threadIdx.x & 63, xp = blockIdx.x*4 + (threadIdx.x >> 6);
    int yp = blockIdx.y, b = blockIdx.z;
    int X = W + 4, xi = xp - 2, yi = yp - 2;
    float v = 0.f;
    if ((unsigned)xi < (unsigned)W && (unsigned)yi < (unsigned)H) {
        if (MODE == 0)      v = in[(((size_t)b*64 + ic)*H + yi)*W + xi];
        else if (MODE == 1) v = in[(((size_t)b*64 + ic)*W + xi)*H + yi];
        else {
            int h2 = H>>1, w2 = W>>1, L2 = h2*w2, s = (yi&1)*2 + (xi&1), hy = yi>>1, hx = xi>>1;
            if (s == 0) {
                v = in[((size_t)b*64 + ic)*L2 + hx*h2 + hy];
                if (llB) v += llB[(((size_t)b*64 + ic)*h2 + hy)*w2 + hx];
            } else v = high[((((size_t)b*64 + ic)*4 + s)*h2 + hy)*w2 + hx];
        }
    }
    __half* PH = (__half*)PADB;
    __half* PL = PH + (size_t)4*(H+4)*X*64;
    size_t idx = (((size_t)b*(H+4) + yp)*X + xp)*64 + ic;
    __half hv = __float2half(v);
    PH[idx] = hv;
    PL[idx] = __float2half(v - __half2float(hv));
}

// ---- warp-MMA fp16 2-term conv: M=128(8rows x 16px), N=64 oc, 25 taps x K=64 ic ----
// A split hi/lo fp16 (residual), B single fp16. warps 4(wm) x 2(wn).
// smem: A hi [12][20][128B] @0 (30720), A lo @30720, B @61440: 4 bufs x 8192 (32KB).
#define CSM 94208
__global__ void __launch_bounds__(256, 2) convt_k(
    const void* __restrict__ PADB, const u32* __restrict__ WBu,
    float* __restrict__ outP, float* __restrict__ outLL, int H, int W, int OUTMODE)
{
    extern __shared__ char sm[];
    u32 su = s2u(sm);
    int tid = threadIdx.x, wid = tid >> 5, lane = tid & 31;
    int wm = wid & 3, wn = wid >> 2;
    int b = blockIdx.z, Y0 = blockIdx.y * 8, x0 = blockIdx.x * 16;
    int X = W + 4;

    // A window: 12 rows x 20 xpos x 64 ic, hi+lo planes, via cp.async (pre-swizzled dst)
    {
        const char* PB = (const char*)PADB;
        size_t termoff = (size_t)4*(H+4)*X*64*2;   // bytes per plane
        #pragma unroll
        for (int it = 0; it < 15; it++) {
            int i = it*256 + tid;
            int term = i / 1920, r2 = i % 1920, rid = r2 >> 3, ch = r2 & 7;
            int r = rid / 20, xx = rid % 20;
            u32 dst = su + (u32)term*30720u + (u32)(rid*128 + ((ch ^ (rid & 7))*16));
            const char* src = PB + (size_t)term*termoff
                            + ((((size_t)b*(H+4) + Y0 + r)*X + x0 + xx)*64 + ch*8)*2;
            cpasync16(dst, src);
        }
        CP_COMMIT();
    }

    auto issueBpair = [&](int p) {
        #pragma unroll
        for (int tt = 0; tt < 2; tt++) {
            int tap = 2*p + tt;
            if (tap > 24) break;
            #pragma unroll
            for (int it = 0; it < 2; it++) {
                int u = it*256 + tid, oc = u >> 3, ch = u & 7;
                u32 dst = su + 61440u + (u32)(tap & 3)*8192u
                        + (u32)(oc*128 + ((ch ^ (oc & 7))*16));
                cpasync16(dst, WBu + (size_t)tap*2048 + oc*32 + ch*4);
            }
        }
        CP_COMMIT();
    };
    issueBpair(0);

    // lane constants
    int pixrow[2], hi16 = lane >> 4;
    #pragma unroll
    for (int mt = 0; mt < 2; mt++) {
        int pix = wm*32 + mt*16 + (lane & 15);
        pixrow[mt] = (pix >> 4)*20 + (pix & 15);
    }
    u32 bnoff[2]; int b7[2]; int bhalf = (lane >> 3) & 1;
    #pragma unroll
    for (int g2 = 0; g2 < 2; g2++) {
        int boc = wn*32 + g2*16 + ((lane >> 4) << 3) + (lane & 7);
        bnoff[g2] = su + 61440u + (u32)(boc*128);
        b7[g2] = boc & 7;
    }

    float acc[2][4][4];
    #pragma unroll
    for (int mt = 0; mt < 2; mt++)
        #pragma unroll
        for (int nt = 0; nt < 4; nt++)
            #pragma unroll
            for (int q = 0; q < 4; q++) acc[mt][nt][q] = 0.f;

    for (int p = 0; p < 13; p++) {
        CP_WAIT0();
        __syncthreads();
        if (p < 12) issueBpair(p + 1);

        #pragma unroll
        for (int tt = 0; tt < 2; tt++) {
            int tap = 2*p + tt;
            if (tap > 24) break;
            int drow = (tap/5)*20 + (tap%5);
            u32 aaddr[2]; int ar7[2];
            #pragma unroll
            for (int mt = 0; mt < 2; mt++) {
                int rid = pixrow[mt] + drow;
                ar7[mt] = rid & 7;
                aaddr[mt] = su + (u32)(rid*128);
            }
            u32 bbuf = (u32)(tap & 3)*8192u;

            #pragma unroll
            for (int ks = 0; ks < 4; ks++) {
                int cA = ks*2 + hi16, cB = ks*2 + bhalf;
                u32 ah[2][4], al[2][4], bh[8];
                #pragma unroll
                for (int mt = 0; mt < 2; mt++) {
                    u32 sw = (u32)(((cA ^ ar7[mt]))*16);
                    ldsm4(ah[mt], aaddr[mt] + sw);
                    ldsm4(al[mt], aaddr[mt] + 30720u + sw);
                }
                #pragma unroll
                for (int g2 = 0; g2 < 2; g2++) {
                    u32 sw = (u32)(((cB ^ b7[g2]))*16);
                    ldsm4(bh + g2*4, bnoff[g2] + bbuf + sw);
                }
                #pragma unroll
                for (int mt = 0; mt < 2; mt++)
                    #pragma unroll
                    for (int nt = 0; nt < 4; nt++) {
                        mma16816h(acc[mt][nt], ah[mt], bh + nt*2);
                        mma16816h(acc[mt][nt], al[mt], bh + nt*2);
                    }
            }
        }
    }

    int g = lane >> 2, t4 = lane & 3;
    int h2 = H >> 1, w2 = W >> 1, L2 = h2*w2;
    #pragma unroll
    for (int mt = 0; mt < 2; mt++)
        #pragma unroll
        for (int half = 0; half < 2; half++) {
            int m = wm*32 + mt*16 + g + half*8;
            int y = Y0 + (m >> 4), gx = x0 + (m & 15);
            #pragma unroll
            for (int nt = 0; nt < 4; nt++)
                #pragma unroll
                for (int q = 0; q < 2; q++) {
                    int oc = wn*32 + nt*8 + 2*t4 + q;
                    float v = acc[mt][nt][half*2 + q];
                    if (OUTMODE == 0) {
                        outP[(((size_t)b*64 + oc)*H + y)*W + gx] = v;
                    } else {
                        int s = (y & 1)*2 + (gx & 1), hy = y >> 1, hx = gx >> 1;
                        if (s == 0) outLL[((size_t)b*64 + oc)*L2 + hx*h2 + hy] = v;
                        else        outP[((((size_t)b*64 + oc)*4 + s)*h2 + hy)*w2 + hx] = v;
                    }
                }
        }
}

// ---- HMMA bf16 3-term GEMM: C[128m x 64n] = A[.,K] @ W[n,K]^T ----
// AMODE 0: A row-major. AMODE 1: seq-gather. AMODE 3: A=ys with fused (ys+xs*D)*silu(z).
template<int AMODE, int EPI, int K>
__global__ void __launch_bounds__(256) gemmt_k(const float* __restrict__ A, const u32* __restrict__ WG,
    u32 wsz, float* __restrict__ out, const float* __restrict__ bias, int lda, int L, float* __restrict__ ws)
{
    extern __shared__ char sm[];
    constexpr int rowB = (K + 8) * 2;
    constexpr u32 sAlo = 128u * rowB, sW = 256u * rowB;
    constexpr u32 wterm = 64u * rowB;
    u32 su = s2u(sm);
    int tid = threadIdx.x, wid = tid >> 5, lane = tid & 31;
    int wm = wid & 3, wn = wid >> 2;
    int m0 = blockIdx.x * 128, n0 = blockIdx.y * 64;
    int b = m0 / L, l0 = m0 % L;
    size_t Mt = (size_t)gridDim.x * 128;

    if (AMODE == 0) {
        #pragma unroll
        for (int it = 0; it < K / 8; it++) {
            int i = it*256 + tid;
            int ml = i / (K / 4), kq = i % (K / 4);
            float4 v = *(const float4*)(A + (size_t)(m0 + ml)*lda + kq*4);
            *(uint2*)(sm + ml*rowB + kq*8) = make_uint2(bpack(v.x, v.y), bpack(v.z, v.w));
            *(uint2*)(sm + sAlo + ml*rowB + kq*8) =
                make_uint2(bpack(bres(v.x), bres(v.y)), bpack(bres(v.z), bres(v.w)));
        }
    } else if (AMODE == 3) {
        #pragma unroll
        for (int it = 0; it < K / 8; it++) {
            int i = it*256 + tid;
            int ml = i / (K / 4), kq = i % (K / 4);
            int m = m0 + ml;
            float4 ys = *(const float4*)(A + (size_t)m*128 + kq*4);
            float4 xs = *(const float4*)(ws + Mt*256 + (size_t)m*128 + kq*4);
            float4 zz = *(const float4*)(ws + (size_t)m*256 + 128 + kq*4);
            float4 dd = *(const float4*)(bias + kq*4);
            float4 v;
            v.x = (ys.x + xs.x*dd.x) * (zz.x * __fdividef(1.f, 1.f + __expf(-zz.x)));
            v.y = (ys.y + xs.y*dd.y) * (zz.y * __fdividef(1.f, 1.f + __expf(-zz.y)));
            v.z = (ys.z + xs.z*dd.z) * (zz.z * __fdividef(1.f, 1.f + __expf(-zz.z)));
            v.w = (ys.w + xs.w*dd.w) * (zz.w * __fdividef(1.f, 1.f + __expf(-zz.w)));
            *(uint2*)(sm + ml*rowB + kq*8) = make_uint2(bpack(v.x, v.y), bpack(v.z, v.w));
            *(uint2*)(sm + sAlo + ml*rowB + kq*8) =
                make_uint2(bpack(bres(v.x), bres(v.y)), bpack(bres(v.z), bres(v.w)));
        }
    } else {
        #pragma unroll
        for (int it = 0; it < K / 8; it++) {
            int i = it*256 + tid;
            int k = i >> 5, mq = i & 31;
            float4 v = *(const float4*)(A + ((size_t)b*64 + k)*L + l0 + mq*4);
            float vv[4] = {v.x, v.y, v.z, v.w};
            #pragma unroll
            for (int j = 0; j < 4; j++) {
                int ml = mq*4 + j;
                *(__nv_bfloat16*)(sm + ml*rowB + k*2) = __float2bfloat16(vv[j]);
                *(__nv_bfloat16*)(sm + sAlo + ml*rowB + k*2) = __float2bfloat16(bres(vv[j]));
            }
        }
    }
    constexpr int kw4 = K / 8;
    #pragma unroll
    for (int it = 0; it < (2*64*kw4 + 255) / 256; it++) {
        int i = it*256 + tid;
        if (i < 2*64*kw4) {
            int term = i / (64*kw4), r = i % (64*kw4), n = r / kw4, kq = r % kw4;
            uint4 v = *(const uint4*)(WG + (size_t)term*wsz + (size_t)(n0 + n)*(K/2) + kq*4);
            *(uint4*)(sm + sW + term*wterm + n*rowB + kq*16) = v;
        }
    }
    __syncthreads();

    u32 abase[2], bbase[4];
    #pragma unroll
    for (int mt = 0; mt < 2; mt++)
        abase[mt] = su + (u32)((wm*32 + mt*16 + (lane & 15))*rowB + (lane >> 4)*16);
    #pragma unroll
    for (int nt = 0; nt < 4; nt++)
        bbase[nt] = su + sW + (u32)((wn*32 + nt*8 + (lane & 7))*rowB + ((lane >> 3) & 1)*16);

    float acc[2][4][4];
    #pragma unroll
    for (int mt = 0; mt < 2; mt++)
        #pragma unroll
        for (int nt = 0; nt < 4; nt++)
            #pragma unroll
            for (int q = 0; q < 4; q++) acc[mt][nt][q] = 0.f;

    #pragma unroll
    for (int ks = 0; ks < K / 16; ks++) {
        u32 ko = (u32)(ks*32);
        u32 ah[2][4], al[2][4], bh[4][2], bl[4][2];
        #pragma unroll
        for (int mt = 0; mt < 2; mt++) {
            ldsm4(ah[mt], abase[mt] + ko);
            ldsm4(al[mt], abase[mt] + sAlo + ko);
        }
        #pragma unroll
        for (int nt = 0; nt < 4; nt++) {
            ldsm2(bh[nt], bbase[nt] + ko);
            ldsm2(bl[nt], bbase[nt] + wterm + ko);
        }
        #pragma unroll
        for (int mt = 0; mt < 2; mt++)
            #pragma unroll
            for (int nt = 0; nt < 4; nt++) {
                mma16816(acc[mt][nt], ah[mt], bh[nt]);
                mma16816(acc[mt][nt], ah[mt], bl[nt]);
                mma16816(acc[mt][nt], al[mt], bh[nt]);
            }
    }

    int g = lane >> 2, t4 = lane & 3;
    #pragma unroll
    for (int mt = 0; mt < 2; mt++)
        #pragma unroll
        for (int half = 0; half < 2; half++) {
            int mloc = wm*32 + mt*16 + g + half*8;
            int m = m0 + mloc;
            #pragma unroll
            for (int nt = 0; nt < 4; nt++)
                #pragma unroll
                for (int q = 0; q < 2; q++) {
                    int n = n0 + wn*32 + nt*8 + 2*t4 + q;
                    float v = acc[mt][nt][half*2 + q];
                    if (EPI == 1) {
                        out[(size_t)m*256 + n] = v;
                    } else if (EPI == 2) {
                        if (n < 128)      ws[Mt*384 + (size_t)m*128 + n] = softplus_f(v + bias[n]);
                        else if (n < 160) ws[Mt*512 + (size_t)m*32 + n - 128] = v;
                    } else {
                        out[((size_t)b*64 + n)*L + l0 + mloc] = v;
                    }
                }
        }
}

__global__ void dwconv_k(const float* __restrict__ cw, const float* __restrict__ cb, int L, float* __restrict__ ws)
{
    size_t Mt = (size_t)gridDim.x * 2;
    size_t g = (size_t)blockIdx.x * 256 + threadIdx.x;
    int d = (int)(g & 127);
    size_t m = g >> 7;
    int l = (int)(m % (size_t)L);
    float acc = cb[d];
    #pragma unroll
    for (int j = 0; j < 4; j++) {
        int lj = l - 3 + j;
        if (lj >= 0) acc = fmaf(cw[d*4 + j], ws[(m - 3 + j)*256 + d], acc);
    }
    ws[Mt*256 + g] = acc * __fdividef(1.f, 1.f + __expf(-acc));
}

__global__ void scan1_k(int L, int NCH, float* __restrict__ ws, const float* __restrict__ Ab)
{
    size_t Mt = (size_t)4 * L;
    const float* dt = ws + Mt*384; const float* xs = ws + Mt*256; const float* bc = ws + Mt*512;
    int t = threadIdx.x, s = t & 15;
    int ch = blockIdx.y, b = blockIdx.z, d = blockIdx.x * 16 + (t >> 4);
    float a = Ab[d*16 + s];
    float h = 0.f, P = 1.f;
    size_t ml = (size_t)b*L + (size_t)ch*128;
    for (int i = 0; i < 128; i++) {
        size_t m = ml + i;
        float dtv = __ldg(dt + m*128 + d);
        float e = __expf(dtv * a);
        h = h*e + dtv*__ldg(xs + m*128 + d)*__ldg(bc + m*32 + s);
        P *= e;
    }
    size_t ix = (((size_t)(b*NCH + ch)*128) + d)*16 + s;
    ws[Mt*672 + ix] = P;
    ws[Mt*688 + ix] = h;
}

__global__ void scan2_k(int L, int NCH, float* __restrict__ ws)
{
    size_t Mt = (size_t)4 * L;
    int g = blockIdx.x * 256 + threadIdx.x;
    int b = g >> 11, ds = g & 2047;
    float carry = 0.f;
    for (int ch = 0; ch < NCH; ch++) {
        size_t ix = ((size_t)(b*NCH + ch))*2048 + ds;
        ws[Mt*704 + ix] = carry;
        carry = carry * ws[Mt*672 + ix] + ws[Mt*688 + ix];
    }
}

__global__ void scan3_k(int L, int NCH, float* __restrict__ ws, const float* __restrict__ Ab)
{
    size_t Mt = (size_t)4 * L;
    const float* dt = ws + Mt*384; const float* xs = ws + Mt*256; const float* bc = ws + Mt*512;
    int t = threadIdx.x, s = t & 15;
    int ch = blockIdx.y, b = blockIdx.z, d = blockIdx.x * 16 + (t >> 4);
    float a = Ab[d*16 + s];
    size_t ix = (((size_t)(b*NCH + ch)*128) + d)*16 + s;
    float h = ws[Mt*704 + ix];
    size_t ml = (size_t)b*L + (size_t)ch*128;
    for (int i = 0; i < 128; i++) {
        size_t m = ml + i;
        float dtv = __ldg(dt + m*128 + d);
        float e = __expf(dtv * a);
        h = h*e + dtv*__ldg(xs + m*128 + d)*__ldg(bc + m*32 + s);
        float part = h * __ldg(bc + m*32 + 16 + s);
        part += __shfl_xor_sync(0xffffffffu, part, 8);
        part += __shfl_xor_sync(0xffffffffu, part, 4);
        part += __shfl_xor_sync(0xffffffffu, part, 2);
        part += __shfl_xor_sync(0xffffffffu, part, 1);
        if (s == 0) ws[Mt*544 + m*128 + d] = part;
    }
}

extern "C" void kernel_launch(void* const* d_in, const int* in_sizes, int n_in,
                              void* d_out, int out_size)
{
    const float* x      = (const float*)d_in[0];
    const float* wt     = (const float*)d_in[1];
    const float* iwt    = (const float*)d_in[2];
    const float* W_in   = (const float*)d_in[3];
    const float* conv_w = (const float*)d_in[4];
    const float* conv_b = (const float*)d_in[5];
    const float* W_x    = (const float*)d_in[6];
    const float* W_dt   = (const float*)d_in[7];
    const float* b_dt   = (const float*)d_in[8];
    const float* A_log  = (const float*)d_in[9];
    const float* Dp     = (const float*)d_in[10];
    const float* W_out  = (const float*)d_in[11];
    (void)in_sizes; (void)n_in; (void)out_size;

    float* S = nullptr;
    cudaGetSymbolAddress((void**)&S, g_scratch);
    cudaFuncSetAttribute(convt_k, cudaFuncAttributeMaxDynamicSharedMemorySize, CSM);
    cudaFuncSetAttribute(gemmt_k<1,1,64>,  cudaFuncAttributeMaxDynamicSharedMemorySize, 55296);
    cudaFuncSetAttribute(gemmt_k<0,2,128>, cudaFuncAttributeMaxDynamicSharedMemorySize, 104448);
    cudaFuncSetAttribute(gemmt_k<3,3,128>, cudaFuncAttributeMaxDynamicSharedMemorySize, 104448);
    const u32* WB0 = (const u32*)S + O_WB;
    const u32* WB1 = WB0 + 51200;
    const u32* WG  = (const u32*)S + O_WG;
    const float* Ab = S + O_AB;
    void* PADB = (void*)(S + O_PAD);
    cudaStream_t s2 = g_si.s2;

    prep_k<<<800, 256>>>(wt, iwt, A_log, W_x, W_dt, S);
    prep2_k<<<192, 256>>>(W_in, W_out, S);

    auto mamba = [&](int L, int NCH, const float* llseq, float* llm, float* ws, cudaStream_t st) {
        int M = 4 * L;
        gemmt_k<1,1,64><<<dim3(M/128, 4), 256, 55296, st>>>(llseq, WG, 8192u, ws, nullptr, 0, L, ws);
        dwconv_k<<<(M*128)/256, 256, 0, st>>>(conv_w, conv_b, L, ws);
        gemmt_k<0,2,128><<<dim3(M/128, 3), 256, 104448, st>>>(ws + (size_t)M*256, WG + 16384, 12288u, nullptr, b_dt, 128, L, ws);
        scan1_k<<<dim3(8, NCH, 4), 256, 0, st>>>(L, NCH, ws, Ab);
        scan2_k<<<32, 256, 0, st>>>(L, NCH, ws);
        scan3_k<<<dim3(8, NCH, 4), 256, 0, st>>>(L, NCH, ws, Ab);
        gemmt_k<3,3,128><<<dim3(M/128, 1), 256, 104448, st>>>(ws + (size_t)M*544, WG + 40960, 4096u, llm, Dp, 128, L, ws);
    };

    // level-0 decomposition
    pad_k<0><<<dim3(49,196,4), 256>>>(x, nullptr, nullptr, PADB, 192, 192);
    convt_k<<<dim3(12,24,4), 256, CSM>>>(PADB, WB0, S + O_HI0, S + O_LL0, 192, 192, 1);

    // fork: chain A (default stream) = mamba level-0; chain B (s2) = full level-1 subtree
    cudaEventRecord(g_si.evF, 0);
    cudaStreamWaitEvent(s2, g_si.evF, 0);

    mamba(9216, 72, S + O_LL0, S + O_LM0, S + O_WS0, 0);

    pad_k<1><<<dim3(25,100,4), 256, 0, s2>>>(S + O_LL0, nullptr, nullptr, PADB, 96, 96);
    convt_k<<<dim3(6,12,4), 256, CSM, s2>>>(PADB, WB0, S + O_HI1, S + O_LL1, 96, 96, 1);
    mamba(2304, 18, S + O_LL1, S + O_LM1, S + O_WS1, s2);
    pad_k<2><<<dim3(25,100,4), 256, 0, s2>>>(S + O_LM1, nullptr, S + O_HI1, PADB, 96, 96);
    convt_k<<<dim3(6,12,4), 256, CSM, s2>>>(PADB, WB1, S + O_RC, nullptr, 96, 96, 0);

    // join
    cudaEventRecord(g_si.evJ, s2);
    cudaStreamWaitEvent(0, g_si.evJ, 0);

    pad_k<2><<<dim3(49,196,4), 256>>>(S + O_LM0, S + O_RC, S + O_HI0, PADB, 192, 192);
    convt_k<<<dim3(12,24,4), 256, CSM>>>(PADB, WB1, (float*)d_out, nullptr, 192, 192, 0);
}

// round 14
// speedup vs baseline: 2.7029x; 1.0075x over previous
#include <cuda_runtime.h>
#include <cuda_bf16.h>
#include <cuda_fp16.h>
#include <cstdint>

typedef unsigned int u32;
#define DEV static __device__ __forceinline__

DEV u32 hpack(float lo, float hi){ __half2 h = __floats2half2_rn(lo, hi); return *(u32*)&h; }
DEV float hres(float a){ return a - __half2float(__float2half(a)); }
DEV u32 s2u(const void* p){ u32 a; asm("{ .reg .u64 t; cvta.to.shared.u64 t, %1; cvt.u32.u64 %0, t; }" : "=r"(a) : "l"(p)); return a; }

DEV void ldsm4(u32* r, u32 a){ asm volatile("ldmatrix.sync.aligned.m8n8.x4.shared.b16 {%0,%1,%2,%3}, [%4];"
  : "=r"(r[0]),"=r"(r[1]),"=r"(r[2]),"=r"(r[3]) : "r"(a)); }
DEV void ldsm2(u32* r, u32 a){ asm volatile("ldmatrix.sync.aligned.m8n8.x2.shared.b16 {%0,%1}, [%2];"
  : "=r"(r[0]),"=r"(r[1]) : "r"(a)); }
DEV void mma16816h(float* c, const u32* a, const u32* b){
  asm volatile("mma.sync.aligned.m16n8k16.row.col.f32.f16.f16.f32 {%0,%1,%2,%3},{%4,%5,%6,%7},{%8,%9},{%0,%1,%2,%3};"
    : "+f"(c[0]),"+f"(c[1]),"+f"(c[2]),"+f"(c[3])
    : "r"(a[0]),"r"(a[1]),"r"(a[2]),"r"(a[3]),"r"(b[0]),"r"(b[1]));
}
DEV void cpasync16(u32 dst, const void* src){
  asm volatile("cp.async.cg.shared.global [%0], [%1], 16;" :: "r"(dst), "l"(src) : "memory");
}
#define CP_COMMIT() asm volatile("cp.async.commit_group;" ::: "memory")
#define CP_WAIT0()  asm volatile("cp.async.wait_group 0;" ::: "memory")

// ---- scratch offsets (floats) ----
#define O_LL0 0ull
#define O_HI0 2359296ull
#define O_LL1 11796480ull
#define O_HI1 12386304ull
#define O_LM0 14745600ull
#define O_LM1 17104896ull
#define O_RC  17694720ull
#define O_WS0 20054016ull
#define O_WB  46596096ull
#define O_AB  46800896ull
#define O_WE  46802944ull
#define O_PAD 46827520ull
#define O_WG  56662016ull
#define O_WS1 56711168ull
#define S_TOT 63346688ull

__device__ __align__(16) float g_scratch[S_TOT];

struct StreamInit {
    cudaStream_t s2; cudaEvent_t evF, evJ;
    StreamInit() {
        cudaStreamCreate(&s2);
        cudaEventCreateWithFlags(&evF, cudaEventDisableTiming);
        cudaEventCreateWithFlags(&evJ, cudaEventDisableTiming);
    }
};
static StreamInit g_si;

DEV float softplus_f(float x){ return fmaxf(x, 0.f) + log1pf(__expf(-fabsf(x))); }

// ---- prep: fp16 conv-weight slabs (single term), A=-exp(A_log), Weff ----
__global__ void prep_k(const float* __restrict__ wt, const float* __restrict__ iwt,
                       const float* __restrict__ A_log, const float* __restrict__ W_x,
                       const float* __restrict__ W_dt, float* __restrict__ base)
{
    int i = blockIdx.x * 256 + threadIdx.x;
    if (i < 102400) {
        int f = i / 51200, r = i % 51200;
        int tap = r / 2048, r3 = r % 2048, oc = r3 >> 5, k2 = r3 & 31;
        const float* filt = f ? iwt : wt;
        float w0 = filt[(oc*64 + 2*k2)*25 + tap];
        float w1 = filt[(oc*64 + 2*k2 + 1)*25 + tap];
        ((u32*)base)[O_WB + i] = hpack(w0, w1);
    }
    if (i < 2048) base[O_AB + i] = -__expf(A_log[i]);
    if (i < 16384) {
        int d = i >> 7, k = i & 127;
        float s = 0.f;
        #pragma unroll
        for (int r = 0; r < 4; r++) s += W_dt[d*4 + r] * W_x[r*128 + k];
        base[O_WE + i] = s;
    }
    if (i < 8192) {
        int j = i >> 7, k = i & 127;
        base[O_WE + (size_t)(128 + j)*128 + k] = (j < 32) ? W_x[(4 + j)*128 + k] : 0.f;
    }
}

// ---- prep2: fp16 GEMM weight slabs (single term): W_in 256x64 | Weff 192x128 | W_out 64x128 ----
__global__ void prep2_k(const float* __restrict__ W_in, const float* __restrict__ W_out,
                        float* __restrict__ base)
{
    int i = blockIdx.x * 256 + threadIdx.x;
    if (i >= 24576) return;
    const float* src; int K, n, k2;
    if (i < 8192)       { n = i >> 5; k2 = i & 31; K = 64;  src = W_in; }
    else if (i < 20480) { int j = i - 8192;  n = j >> 6; k2 = j & 63; K = 128; src = base + O_WE; }
    else                { int j = i - 20480; n = j >> 6; k2 = j & 63; K = 128; src = W_out; }
    float w0 = src[(size_t)n*K + 2*k2], w1 = src[(size_t)n*K + 2*k2 + 1];
    ((u32*)base)[O_WG + i] = hpack(w0, w1);
}

// ---- pad into NHWC fp16 hi/lo planes, 4 px per block ----
template<int MODE>
__global__ void pad_k(const float* __restrict__ in, const float* __restrict__ llB,
                      const float* __restrict__ high, void* __restrict__ PADB, int H, int W)
{
    int ic = threadIdx.x & 63, xp = blockIdx.x*4 + (threadIdx.x >> 6);
    int yp = blockIdx.y, b = blockIdx.z;
    int X = W + 4, xi = xp - 2, yi = yp - 2;
    float v = 0.f;
    if ((unsigned)xi < (unsigned)W && (unsigned)yi < (unsigned)H) {
        if (MODE == 0)      v = in[(((size_t)b*64 + ic)*H + yi)*W + xi];
        else if (MODE == 1) v = in[(((size_t)b*64 + ic)*W + xi)*H + yi];
        else {
            int h2 = H>>1, w2 = W>>1, L2 = h2*w2, s = (yi&1)*2 + (xi&1), hy = yi>>1, hx = xi>>1;
            if (s == 0) {
                v = in[((size_t)b*64 + ic)*L2 + hx*h2 + hy];
                if (llB) v += llB[(((size_t)b*64 + ic)*h2 + hy)*w2 + hx];
            } else v = high[((((size_t)b*64 + ic)*4 + s)*h2 + hy)*w2 + hx];
        }
    }
    __half* PH = (__half*)PADB;
    __half* PL = PH + (size_t)4*(H+4)*X*64;
    size_t idx = (((size_t)b*(H+4) + yp)*X + xp)*64 + ic;
    __half hv = __float2half(v);
    PH[idx] = hv;
    PL[idx] = __float2half(v - __half2float(hv));
}

// ---- warp-MMA fp16 2-term conv: M=128(8rows x 16px), N=64 oc, 25 taps x K=64 ic ----
// A split hi/lo fp16, B single fp16. warps 4(wm) x 2(wn).
// smem: A hi [12][20][128B] @0 (30720), A lo @30720, B @61440: 4 bufs x 8192 (32KB).
// Epilogue staging reuses A region: ep[oc*132 + m] f32 (33792B).
#define CSM 94208
__global__ void __launch_bounds__(256, 2) convt_k(
    const void* __restrict__ PADB, const u32* __restrict__ WBu,
    float* __restrict__ outP, float* __restrict__ outLL, int H, int W, int OUTMODE)
{
    extern __shared__ char sm[];
    u32 su = s2u(sm);
    int tid = threadIdx.x, wid = tid >> 5, lane = tid & 31;
    int wm = wid & 3, wn = wid >> 2;
    int b = blockIdx.z, Y0 = blockIdx.y * 8, x0 = blockIdx.x * 16;
    int X = W + 4;

    // A window: 12 rows x 20 xpos x 64 ic, hi+lo planes, via cp.async (pre-swizzled dst)
    {
        const char* PB = (const char*)PADB;
        size_t termoff = (size_t)4*(H+4)*X*64*2;   // bytes per plane
        #pragma unroll
        for (int it = 0; it < 15; it++) {
            int i = it*256 + tid;
            int term = i / 1920, r2 = i % 1920, rid = r2 >> 3, ch = r2 & 7;
            int r = rid / 20, xx = rid % 20;
            u32 dst = su + (u32)term*30720u + (u32)(rid*128 + ((ch ^ (rid & 7))*16));
            const char* src = PB + (size_t)term*termoff
                            + ((((size_t)b*(H+4) + Y0 + r)*X + x0 + xx)*64 + ch*8)*2;
            cpasync16(dst, src);
        }
        CP_COMMIT();
    }

    auto issueBpair = [&](int p) {
        #pragma unroll
        for (int tt = 0; tt < 2; tt++) {
            int tap = 2*p + tt;
            if (tap > 24) break;
            #pragma unroll
            for (int it = 0; it < 2; it++) {
                int u = it*256 + tid, oc = u >> 3, ch = u & 7;
                u32 dst = su + 61440u + (u32)(tap & 3)*8192u
                        + (u32)(oc*128 + ((ch ^ (oc & 7))*16));
                cpasync16(dst, WBu + (size_t)tap*2048 + oc*32 + ch*4);
            }
        }
        CP_COMMIT();
    };
    issueBpair(0);

    // lane constants
    int pixrow[2], hi16 = lane >> 4;
    #pragma unroll
    for (int mt = 0; mt < 2; mt++) {
        int pix = wm*32 + mt*16 + (lane & 15);
        pixrow[mt] = (pix >> 4)*20 + (pix & 15);
    }
    u32 bnoff[2]; int b7[2]; int bhalf = (lane >> 3) & 1;
    #pragma unroll
    for (int g2 = 0; g2 < 2; g2++) {
        int boc = wn*32 + g2*16 + ((lane >> 4) << 3) + (lane & 7);
        bnoff[g2] = su + 61440u + (u32)(boc*128);
        b7[g2] = boc & 7;
    }

    float acc[2][4][4];
    #pragma unroll
    for (int mt = 0; mt < 2; mt++)
        #pragma unroll
        for (int nt = 0; nt < 4; nt++)
            #pragma unroll
            for (int q = 0; q < 4; q++) acc[mt][nt][q] = 0.f;

    for (int p = 0; p < 13; p++) {
        CP_WAIT0();
        __syncthreads();
        if (p < 12) issueBpair(p + 1);

        #pragma unroll
        for (int tt = 0; tt < 2; tt++) {
            int tap = 2*p + tt;
            if (tap > 24) break;
            int drow = (tap/5)*20 + (tap%5);
            u32 aaddr[2]; int ar7[2];
            #pragma unroll
            for (int mt = 0; mt < 2; mt++) {
                int rid = pixrow[mt] + drow;
                ar7[mt] = rid & 7;
                aaddr[mt] = su + (u32)(rid*128);
            }
            u32 bbuf = (u32)(tap & 3)*8192u;

            #pragma unroll
            for (int ks = 0; ks < 4; ks++) {
                int cA = ks*2 + hi16, cB = ks*2 + bhalf;
                u32 ah[2][4], al[2][4], bh[8];
                #pragma unroll
                for (int mt = 0; mt < 2; mt++) {
                    u32 sw = (u32)(((cA ^ ar7[mt]))*16);
                    ldsm4(ah[mt], aaddr[mt] + sw);
                    ldsm4(al[mt], aaddr[mt] + 30720u + sw);
                }
                #pragma unroll
                for (int g2 = 0; g2 < 2; g2++) {
                    u32 sw = (u32)(((cB ^ b7[g2]))*16);
                    ldsm4(bh + g2*4, bnoff[g2] + bbuf + sw);
                }
                #pragma unroll
                for (int mt = 0; mt < 2; mt++)
                    #pragma unroll
                    for (int nt = 0; nt < 4; nt++) {
                        mma16816h(acc[mt][nt], ah[mt], bh + nt*2);
                        mma16816h(acc[mt][nt], al[mt], bh + nt*2);
                    }
            }
        }
    }

    // ---- epilogue: stage to smem, vectorized stores ----
    __syncthreads();
    float* ep = (float*)sm;
    {
        int g = lane >> 2, t4 = lane & 3;
        #pragma unroll
        for (int mt = 0; mt < 2; mt++)
            #pragma unroll
            for (int half = 0; half < 2; half++) {
                int m = wm*32 + mt*16 + g + half*8;
                #pragma unroll
                for (int nt = 0; nt < 4; nt++)
                    #pragma unroll
                    for (int q = 0; q < 2; q++) {
                        int oc = wn*32 + nt*8 + 2*t4 + q;
                        ep[oc*132 + m] = acc[mt][nt][half*2 + q];
                    }
            }
    }
    __syncthreads();
    if (OUTMODE == 0) {
        #pragma unroll
        for (int it = 0; it < 8; it++) {
            int u = it*256 + tid;
            int oc = u >> 5, rem = u & 31, y = rem >> 2, xq = rem & 3;
            float4 v = *(float4*)(ep + oc*132 + y*16 + xq*4);
            *(float4*)(outP + (((size_t)b*64 + oc)*H + Y0 + y)*W + x0 + xq*4) = v;
        }
    } else {
        int h2 = H >> 1, w2 = W >> 1, L2 = h2*w2;
        int hx0 = x0 >> 1, hy0 = Y0 >> 1;
        #pragma unroll
        for (int it = 0; it < 8; it++) {
            int u = it*256 + tid;
            if (u < 512) {
                int oc = u >> 3, hx = u & 7;
                float4 v;
                v.x = ep[oc*132 + 0  + 2*hx];
                v.y = ep[oc*132 + 32 + 2*hx];
                v.z = ep[oc*132 + 64 + 2*hx];
                v.w = ep[oc*132 + 96 + 2*hx];
                *(float4*)(outLL + ((size_t)b*64 + oc)*L2 + (hx0 + hx)*h2 + hy0) = v;
            } else {
                int ub = u - 512;
                int s = 1 + (ub >> 9), rem = ub & 511;
                int oc = rem >> 3, r2 = rem & 7, hy = r2 >> 1, xq = r2 & 1;
                int pp = s >> 1, qq = s & 1;
                int mb = (2*hy + pp)*16 + qq + 8*xq;
                float4 v;
                v.x = ep[oc*132 + mb + 0];
                v.y = ep[oc*132 + mb + 2];
                v.z = ep[oc*132 + mb + 4];
                v.w = ep[oc*132 + mb + 6];
                *(float4*)(outP + ((((size_t)b*64 + oc)*4 + s)*h2 + hy0 + hy)*w2 + hx0 + xq*4) = v;
            }
        }
    }
}

// ---- HMMA fp16 2-term GEMM: C[128m x 64n] = A[.,K] @ W[n,K]^T ----
// AMODE 0: A row-major. AMODE 1: seq-gather. AMODE 3: A=ys fused (ys+xs*D)*silu(z).
template<int AMODE, int EPI, int K>
__global__ void __launch_bounds__(256) gemmt_k(const float* __restrict__ A, const u32* __restrict__ WG,
    float* __restrict__ out, const float* __restrict__ bias, int lda, int L, float* __restrict__ ws)
{
    extern __shared__ char sm[];
    constexpr int rowB = (K + 8) * 2;
    constexpr u32 sAlo = 128u * rowB, sW = 256u * rowB;
    u32 su = s2u(sm);
    int tid = threadIdx.x, wid = tid >> 5, lane = tid & 31;
    int wm = wid & 3, wn = wid >> 2;
    int m0 = blockIdx.x * 128, n0 = blockIdx.y * 64;
    int b = m0 / L, l0 = m0 % L;
    size_t Mt = (size_t)gridDim.x * 128;

    if (AMODE == 0) {
        #pragma unroll
        for (int it = 0; it < K / 8; it++) {
            int i = it*256 + tid;
            int ml = i / (K / 4), kq = i % (K / 4);
            float4 v = *(const float4*)(A + (size_t)(m0 + ml)*lda + kq*4);
            *(uint2*)(sm + ml*rowB + kq*8) = make_uint2(hpack(v.x, v.y), hpack(v.z, v.w));
            *(uint2*)(sm + sAlo + ml*rowB + kq*8) =
                make_uint2(hpack(hres(v.x), hres(v.y)), hpack(hres(v.z), hres(v.w)));
        }
    } else if (AMODE == 3) {
        #pragma unroll
        for (int it = 0; it < K / 8; it++) {
            int i = it*256 + tid;
            int ml = i / (K / 4), kq = i % (K / 4);
            int m = m0 + ml;
            float4 ys = *(const float4*)(A + (size_t)m*128 + kq*4);
            float4 xs = *(const float4*)(ws + Mt*256 + (size_t)m*128 + kq*4);
            float4 zz = *(const float4*)(ws + (size_t)m*256 + 128 + kq*4);
            float4 dd = *(const float4*)(bias + kq*4);
            float4 v;
            v.x = (ys.x + xs.x*dd.x) * (zz.x * __fdividef(1.f, 1.f + __expf(-zz.x)));
            v.y = (ys.y + xs.y*dd.y) * (zz.y * __fdividef(1.f, 1.f + __expf(-zz.y)));
            v.z = (ys.z + xs.z*dd.z) * (zz.z * __fdividef(1.f, 1.f + __expf(-zz.z)));
            v.w = (ys.w + xs.w*dd.w) * (zz.w * __fdividef(1.f, 1.f + __expf(-zz.w)));
            *(uint2*)(sm + ml*rowB + kq*8) = make_uint2(hpack(v.x, v.y), hpack(v.z, v.w));
            *(uint2*)(sm + sAlo + ml*rowB + kq*8) =
                make_uint2(hpack(hres(v.x), hres(v.y)), hpack(hres(v.z), hres(v.w)));
        }
    } else {
        #pragma unroll
        for (int it = 0; it < K / 8; it++) {
            int i = it*256 + tid;
            int k = i >> 5, mq = i & 31;
            float4 v = *(const float4*)(A + ((size_t)b*64 + k)*L + l0 + mq*4);
            float vv[4] = {v.x, v.y, v.z, v.w};
            #pragma unroll
            for (int j = 0; j < 4; j++) {
                int ml = mq*4 + j;
                *(__half*)(sm + ml*rowB + k*2) = __float2half(vv[j]);
                *(__half*)(sm + sAlo + ml*rowB + k*2) = __float2half(hres(vv[j]));
            }
        }
    }
    constexpr int kw4 = K / 8;
    #pragma unroll
    for (int it = 0; it < (64*kw4 + 255) / 256; it++) {
        int i = it*256 + tid;
        if (i < 64*kw4) {
            int n = i / kw4, kq = i % kw4;
            uint4 v = *(const uint4*)(WG + (size_t)(n0 + n)*(K/2) + kq*4);
            *(uint4*)(sm + sW + n*rowB + kq*16) = v;
        }
    }
    __syncthreads();

    u32 abase[2], bbase[4];
    #pragma unroll
    for (int mt = 0; mt < 2; mt++)
        abase[mt] = su + (u32)((wm*32 + mt*16 + (lane & 15))*rowB + (lane >> 4)*16);
    #pragma unroll
    for (int nt = 0; nt < 4; nt++)
        bbase[nt] = su + sW + (u32)((wn*32 + nt*8 + (lane & 7))*rowB + ((lane >> 3) & 1)*16);

    float acc[2][4][4];
    #pragma unroll
    for (int mt = 0; mt < 2; mt++)
        #pragma unroll
        for (int nt = 0; nt < 4; nt++)
            #pragma unroll
            for (int q = 0; q < 4; q++) acc[mt][nt][q] = 0.f;

    #pragma unroll
    for (int ks = 0; ks < K / 16; ks++) {
        u32 ko = (u32)(ks*32);
        u32 ah[2][4], al[2][4], bh[4][2];
        #pragma unroll
        for (int mt = 0; mt < 2; mt++) {
            ldsm4(ah[mt], abase[mt] + ko);
            ldsm4(al[mt], abase[mt] + sAlo + ko);
        }
        #pragma unroll
        for (int nt = 0; nt < 4; nt++) ldsm2(bh[nt], bbase[nt] + ko);
        #pragma unroll
        for (int mt = 0; mt < 2; mt++)
            #pragma unroll
            for (int nt = 0; nt < 4; nt++) {
                mma16816h(acc[mt][nt], ah[mt], bh[nt]);
                mma16816h(acc[mt][nt], al[mt], bh[nt]);
            }
    }

    int g = lane >> 2, t4 = lane & 3;
    #pragma unroll
    for (int mt = 0; mt < 2; mt++)
        #pragma unroll
        for (int half = 0; half < 2; half++) {
            int mloc = wm*32 + mt*16 + g + half*8;
            int m = m0 + mloc;
            #pragma unroll
            for (int nt = 0; nt < 4; nt++)
                #pragma unroll
                for (int q = 0; q < 2; q++) {
                    int n = n0 + wn*32 + nt*8 + 2*t4 + q;
                    float v = acc[mt][nt][half*2 + q];
                    if (EPI == 1) {
                        out[(size_t)m*256 + n] = v;
                    } else if (EPI == 2) {
                        if (n < 128)      ws[Mt*384 + (size_t)m*128 + n] = softplus_f(v + bias[n]);
                        else if (n < 160) ws[Mt*512 + (size_t)m*32 + n - 128] = v;
                    } else {
                        out[((size_t)b*64 + n)*L + l0 + mloc] = v;
                    }
                }
        }
}

__global__ void dwconv_k(const float* __restrict__ cw, const float* __restrict__ cb, int L, float* __restrict__ ws)
{
    size_t Mt = (size_t)gridDim.x * 2;
    size_t g = (size_t)blockIdx.x * 256 + threadIdx.x;
    int d = (int)(g & 127);
    size_t m = g >> 7;
    int l = (int)(m % (size_t)L);
    float acc = cb[d];
    #pragma unroll
    for (int j = 0; j < 4; j++) {
        int lj = l - 3 + j;
        if (lj >= 0) acc = fmaf(cw[d*4 + j], ws[(m - 3 + j)*256 + d], acc);
    }
    ws[Mt*256 + g] = acc * __fdividef(1.f, 1.f + __expf(-acc));
}

__global__ void scan1_k(int L, int NCH, float* __restrict__ ws, const float* __restrict__ Ab)
{
    size_t Mt = (size_t)4 * L;
    const float* dt = ws + Mt*384; const float* xs = ws + Mt*256; const float* bc = ws + Mt*512;
    int t = threadIdx.x, s = t & 15;
    int ch = blockIdx.y, b = blockIdx.z, d = blockIdx.x * 16 + (t >> 4);
    float a = Ab[d*16 + s];
    float h = 0.f, P = 1.f;
    size_t ml = (size_t)b*L + (size_t)ch*128;
    for (int i = 0; i < 128; i++) {
        size_t m = ml + i;
        float dtv = __ldg(dt + m*128 + d);
        float e = __expf(dtv * a);
        h = h*e + dtv*__ldg(xs + m*128 + d)*__ldg(bc + m*32 + s);
        P *= e;
    }
    size_t ix = (((size_t)(b*NCH + ch)*128) + d)*16 + s;
    ws[Mt*672 + ix] = P;
    ws[Mt*688 + ix] = h;
}

__global__ void scan2_k(int L, int NCH, float* __restrict__ ws)
{
    size_t Mt = (size_t)4 * L;
    int g = blockIdx.x * 256 + threadIdx.x;
    int b = g >> 11, ds = g & 2047;
    float carry = 0.f;
    for (int ch = 0; ch < NCH; ch++) {
        size_t ix = ((size_t)(b*NCH + ch))*2048 + ds;
        ws[Mt*704 + ix] = carry;
        carry = carry * ws[Mt*672 + ix] + ws[Mt*688 + ix];
    }
}

__global__ void scan3_k(int L, int NCH, float* __restrict__ ws, const float* __restrict__ Ab)
{
    size_t Mt = (size_t)4 * L;
    const float* dt = ws + Mt*384; const float* xs = ws + Mt*256; const float* bc = ws + Mt*512;
    int t = threadIdx.x, s = t & 15;
    int ch = blockIdx.y, b = blockIdx.z, d = blockIdx.x * 16 + (t >> 4);
    float a = Ab[d*16 + s];
    size_t ix = (((size_t)(b*NCH + ch)*128) + d)*16 + s;
    float h = ws[Mt*704 + ix];
    size_t ml = (size_t)b*L + (size_t)ch*128;
    for (int i = 0; i < 128; i++) {
        size_t m = ml + i;
        float dtv = __ldg(dt + m*128 + d);
        float e = __expf(dtv * a);
        h = h*e + dtv*__ldg(xs + m*128 + d)*__ldg(bc + m*32 + s);
        float part = h * __ldg(bc + m*32 + 16 + s);
        part += __shfl_xor_sync(0xffffffffu, part, 8);
        part += __shfl_xor_sync(0xffffffffu, part, 4);
        part += __shfl_xor_sync(0xffffffffu, part, 2);
        part += __shfl_xor_sync(0xffffffffu, part, 1);
        if (s == 0) ws[Mt*544 + m*128 + d] = part;
    }
}

extern "C" void kernel_launch(void* const* d_in, const int* in_sizes, int n_in,
                              void* d_out, int out_size)
{
    const float* x      = (const float*)d_in[0];
    const float* wt     = (const float*)d_in[1];
    const float* iwt    = (const float*)d_in[2];
    const float* W_in   = (const float*)d_in[3];
    const float* conv_w = (const float*)d_in[4];
    const float* conv_b = (const float*)d_in[5];
    const float* W_x    = (const float*)d_in[6];
    const float* W_dt   = (const float*)d_in[7];
    const float* b_dt   = (const float*)d_in[8];
    const float* A_log  = (const float*)d_in[9];
    const float* Dp     = (const float*)d_in[10];
    const float* W_out  = (const float*)d_in[11];
    (void)in_sizes; (void)n_in; (void)out_size;

    float* S = nullptr;
    cudaGetSymbolAddress((void**)&S, g_scratch);
    cudaFuncSetAttribute(convt_k, cudaFuncAttributeMaxDynamicSharedMemorySize, CSM);
    cudaFuncSetAttribute(gemmt_k<1,1,64>,  cudaFuncAttributeMaxDynamicSharedMemorySize, 46080);
    cudaFuncSetAttribute(gemmt_k<0,2,128>, cudaFuncAttributeMaxDynamicSharedMemorySize, 87040);
    cudaFuncSetAttribute(gemmt_k<3,3,128>, cudaFuncAttributeMaxDynamicSharedMemorySize, 87040);
    const u32* WB0 = (const u32*)S + O_WB;
    const u32* WB1 = WB0 + 51200;
    const u32* WG  = (const u32*)S + O_WG;
    const float* Ab = S + O_AB;
    void* PADB = (void*)(S + O_PAD);
    cudaStream_t s2 = g_si.s2;

    prep_k<<<800, 256>>>(wt, iwt, A_log, W_x, W_dt, S);
    prep2_k<<<96, 256>>>(W_in, W_out, S);

    auto mamba = [&](int L, int NCH, const float* llseq, float* llm, float* ws, cudaStream_t st) {
        int M = 4 * L;
        gemmt_k<1,1,64><<<dim3(M/128, 4), 256, 46080, st>>>(llseq, WG, ws, nullptr, 0, L, ws);
        dwconv_k<<<(M*128)/256, 256, 0, st>>>(conv_w, conv_b, L, ws);
        gemmt_k<0,2,128><<<dim3(M/128, 3), 256, 87040, st>>>(ws + (size_t)M*256, WG + 8192, nullptr, b_dt, 128, L, ws);
        scan1_k<<<dim3(8, NCH, 4), 256, 0, st>>>(L, NCH, ws, Ab);
        scan2_k<<<32, 256, 0, st>>>(L, NCH, ws);
        scan3_k<<<dim3(8, NCH, 4), 256, 0, st>>>(L, NCH, ws, Ab);
        gemmt_k<3,3,128><<<dim3(M/128, 1), 256, 87040, st>>>(ws + (size_t)M*544, WG + 20480, llm, Dp, 128, L, ws);
    };

    // level-0 decomposition
    pad_k<0><<<dim3(49,196,4), 256>>>(x, nullptr, nullptr, PADB, 192, 192);
    convt_k<<<dim3(12,24,4), 256, CSM>>>(PADB, WB0, S + O_HI0, S + O_LL0, 192, 192, 1);

    // fork: chain A (default stream) = mamba level-0; chain B (s2) = full level-1 subtree
    cudaEventRecord(g_si.evF, 0);
    cudaStreamWaitEvent(s2, g_si.evF, 0);

    mamba(9216, 72, S + O_LL0, S + O_LM0, S + O_WS0, 0);

    pad_k<1><<<dim3(25,100,4), 256, 0, s2>>>(S + O_LL0, nullptr, nullptr, PADB, 96, 96);
    convt_k<<<dim3(6,12,4), 256, CSM, s2>>>(PADB, WB0, S + O_HI1, S + O_LL1, 96, 96, 1);
    mamba(2304, 18, S + O_LL1, S + O_LM1, S + O_WS1, s2);
    pad_k<2><<<dim3(25,100,4), 256, 0, s2>>>(S + O_LM1, nullptr, S + O_HI1, PADB, 96, 96);
    convt_k<<<dim3(6,12,4), 256, CSM, s2>>>(PADB, WB1, S + O_RC, nullptr, 96, 96, 0);

    // join
    cudaEventRecord(g_si.evJ, s2);
    cudaStreamWaitEvent(0, g_si.evJ, 0);

    pad_k<2><<<dim3(49,196,4), 256>>>(S + O_LM0, S + O_RC, S + O_HI0, PADB, 192, 192);
    convt_k<<<dim3(12,24,4), 256, CSM>>>(PADB, WB1, (float*)d_out, nullptr, 192, 192, 0);
}